// round 9
// baseline (speedup 1.0000x reference)
#include <cuda_runtime.h>
#include <math.h>
#include <stdint.h>

// Problem dims
#define BB 4096
#define TT 64
#define FF 256
#define HH 256
#define AA 12
#define MTOT (BB*TT)            // 262144 rows
#define G3  768

// Scratch (device globals; no cudaMalloc allowed)
__device__ float g_xg [(size_t)MTOT * G3];     // xg, later reused as t12 [M,512]
__device__ float g_lat[(size_t)MTOT * HH];
__device__ float g_t1 [(size_t)MTOT * HH];     // rounded features
__device__ float g_t2a[(size_t)MTOT * HH];
__device__ float g_t2c[(size_t)MTOT * HH];
__device__ float g_wt2[16 * 14336];            // W_hh fragment-major (padded slots)
__device__ float g_wihr[768 * 256];            // W_ih rounded
__device__ float g_w1c [512 * 256];            // [Aw1; Cw1] rounded
__device__ float g_w2a [256 * 256];
__device__ float g_w2c [256 * 256];
__device__ float g_b1c [512];                  // [Ab1 | Cb1]

__device__ __forceinline__ float round_tf32(float x) {
    uint32_t r;
    asm("cvt.rna.tf32.f32 %0, %1;" : "=r"(r) : "f"(x));
    return __uint_as_float(r);
}

__device__ __forceinline__ uint32_t smem_u32(const void* p) {
    uint32_t a;
    asm("{ .reg .u64 t; cvta.to.shared.u64 t, %1; cvt.u32.u64 %0, t; }"
        : "=r"(a) : "l"(p));
    return a;
}

__device__ __forceinline__ void cp16_cg(void* dst, const void* src) {
    asm volatile("cp.async.cg.shared.global [%0], [%1], 16;"
                 :: "r"(smem_u32(dst)), "l"(src) : "memory");
}
__device__ __forceinline__ void l2_prefetch(const void* p) {
    asm volatile("prefetch.global.L2 [%0];" :: "l"(p));
}
#define CP_COMMIT()  asm volatile("cp.async.commit_group;" ::: "memory")
#define CP_WAIT1()   asm volatile("cp.async.wait_group 1;" ::: "memory")
#define CP_WAITALL() asm volatile("cp.async.wait_all;" ::: "memory")

// ldmatrix fragment loaders (tf32 elements as b16 pairs; mapping == mma frags)
#define LDMX4(r0,r1,r2,r3,addr) \
    asm volatile("ldmatrix.sync.aligned.m8n8.x4.shared.b16 {%0,%1,%2,%3}, [%4];" \
                 : "=r"(r0),"=r"(r1),"=r"(r2),"=r"(r3) : "r"(addr))
#define LDMX2(r0,r1,addr) \
    asm volatile("ldmatrix.sync.aligned.m8n8.x2.shared.b16 {%0,%1}, [%2];" \
                 : "=r"(r0),"=r"(r1) : "r"(addr))

__device__ __forceinline__ void mma_tf32(
    float& c0, float& c1, float& c2, float& c3,
    uint32_t a0, uint32_t a1, uint32_t a2, uint32_t a3,
    uint32_t b0, uint32_t b1)
{
    asm volatile(
        "mma.sync.aligned.m16n8k8.row.col.f32.tf32.tf32.f32 "
        "{%0,%1,%2,%3}, {%4,%5,%6,%7}, {%8,%9}, {%0,%1,%2,%3};"
        : "+f"(c0), "+f"(c1), "+f"(c2), "+f"(c3)
        : "r"(a0), "r"(a1), "r"(a2), "r"(a3), "r"(b0), "r"(b1));
}

// ===========================================================================
// Prep: ALL weight prep in one kernel.
// W_hh -> fragment-major layout (see R8 comment).
// ===========================================================================
#define PREP_F4 114688
__global__ void prep_all(
    const float4* __restrict__ Wih, const float4* __restrict__ Aw1,
    const float4* __restrict__ Cw1, const float4* __restrict__ Aw2,
    const float4* __restrict__ Cw2, const float4* __restrict__ Ab1,
    const float4* __restrict__ Cb1, const float*  __restrict__ W_hh,
    float4* __restrict__ wihr, float4* __restrict__ w1c,
    float4* __restrict__ w2a, float4* __restrict__ w2c,
    float4* __restrict__ b1c, float* __restrict__ Wt2)
{
    int i = blockIdx.x * 256 + threadIdx.x;
    if (i < PREP_F4) {
        const float4* src;
        float4* dst;
        if (i < 49152)      { src = Wih + i;            dst = wihr + i; }
        else if (i < 65536) { src = Aw1 + (i - 49152);  dst = w1c + (i - 49152); }
        else if (i < 81920) { src = Cw1 + (i - 65536);  dst = w1c + 16384 + (i - 65536); }
        else if (i < 98304) { src = Aw2 + (i - 81920);  dst = w2a + (i - 81920); }
        else                { src = Cw2 + (i - 98304);  dst = w2c + (i - 98304); }
        float4 v = *src;
        v.x = round_tf32(v.x); v.y = round_tf32(v.y);
        v.z = round_tf32(v.z); v.w = round_tf32(v.w);
        *dst = v;
        if (i < 64)       b1c[i] = Ab1[i];
        else if (i < 128) b1c[i] = Cb1[i - 64];
    } else {
        int j2 = i - PREP_F4;              // 0..196607
        int gcol = j2 >> 8, k = j2 & 255;
        int g = gcol >> 8, rem = gcol & 255;
        int wn = rem >> 5, nt = (rem >> 3) & 3, lanehi = rem & 7;
        int kt = k >> 4, s = (k >> 3) & 1, lanelo = k & 3, b = (k >> 2) & 1;
        int lane = lanehi * 4 + lanelo;
        int idx = (g * 4 + nt) * 2 + b;
        Wt2[(size_t)(kt * 2 + s) * 7168 + (wn * 32 + lane) * 28 + idx] =
            round_tf32(W_hh[(size_t)gcol * 256 + k]);
    }
}

__global__ void round_copy4(const float4* __restrict__ src, float4* __restrict__ dst)
{
    size_t i = (size_t)blockIdx.x * 256 + threadIdx.x;
    float4 v = src[i];
    v.x = round_tf32(v.x); v.y = round_tf32(v.y);
    v.z = round_tf32(v.z); v.w = round_tf32(v.w);
    dst[i] = v;
}

// ===========================================================================
// tf32 mma.sync GEMM: CTA tile 64x128x32, 256 threads (8 warps = 2x4),
// warp tile 32x32 (acc=32 regs) -> 3 CTAs/SM (24 warps) for latency hiding.
// cp.async 2-stage, ldmatrix fragments.
// grid = (N/128, M/64) -- N fastest for A reuse in L2.
// ===========================================================================
#define GBM 64
#define GBN 128
#define GBK 32
#define APITCH 36
#define ASTAGE (GBM * APITCH)                 // 2304 floats
#define BSTAGE (GBN * APITCH)                 // 4608 floats
#define STG    (ASTAGE + BSTAGE)              // 6912 floats per stage
#define GEMM_SMEM ((2 * STG + GBN) * 4)       // 55808 bytes -> 3 CTAs/SM

template<bool DO_TANH, bool ROUND_OUT>
__global__ __launch_bounds__(256, 3) void gemm_mma(
    const float* __restrict__ A, const float* __restrict__ W,
    const float* __restrict__ bias, float* __restrict__ C,
    int N, int K, int lda)
{
    extern __shared__ float sm[];
    float* sBias = sm + 2 * STG;

    const int tid  = threadIdx.x;
    const int lane = tid & 31;
    const int wid  = tid >> 5;
    const int wm   = wid >> 2;          // 0..1 : 32-row group
    const int wn   = wid & 3;           // 0..3 : 32-col group
    const int    bn = blockIdx.x * GBN;
    const size_t bm = (size_t)blockIdx.y * GBM;

    if (tid < GBN) sBias[tid] = bias[bn + tid];

    // A: 64 rows x 8 f4; thread: row=tid>>2, f4 = (tid&3) and (tid&3)+4
    const int arow = tid >> 2;
    const int af4  = tid & 3;
    // B: 128 rows x 8 f4; thread: row=tid>>1, f4 base=(tid&1)*4, 4 consecutive
    const int brow = tid >> 1;
    const int bf4  = (tid & 1) * 4;

    const float* Ag = A + (bm + arow) * lda;
    const float* Wg = W + ((size_t)(bn + brow)) * K;

    const uint32_t sbase = smem_u32(sm);
    const int a_lm = (wm * 32 + (lane & 15)) * APITCH + ((lane >> 4) << 2);
    const int b_lm = (wn * 32 + (lane & 7)) * APITCH + (((lane >> 3) & 1) << 2);

    float acc[2][4][4];
#pragma unroll
    for (int mt = 0; mt < 2; mt++)
#pragma unroll
        for (int nt = 0; nt < 4; nt++)
#pragma unroll
            for (int q = 0; q < 4; q++) acc[mt][nt][q] = 0.f;

    const int NK = K / GBK;

    auto stage_copy = [&](int kt) {
        float* st = sm + (kt & 1) * STG;
        const float* ap = Ag + kt * GBK;
        const float* wp = Wg + kt * GBK;
        float* dA = st + arow * APITCH;
        float* dB = st + ASTAGE + brow * APITCH;
        cp16_cg(dA + af4 * 4,       ap + af4 * 4);
        cp16_cg(dA + (af4 + 4) * 4, ap + (af4 + 4) * 4);
#pragma unroll
        for (int u = 0; u < 4; u++)
            cp16_cg(dB + (bf4 + u) * 4, wp + (bf4 + u) * 4);
    };

    stage_copy(0); CP_COMMIT();
    stage_copy(1); CP_COMMIT();

    for (int kt = 0; kt < NK; kt++) {
        if (kt < NK - 1) { CP_WAIT1(); } else { CP_WAITALL(); }
        __syncthreads();

        const uint32_t bufA = sbase + ((kt & 1) * STG) * 4;
        const uint32_t bufB = bufA + ASTAGE * 4;
#pragma unroll
        for (int k8 = 0; k8 < 4; k8++) {
            const int k0 = k8 * 8;
            uint32_t a[2][4];
#pragma unroll
            for (int mt = 0; mt < 2; mt++)
                LDMX4(a[mt][0], a[mt][1], a[mt][2], a[mt][3],
                      bufA + (a_lm + mt * 16 * APITCH + k0) * 4);
            uint32_t b[4][2];
#pragma unroll
            for (int nt = 0; nt < 4; nt++)
                LDMX2(b[nt][0], b[nt][1],
                      bufB + (b_lm + nt * 8 * APITCH + k0) * 4);
#pragma unroll
            for (int mt = 0; mt < 2; mt++)
#pragma unroll
                for (int nt = 0; nt < 4; nt++)
                    mma_tf32(acc[mt][nt][0], acc[mt][nt][1],
                             acc[mt][nt][2], acc[mt][nt][3],
                             a[mt][0], a[mt][1], a[mt][2], a[mt][3],
                             b[nt][0], b[nt][1]);
        }
        __syncthreads();
        if (kt + 2 < NK) { stage_copy(kt + 2); CP_COMMIT(); }
    }

    // epilogue
#pragma unroll
    for (int mt = 0; mt < 2; mt++) {
        const size_t row = bm + wm * 32 + mt * 16 + (lane >> 2);
        float* c0p = C + row * N + bn + wn * 32;
        float* c1p = c0p + (size_t)8 * N;
#pragma unroll
        for (int nt = 0; nt < 4; nt++) {
            const int cc = nt * 8 + (lane & 3) * 2;
            const float bx = sBias[wn * 32 + cc];
            const float by = sBias[wn * 32 + cc + 1];
            float v0 = acc[mt][nt][0] + bx, v1 = acc[mt][nt][1] + by;
            float v2 = acc[mt][nt][2] + bx, v3 = acc[mt][nt][3] + by;
            if (DO_TANH) {
                v0 = tanhf(v0); v1 = tanhf(v1);
                v2 = tanhf(v2); v3 = tanhf(v3);
            }
            if (ROUND_OUT) {
                v0 = round_tf32(v0); v1 = round_tf32(v1);
                v2 = round_tf32(v2); v3 = round_tf32(v3);
            }
            *(float2*)(c0p + cc) = make_float2(v0, v1);
            *(float2*)(c1p + cc) = make_float2(v2, v3);
        }
    }
}

// ===========================================================================
// GRU scan (unchanged from R8): 512 threads, fragment-major W, fp32 h in regs.
// ===========================================================================
#define RB2 32
#define HT_PITCH 260
#define WS_STAGE 14336
#define GRU_SMEM ((3*WS_STAGE + 32*HT_PITCH + 768) * 4 + 32*64*4)   // 216576 B

__global__ __launch_bounds__(512, 1) void gru_mma(
    const float* __restrict__ xg, const float* __restrict__ h0,
    const float* __restrict__ Wt2, const float* __restrict__ b_hh,
    const int* __restrict__ starts,
    float* __restrict__ lat, float* __restrict__ h_out)
{
    extern __shared__ float sm[];
    float* ws  = sm;                          // [3][14336]
    float* ht  = ws + 3 * WS_STAGE;           // [32][260]
    int*   sst = (int*)(ht + 32 * HT_PITCH);  // [32][64]
    float* sbh = (float*)(sst + 32 * 64);     // [768]

    const int tid  = threadIdx.x;
    const int lane = tid & 31;
    const int w    = tid >> 5;
    const int wm   = w >> 3;
    const int wn   = w & 7;
    const int b0   = blockIdx.x * RB2;

    for (int i = tid; i < 32 * 64; i += 512)
        sst[i] = starts[(size_t)(b0 + (i >> 6)) * TT + (i & 63)];
    for (int i = tid; i < 768; i += 512) sbh[i] = b_hh[i];

    float2 hreg[2][4];
#pragma unroll
    for (int rh = 0; rh < 2; rh++) {
        const int row = wm * 16 + rh * 8 + (lane >> 2);
        const float m0 = starts[(size_t)(b0 + row) * TT] ? 0.f : 1.f;
#pragma unroll
        for (int nt = 0; nt < 4; nt++) {
            const int c = wn * 32 + nt * 8 + (lane & 3) * 2;
            float2 v = *(const float2*)(h0 + (size_t)(b0 + row) * 256 + c);
            v.x *= m0; v.y *= m0;
            hreg[rh][nt] = v;
            ht[row * HT_PITCH + c]     = round_tf32(v.x);
            ht[row * HT_PITCH + c + 1] = round_tf32(v.y);
        }
    }

    auto stageW = [&](int tile, int buf) {
        const float4* src = (const float4*)(Wt2 + (size_t)tile * WS_STAGE) + tid;
        float4* dst = (float4*)(ws + buf * WS_STAGE) + tid;
#pragma unroll
        for (int u = 0; u < 7; u++)
            cp16_cg(dst + u * 512, src + u * 512);
    };

    stageW(0, 0); CP_COMMIT();
    stageW(1, 1); CP_COMMIT();

    const uint32_t ht_lm = smem_u32(ht)
        + ((wm * 16 + (lane & 15)) * HT_PITCH + ((lane >> 4) << 2)) * 4;
    const int bslot = (wn * 32 + lane) * 28;

    const int KS_TOTAL = TT * 16;
    int ks = 0;

    for (int t = 0; t < TT; t++) {
        float acc[12][4];
#pragma unroll
        for (int j = 0; j < 12; j++)
#pragma unroll
            for (int q = 0; q < 4; q++) acc[j][q] = 0.f;

        for (int kt = 0; kt < 16; kt++) {
            if (ks < KS_TOTAL - 1) { CP_WAIT1(); } else { CP_WAITALL(); }
            __syncthreads();

            if (ks + 2 < KS_TOTAL) {
                stageW((ks + 2) & 15, (ks + 2) % 3);
                CP_COMMIT();
            }

            if (tid < 48) {
                int li = kt * 48 + tid;
                int r = li / 24, cl = li % 24;
                l2_prefetch(xg + ((size_t)(b0 + r) * TT + t) * G3 + cl * 32);
            }

            const float* wstage = ws + (ks % 3) * WS_STAGE;
#pragma unroll
            for (int s = 0; s < 2; s++) {
                const int kg = kt * 16 + s * 8;
                uint32_t a0, a1, a2, a3;
                LDMX4(a0, a1, a2, a3, ht_lm + kg * 4);
                const float* wb = wstage + s * 7168 + bslot;
                float4 bf[6];
#pragma unroll
                for (int u = 0; u < 6; u++)
                    bf[u] = *(const float4*)(wb + u * 4);
                const uint32_t* bw = (const uint32_t*)bf;
#pragma unroll
                for (int j = 0; j < 12; j++)
                    mma_tf32(acc[j][0], acc[j][1], acc[j][2], acc[j][3],
                             a0, a1, a2, a3, bw[j * 2], bw[j * 2 + 1]);
            }
            ks++;
        }
        __syncthreads();

#pragma unroll
        for (int rh = 0; rh < 2; rh++) {
            const int row  = wm * 16 + rh * 8 + (lane >> 2);
            const int grow = b0 + row;
            const size_t gbt = (size_t)grow * TT + t;
            const float* xb = xg + gbt * 768;
            float* lb = lat + gbt * 256;
            float msk = 1.f;
            if (t < TT - 1) msk = sst[row * 64 + t + 1] ? 0.f : 1.f;
            const int q = rh * 2;
#pragma unroll
            for (int nt = 0; nt < 4; nt++) {
                const int c = wn * 32 + nt * 8 + (lane & 3) * 2;
                float2 xr = *(const float2*)(xb + c);
                float2 xz = *(const float2*)(xb + 256 + c);
                float2 xn = *(const float2*)(xb + 512 + c);
                float hr0 = acc[nt][q]         + sbh[c];
                float hr1 = acc[nt][q + 1]     + sbh[c + 1];
                float hz0 = acc[4 + nt][q]     + sbh[256 + c];
                float hz1 = acc[4 + nt][q + 1] + sbh[256 + c + 1];
                float hn0 = acc[8 + nt][q]     + sbh[512 + c];
                float hn1 = acc[8 + nt][q + 1] + sbh[512 + c + 1];
                float r0 = 1.f / (1.f + __expf(-(xr.x + hr0)));
                float r1 = 1.f / (1.f + __expf(-(xr.y + hr1)));
                float z0 = 1.f / (1.f + __expf(-(xz.x + hz0)));
                float z1 = 1.f / (1.f + __expf(-(xz.y + hz1)));
                float n0 = tanhf(xn.x + r0 * hn0);
                float n1 = tanhf(xn.y + r1 * hn1);
                float v0 = (1.f - z0) * n0 + z0 * hreg[rh][nt].x;
                float v1 = (1.f - z1) * n1 + z1 * hreg[rh][nt].y;
                *(float2*)(lb + c) = make_float2(round_tf32(v0), round_tf32(v1));
                if (t == TT - 1) {
                    *(float2*)(h_out + (size_t)grow * 256 + c) = make_float2(v0, v1);
                } else {
                    float m0 = v0 * msk, m1 = v1 * msk;
                    hreg[rh][nt] = make_float2(m0, m1);
                    ht[row * HT_PITCH + c]     = round_tf32(m0);
                    ht[row * HT_PITCH + c + 1] = round_tf32(m1);
                }
            }
        }
    }
}

// ---------------------------------------------------------------------------
// Heads
// ---------------------------------------------------------------------------
__global__ __launch_bounds__(256) void head_kernel(
    const float* __restrict__ t2a, const float* __restrict__ t2c,
    const float* __restrict__ Aw3, const float* __restrict__ Ab3,
    const float* __restrict__ Cw3, const float* __restrict__ Cb3,
    float* __restrict__ out)
{
    __shared__ float wa[12][256];
    __shared__ float wc[256];
    __shared__ float ba[12];
    __shared__ float bc;

    const int tid = threadIdx.x;
    for (int i = tid; i < 12 * 256; i += 256) wa[i >> 8][i & 255] = Aw3[i];
    if (tid < 256) wc[tid] = Cw3[tid];
    if (tid < 12)  ba[tid] = Ab3[tid];
    if (tid == 0)  bc = Cb3[0];
    __syncthreads();

    const int warp = tid >> 5;
    const int lane = tid & 31;
    const size_t row = (size_t)blockIdx.x * 8 + warp;

    const float* ra = t2a + row * 256;
    const float* rc = t2c + row * 256;
    float va[8], vc[8];
#pragma unroll
    for (int u = 0; u < 8; u++) {
        va[u] = ra[lane + 32 * u];
        vc[u] = rc[lane + 32 * u];
    }

    float s[13];
#pragma unroll
    for (int a = 0; a < 12; a++) {
        float acc = 0.f;
#pragma unroll
        for (int u = 0; u < 8; u++) acc = fmaf(va[u], wa[a][lane + 32 * u], acc);
        s[a] = acc;
    }
    {
        float acc = 0.f;
#pragma unroll
        for (int u = 0; u < 8; u++) acc = fmaf(vc[u], wc[lane + 32 * u], acc);
        s[12] = acc;
    }
#pragma unroll
    for (int a = 0; a < 13; a++)
#pragma unroll
        for (int o = 16; o > 0; o >>= 1)
            s[a] += __shfl_xor_sync(0xffffffffu, s[a], o);
    if (lane == 0) {
        float* o = out + row * 13;
#pragma unroll
        for (int a = 0; a < 12; a++) o[a] = s[a] + ba[a];
        o[12] = s[12] + bc;
    }
}

__global__ void std_kernel(const float* __restrict__ log_std, float* __restrict__ out)
{
    int a = threadIdx.x;
    if (a < AA) {
        float v = log_std[a];
        v = fminf(fmaxf(v, -2.0f), -0.5f);
        out[a] = __expf(v);
    }
}

// ---------------------------------------------------------------------------
extern "C" void kernel_launch(void* const* d_in, const int* in_sizes, int n_in,
                              void* d_out, int out_size)
{
    const float* features = (const float*)d_in[0];
    const float* hidden   = (const float*)d_in[1];
    const float* W_ih     = (const float*)d_in[2];
    const float* W_hh     = (const float*)d_in[3];
    const float* b_ih     = (const float*)d_in[4];
    const float* b_hh     = (const float*)d_in[5];
    const float* Aw1      = (const float*)d_in[6];
    const float* Ab1      = (const float*)d_in[7];
    const float* Aw2      = (const float*)d_in[8];
    const float* Ab2      = (const float*)d_in[9];
    const float* Aw3      = (const float*)d_in[10];
    const float* Ab3      = (const float*)d_in[11];
    const float* Cw1      = (const float*)d_in[12];
    const float* Cb1      = (const float*)d_in[13];
    const float* Cw2      = (const float*)d_in[14];
    const float* Cb2      = (const float*)d_in[15];
    const float* Cw3      = (const float*)d_in[16];
    const float* Cb3      = (const float*)d_in[17];
    const float* log_std  = (const float*)d_in[18];
    const int*   starts   = (const int*)d_in[19];

    float* out      = (float*)d_out;
    float* out_main = out;
    float* out_std  = out + (size_t)MTOT * 13;
    float* out_h    = out + (size_t)MTOT * 13 + AA;

    float *xg, *lat, *t1, *t2a, *t2c, *wt2, *wihr, *w1c, *w2a, *w2c, *b1c;
    cudaGetSymbolAddress((void**)&xg,   g_xg);
    cudaGetSymbolAddress((void**)&lat,  g_lat);
    cudaGetSymbolAddress((void**)&t1,   g_t1);
    cudaGetSymbolAddress((void**)&t2a,  g_t2a);
    cudaGetSymbolAddress((void**)&t2c,  g_t2c);
    cudaGetSymbolAddress((void**)&wt2,  g_wt2);
    cudaGetSymbolAddress((void**)&wihr, g_wihr);
    cudaGetSymbolAddress((void**)&w1c,  g_w1c);
    cudaGetSymbolAddress((void**)&w2a,  g_w2a);
    cudaGetSymbolAddress((void**)&w2c,  g_w2c);
    cudaGetSymbolAddress((void**)&b1c,  g_b1c);

    cudaFuncSetAttribute(gemm_mma<false, false>,
                         cudaFuncAttributeMaxDynamicSharedMemorySize, GEMM_SMEM);
    cudaFuncSetAttribute(gemm_mma<true, true>,
                         cudaFuncAttributeMaxDynamicSharedMemorySize, GEMM_SMEM);
    cudaFuncSetAttribute(gemm_mma<true, false>,
                         cudaFuncAttributeMaxDynamicSharedMemorySize, GEMM_SMEM);
    cudaFuncSetAttribute(gru_mma,
                         cudaFuncAttributeMaxDynamicSharedMemorySize, GRU_SMEM);

    dim3 blk(256);

    // Launch order: xg GEMM is launch #4 (ncu profiles the 4th launch).
    // 1) all weight prep
    prep_all<<<1216, blk>>>(
        (const float4*)W_ih, (const float4*)Aw1, (const float4*)Cw1,
        (const float4*)Aw2, (const float4*)Cw2,
        (const float4*)Ab1, (const float4*)Cb1, W_hh,
        (float4*)wihr, (float4*)w1c, (float4*)w2a, (float4*)w2c,
        (float4*)b1c, wt2);
    // 2) features rounded
    round_copy4<<<((size_t)MTOT*256)/1024, blk>>>((const float4*)features, (float4*)t1);
    // 3) std (independent)
    std_kernel<<<1, 32>>>(log_std, out_std);
    // 4) xg = features @ W_ih^T + b_ih          <-- profiled launch
    gemm_mma<false, false><<<dim3(G3/GBN, MTOT/GBM), blk, GEMM_SMEM>>>(
        t1, wihr, b_ih, xg, G3, FF, FF);
    // 5) GRU scan -> lat (tf32-rounded), h_last
    gru_mma<<<BB/RB2, dim3(512), GRU_SMEM>>>(xg, hidden, wt2, b_hh, starts, lat, out_h);
    // 6) fused actor+critic layer1 (reuses g_xg as [M,512])
    gemm_mma<true, true><<<dim3(512/GBN, MTOT/GBM), blk, GEMM_SMEM>>>(
        lat, w1c, b1c, xg, 512, HH, HH);
    // 7,8) layer2 actor / critic
    gemm_mma<true, false><<<dim3(HH/GBN, MTOT/GBM), blk, GEMM_SMEM>>>(
        xg,       w2a, Ab2, t2a, HH, HH, 512);
    gemm_mma<true, false><<<dim3(HH/GBN, MTOT/GBM), blk, GEMM_SMEM>>>(
        xg + 256, w2c, Cb2, t2c, HH, HH, 512);
    // 9) heads
    head_kernel<<<MTOT/8, blk>>>(t2a, t2c, Aw3, Ab3, Cw3, Cb3, out_main);
}

// round 10
// speedup vs baseline: 1.0738x; 1.0738x over previous
#include <cuda_runtime.h>
#include <math.h>
#include <stdint.h>

// Problem dims
#define BB 4096
#define TT 64
#define FF 256
#define HH 256
#define AA 12
#define MTOT (BB*TT)            // 262144 rows
#define G3  768

// Scratch (device globals; no cudaMalloc allowed)
__device__ float g_xg [(size_t)MTOT * G3];     // xg, later reused as t12 [M,512]
__device__ float g_lat[(size_t)MTOT * HH];
__device__ float g_t2a[(size_t)MTOT * HH];
__device__ float g_t2c[(size_t)MTOT * HH];
__device__ float g_wt2[16 * 14336];            // W_hh fragment-major (padded slots)
__device__ float g_wihr[768 * 256];            // W_ih rounded
__device__ float g_w1c [512 * 256];            // [Aw1; Cw1] rounded
__device__ float g_w2a [256 * 256];
__device__ float g_w2c [256 * 256];
__device__ float g_b1c [512];                  // [Ab1 | Cb1]

__device__ __forceinline__ float round_tf32(float x) {
    uint32_t r;
    asm("cvt.rna.tf32.f32 %0, %1;" : "=r"(r) : "f"(x));
    return __uint_as_float(r);
}
__device__ __forceinline__ uint32_t round_tf32_u(uint32_t x) {
    uint32_t r;
    asm("cvt.rna.tf32.f32 %0, %1;" : "=r"(r) : "f"(__uint_as_float(x)));
    return r;
}

__device__ __forceinline__ uint32_t smem_u32(const void* p) {
    uint32_t a;
    asm("{ .reg .u64 t; cvta.to.shared.u64 t, %1; cvt.u32.u64 %0, t; }"
        : "=r"(a) : "l"(p));
    return a;
}

__device__ __forceinline__ void cp16_cg(void* dst, const void* src) {
    asm volatile("cp.async.cg.shared.global [%0], [%1], 16;"
                 :: "r"(smem_u32(dst)), "l"(src) : "memory");
}
__device__ __forceinline__ void l2_prefetch(const void* p) {
    asm volatile("prefetch.global.L2 [%0];" :: "l"(p));
}
#define CP_COMMIT()  asm volatile("cp.async.commit_group;" ::: "memory")
#define CP_WAIT1()   asm volatile("cp.async.wait_group 1;" ::: "memory")
#define CP_WAITALL() asm volatile("cp.async.wait_all;" ::: "memory")

// ldmatrix fragment loaders (tf32 elements as b16 pairs; mapping == mma frags)
#define LDMX4(r0,r1,r2,r3,addr) \
    asm volatile("ldmatrix.sync.aligned.m8n8.x4.shared.b16 {%0,%1,%2,%3}, [%4];" \
                 : "=r"(r0),"=r"(r1),"=r"(r2),"=r"(r3) : "r"(addr))
#define LDMX2(r0,r1,addr) \
    asm volatile("ldmatrix.sync.aligned.m8n8.x2.shared.b16 {%0,%1}, [%2];" \
                 : "=r"(r0),"=r"(r1) : "r"(addr))

__device__ __forceinline__ void mma_tf32(
    float& c0, float& c1, float& c2, float& c3,
    uint32_t a0, uint32_t a1, uint32_t a2, uint32_t a3,
    uint32_t b0, uint32_t b1)
{
    asm volatile(
        "mma.sync.aligned.m16n8k8.row.col.f32.tf32.tf32.f32 "
        "{%0,%1,%2,%3}, {%4,%5,%6,%7}, {%8,%9}, {%0,%1,%2,%3};"
        : "+f"(c0), "+f"(c1), "+f"(c2), "+f"(c3)
        : "r"(a0), "r"(a1), "r"(a2), "r"(a3), "r"(b0), "r"(b1));
}

// ===========================================================================
// Prep: ALL weight prep in one kernel.
// W_hh -> fragment-major layout (see R8 comment).
// ===========================================================================
#define PREP_F4 114688
__global__ void prep_all(
    const float4* __restrict__ Wih, const float4* __restrict__ Aw1,
    const float4* __restrict__ Cw1, const float4* __restrict__ Aw2,
    const float4* __restrict__ Cw2, const float4* __restrict__ Ab1,
    const float4* __restrict__ Cb1, const float*  __restrict__ W_hh,
    float4* __restrict__ wihr, float4* __restrict__ w1c,
    float4* __restrict__ w2a, float4* __restrict__ w2c,
    float4* __restrict__ b1c, float* __restrict__ Wt2)
{
    int i = blockIdx.x * 256 + threadIdx.x;
    if (i < PREP_F4) {
        const float4* src;
        float4* dst;
        if (i < 49152)      { src = Wih + i;            dst = wihr + i; }
        else if (i < 65536) { src = Aw1 + (i - 49152);  dst = w1c + (i - 49152); }
        else if (i < 81920) { src = Cw1 + (i - 65536);  dst = w1c + 16384 + (i - 65536); }
        else if (i < 98304) { src = Aw2 + (i - 81920);  dst = w2a + (i - 81920); }
        else                { src = Cw2 + (i - 98304);  dst = w2c + (i - 98304); }
        float4 v = *src;
        v.x = round_tf32(v.x); v.y = round_tf32(v.y);
        v.z = round_tf32(v.z); v.w = round_tf32(v.w);
        *dst = v;
        if (i < 64)       b1c[i] = Ab1[i];
        else if (i < 128) b1c[i] = Cb1[i - 64];
    } else {
        int j2 = i - PREP_F4;              // 0..196607
        int gcol = j2 >> 8, k = j2 & 255;
        int g = gcol >> 8, rem = gcol & 255;
        int wn = rem >> 5, nt = (rem >> 3) & 3, lanehi = rem & 7;
        int kt = k >> 4, s = (k >> 3) & 1, lanelo = k & 3, b = (k >> 2) & 1;
        int lane = lanehi * 4 + lanelo;
        int idx = (g * 4 + nt) * 2 + b;
        Wt2[(size_t)(kt * 2 + s) * 7168 + (wn * 32 + lane) * 28 + idx] =
            round_tf32(W_hh[(size_t)gcol * 256 + k]);
    }
}

// ===========================================================================
// tf32 mma.sync GEMM (R8 config restored): 128x128x32, 256 threads (2x4),
// warp 64x32, cp.async 2-stage, 2 CTAs/SM, ldmatrix fragments.
// ROUND_A: round A fragments post-ldmatrix (lets A be raw fp32, e.g. features).
// grid = (N/128, M/128) -- N fastest for A reuse in L2.
// ===========================================================================
#define GBM 128
#define GBN 128
#define GBK 32
#define APITCH 36
#define STAGEF (GBM * APITCH)                 // 4608 floats (A or B)
#define GEMM_SMEM ((4 * STAGEF + GBN) * 4)    // 74240 bytes -> 2 CTAs/SM

template<bool DO_TANH, bool ROUND_OUT, bool ROUND_A>
__global__ __launch_bounds__(256, 2) void gemm_mma(
    const float* __restrict__ A, const float* __restrict__ W,
    const float* __restrict__ bias, float* __restrict__ C,
    int N, int K, int lda)
{
    extern __shared__ float sm[];
    float* sBias = sm + 4 * STAGEF;

    const int tid  = threadIdx.x;
    const int lane = tid & 31;
    const int wid  = tid >> 5;
    const int wm   = wid >> 2;
    const int wn   = wid & 3;
    const int    bn = blockIdx.x * GBN;
    const size_t bm = (size_t)blockIdx.y * GBM;

    if (tid < GBN) sBias[tid] = bias[bn + tid];

    const int lrow = tid >> 1;
    const int lkq  = (tid & 1) * 16;
    const float* Ag = A + (bm + lrow) * lda + lkq;
    const float* Wg = W + ((size_t)(bn + lrow)) * K + lkq;

    const uint32_t sbase = smem_u32(sm);
    const int a_lm = (wm * 64 + (lane & 15)) * APITCH + ((lane >> 4) << 2);
    const int b_lm = (wn * 32 + (lane & 7)) * APITCH + (((lane >> 3) & 1) << 2);

    float acc[4][4][4];
#pragma unroll
    for (int mt = 0; mt < 4; mt++)
#pragma unroll
        for (int nt = 0; nt < 4; nt++)
#pragma unroll
            for (int q = 0; q < 4; q++) acc[mt][nt][q] = 0.f;

    const int NK = K / GBK;

    auto stage_copy = [&](int kt) {
        float* st = sm + (kt & 1) * 2 * STAGEF;
        const float* ap = Ag + kt * GBK;
        const float* wp = Wg + kt * GBK;
        float* dA = st + lrow * APITCH + lkq;
        float* dB = st + STAGEF + lrow * APITCH + lkq;
#pragma unroll
        for (int u = 0; u < 4; u++) {
            cp16_cg(dA + 4 * u, ap + 4 * u);
            cp16_cg(dB + 4 * u, wp + 4 * u);
        }
    };

    stage_copy(0); CP_COMMIT();
    stage_copy(1); CP_COMMIT();

    for (int kt = 0; kt < NK; kt++) {
        if (kt < NK - 1) { CP_WAIT1(); } else { CP_WAITALL(); }
        __syncthreads();

        const uint32_t bufA = sbase + ((kt & 1) * 2 * STAGEF) * 4;
        const uint32_t bufB = bufA + STAGEF * 4;
#pragma unroll
        for (int k8 = 0; k8 < 4; k8++) {
            const int k0 = k8 * 8;
            uint32_t a[4][4];
#pragma unroll
            for (int mt = 0; mt < 4; mt++) {
                LDMX4(a[mt][0], a[mt][1], a[mt][2], a[mt][3],
                      bufA + (a_lm + mt * 16 * APITCH + k0) * 4);
                if (ROUND_A) {
#pragma unroll
                    for (int q = 0; q < 4; q++)
                        a[mt][q] = round_tf32_u(a[mt][q]);
                }
            }
            uint32_t b[4][2];
#pragma unroll
            for (int nt = 0; nt < 4; nt++)
                LDMX2(b[nt][0], b[nt][1],
                      bufB + (b_lm + nt * 8 * APITCH + k0) * 4);
#pragma unroll
            for (int mt = 0; mt < 4; mt++)
#pragma unroll
                for (int nt = 0; nt < 4; nt++)
                    mma_tf32(acc[mt][nt][0], acc[mt][nt][1],
                             acc[mt][nt][2], acc[mt][nt][3],
                             a[mt][0], a[mt][1], a[mt][2], a[mt][3],
                             b[nt][0], b[nt][1]);
        }
        __syncthreads();
        if (kt + 2 < NK) { stage_copy(kt + 2); CP_COMMIT(); }
    }

#pragma unroll
    for (int mt = 0; mt < 4; mt++) {
        const size_t row = bm + wm * 64 + mt * 16 + (lane >> 2);
        float* c0p = C + row * N + bn + wn * 32;
        float* c1p = c0p + (size_t)8 * N;
#pragma unroll
        for (int nt = 0; nt < 4; nt++) {
            const int cc = nt * 8 + (lane & 3) * 2;
            const float bx = sBias[wn * 32 + cc];
            const float by = sBias[wn * 32 + cc + 1];
            float v0 = acc[mt][nt][0] + bx, v1 = acc[mt][nt][1] + by;
            float v2 = acc[mt][nt][2] + bx, v3 = acc[mt][nt][3] + by;
            if (DO_TANH) {
                v0 = tanhf(v0); v1 = tanhf(v1);
                v2 = tanhf(v2); v3 = tanhf(v3);
            }
            if (ROUND_OUT) {
                v0 = round_tf32(v0); v1 = round_tf32(v1);
                v2 = round_tf32(v2); v3 = round_tf32(v3);
            }
            *(float2*)(c0p + cc) = make_float2(v0, v1);
            *(float2*)(c1p + cc) = make_float2(v2, v3);
        }
    }
}

// ===========================================================================
// GRU scan (unchanged from R8): 512 threads, fragment-major W, fp32 h in regs.
// ===========================================================================
#define RB2 32
#define HT_PITCH 260
#define WS_STAGE 14336
#define GRU_SMEM ((3*WS_STAGE + 32*HT_PITCH + 768) * 4 + 32*64*4)   // 216576 B

__global__ __launch_bounds__(512, 1) void gru_mma(
    const float* __restrict__ xg, const float* __restrict__ h0,
    const float* __restrict__ Wt2, const float* __restrict__ b_hh,
    const int* __restrict__ starts,
    float* __restrict__ lat, float* __restrict__ h_out)
{
    extern __shared__ float sm[];
    float* ws  = sm;                          // [3][14336]
    float* ht  = ws + 3 * WS_STAGE;           // [32][260]
    int*   sst = (int*)(ht + 32 * HT_PITCH);  // [32][64]
    float* sbh = (float*)(sst + 32 * 64);     // [768]

    const int tid  = threadIdx.x;
    const int lane = tid & 31;
    const int w    = tid >> 5;
    const int wm   = w >> 3;
    const int wn   = w & 7;
    const int b0   = blockIdx.x * RB2;

    for (int i = tid; i < 32 * 64; i += 512)
        sst[i] = starts[(size_t)(b0 + (i >> 6)) * TT + (i & 63)];
    for (int i = tid; i < 768; i += 512) sbh[i] = b_hh[i];

    float2 hreg[2][4];
#pragma unroll
    for (int rh = 0; rh < 2; rh++) {
        const int row = wm * 16 + rh * 8 + (lane >> 2);
        const float m0 = starts[(size_t)(b0 + row) * TT] ? 0.f : 1.f;
#pragma unroll
        for (int nt = 0; nt < 4; nt++) {
            const int c = wn * 32 + nt * 8 + (lane & 3) * 2;
            float2 v = *(const float2*)(h0 + (size_t)(b0 + row) * 256 + c);
            v.x *= m0; v.y *= m0;
            hreg[rh][nt] = v;
            ht[row * HT_PITCH + c]     = round_tf32(v.x);
            ht[row * HT_PITCH + c + 1] = round_tf32(v.y);
        }
    }

    auto stageW = [&](int tile, int buf) {
        const float4* src = (const float4*)(Wt2 + (size_t)tile * WS_STAGE) + tid;
        float4* dst = (float4*)(ws + buf * WS_STAGE) + tid;
#pragma unroll
        for (int u = 0; u < 7; u++)
            cp16_cg(dst + u * 512, src + u * 512);
    };

    stageW(0, 0); CP_COMMIT();
    stageW(1, 1); CP_COMMIT();

    const uint32_t ht_lm = smem_u32(ht)
        + ((wm * 16 + (lane & 15)) * HT_PITCH + ((lane >> 4) << 2)) * 4;
    const int bslot = (wn * 32 + lane) * 28;

    const int KS_TOTAL = TT * 16;
    int ks = 0;

    for (int t = 0; t < TT; t++) {
        float acc[12][4];
#pragma unroll
        for (int j = 0; j < 12; j++)
#pragma unroll
            for (int q = 0; q < 4; q++) acc[j][q] = 0.f;

        for (int kt = 0; kt < 16; kt++) {
            if (ks < KS_TOTAL - 1) { CP_WAIT1(); } else { CP_WAITALL(); }
            __syncthreads();

            if (ks + 2 < KS_TOTAL) {
                stageW((ks + 2) & 15, (ks + 2) % 3);
                CP_COMMIT();
            }

            if (tid < 48) {
                int li = kt * 48 + tid;
                int r = li / 24, cl = li % 24;
                l2_prefetch(xg + ((size_t)(b0 + r) * TT + t) * G3 + cl * 32);
            }

            const float* wstage = ws + (ks % 3) * WS_STAGE;
#pragma unroll
            for (int s = 0; s < 2; s++) {
                const int kg = kt * 16 + s * 8;
                uint32_t a0, a1, a2, a3;
                LDMX4(a0, a1, a2, a3, ht_lm + kg * 4);
                const float* wb = wstage + s * 7168 + bslot;
                float4 bf[6];
#pragma unroll
                for (int u = 0; u < 6; u++)
                    bf[u] = *(const float4*)(wb + u * 4);
                const uint32_t* bw = (const uint32_t*)bf;
#pragma unroll
                for (int j = 0; j < 12; j++)
                    mma_tf32(acc[j][0], acc[j][1], acc[j][2], acc[j][3],
                             a0, a1, a2, a3, bw[j * 2], bw[j * 2 + 1]);
            }
            ks++;
        }
        __syncthreads();

#pragma unroll
        for (int rh = 0; rh < 2; rh++) {
            const int row  = wm * 16 + rh * 8 + (lane >> 2);
            const int grow = b0 + row;
            const size_t gbt = (size_t)grow * TT + t;
            const float* xb = xg + gbt * 768;
            float* lb = lat + gbt * 256;
            float msk = 1.f;
            if (t < TT - 1) msk = sst[row * 64 + t + 1] ? 0.f : 1.f;
            const int q = rh * 2;
#pragma unroll
            for (int nt = 0; nt < 4; nt++) {
                const int c = wn * 32 + nt * 8 + (lane & 3) * 2;
                float2 xr = *(const float2*)(xb + c);
                float2 xz = *(const float2*)(xb + 256 + c);
                float2 xn = *(const float2*)(xb + 512 + c);
                float hr0 = acc[nt][q]         + sbh[c];
                float hr1 = acc[nt][q + 1]     + sbh[c + 1];
                float hz0 = acc[4 + nt][q]     + sbh[256 + c];
                float hz1 = acc[4 + nt][q + 1] + sbh[256 + c + 1];
                float hn0 = acc[8 + nt][q]     + sbh[512 + c];
                float hn1 = acc[8 + nt][q + 1] + sbh[512 + c + 1];
                float r0 = 1.f / (1.f + __expf(-(xr.x + hr0)));
                float r1 = 1.f / (1.f + __expf(-(xr.y + hr1)));
                float z0 = 1.f / (1.f + __expf(-(xz.x + hz0)));
                float z1 = 1.f / (1.f + __expf(-(xz.y + hz1)));
                float n0 = tanhf(xn.x + r0 * hn0);
                float n1 = tanhf(xn.y + r1 * hn1);
                float v0 = (1.f - z0) * n0 + z0 * hreg[rh][nt].x;
                float v1 = (1.f - z1) * n1 + z1 * hreg[rh][nt].y;
                *(float2*)(lb + c) = make_float2(round_tf32(v0), round_tf32(v1));
                if (t == TT - 1) {
                    *(float2*)(h_out + (size_t)grow * 256 + c) = make_float2(v0, v1);
                } else {
                    float m0 = v0 * msk, m1 = v1 * msk;
                    hreg[rh][nt] = make_float2(m0, m1);
                    ht[row * HT_PITCH + c]     = round_tf32(m0);
                    ht[row * HT_PITCH + c + 1] = round_tf32(m1);
                }
            }
        }
    }
}

// ---------------------------------------------------------------------------
// Heads
// ---------------------------------------------------------------------------
__global__ __launch_bounds__(256) void head_kernel(
    const float* __restrict__ t2a, const float* __restrict__ t2c,
    const float* __restrict__ Aw3, const float* __restrict__ Ab3,
    const float* __restrict__ Cw3, const float* __restrict__ Cb3,
    float* __restrict__ out)
{
    __shared__ float wa[12][256];
    __shared__ float wc[256];
    __shared__ float ba[12];
    __shared__ float bc;

    const int tid = threadIdx.x;
    for (int i = tid; i < 12 * 256; i += 256) wa[i >> 8][i & 255] = Aw3[i];
    if (tid < 256) wc[tid] = Cw3[tid];
    if (tid < 12)  ba[tid] = Ab3[tid];
    if (tid == 0)  bc = Cb3[0];
    __syncthreads();

    const int warp = tid >> 5;
    const int lane = tid & 31;
    const size_t row = (size_t)blockIdx.x * 8 + warp;

    const float* ra = t2a + row * 256;
    const float* rc = t2c + row * 256;
    float va[8], vc[8];
#pragma unroll
    for (int u = 0; u < 8; u++) {
        va[u] = ra[lane + 32 * u];
        vc[u] = rc[lane + 32 * u];
    }

    float s[13];
#pragma unroll
    for (int a = 0; a < 12; a++) {
        float acc = 0.f;
#pragma unroll
        for (int u = 0; u < 8; u++) acc = fmaf(va[u], wa[a][lane + 32 * u], acc);
        s[a] = acc;
    }
    {
        float acc = 0.f;
#pragma unroll
        for (int u = 0; u < 8; u++) acc = fmaf(vc[u], wc[lane + 32 * u], acc);
        s[12] = acc;
    }
#pragma unroll
    for (int a = 0; a < 13; a++)
#pragma unroll
        for (int o = 16; o > 0; o >>= 1)
            s[a] += __shfl_xor_sync(0xffffffffu, s[a], o);
    if (lane == 0) {
        float* o = out + row * 13;
#pragma unroll
        for (int a = 0; a < 12; a++) o[a] = s[a] + ba[a];
        o[12] = s[12] + bc;
    }
}

__global__ void std_kernel(const float* __restrict__ log_std, float* __restrict__ out)
{
    int a = threadIdx.x;
    if (a < AA) {
        float v = log_std[a];
        v = fminf(fmaxf(v, -2.0f), -0.5f);
        out[a] = __expf(v);
    }
}

// ---------------------------------------------------------------------------
extern "C" void kernel_launch(void* const* d_in, const int* in_sizes, int n_in,
                              void* d_out, int out_size)
{
    const float* features = (const float*)d_in[0];
    const float* hidden   = (const float*)d_in[1];
    const float* W_ih     = (const float*)d_in[2];
    const float* W_hh     = (const float*)d_in[3];
    const float* b_ih     = (const float*)d_in[4];
    const float* b_hh     = (const float*)d_in[5];
    const float* Aw1      = (const float*)d_in[6];
    const float* Ab1      = (const float*)d_in[7];
    const float* Aw2      = (const float*)d_in[8];
    const float* Ab2      = (const float*)d_in[9];
    const float* Aw3      = (const float*)d_in[10];
    const float* Ab3      = (const float*)d_in[11];
    const float* Cw1      = (const float*)d_in[12];
    const float* Cb1      = (const float*)d_in[13];
    const float* Cw2      = (const float*)d_in[14];
    const float* Cb2      = (const float*)d_in[15];
    const float* Cw3      = (const float*)d_in[16];
    const float* Cb3      = (const float*)d_in[17];
    const float* log_std  = (const float*)d_in[18];
    const int*   starts   = (const int*)d_in[19];

    float* out      = (float*)d_out;
    float* out_main = out;
    float* out_std  = out + (size_t)MTOT * 13;
    float* out_h    = out + (size_t)MTOT * 13 + AA;

    float *xg, *lat, *t2a, *t2c, *wt2, *wihr, *w1c, *w2a, *w2c, *b1c;
    cudaGetSymbolAddress((void**)&xg,   g_xg);
    cudaGetSymbolAddress((void**)&lat,  g_lat);
    cudaGetSymbolAddress((void**)&t2a,  g_t2a);
    cudaGetSymbolAddress((void**)&t2c,  g_t2c);
    cudaGetSymbolAddress((void**)&wt2,  g_wt2);
    cudaGetSymbolAddress((void**)&wihr, g_wihr);
    cudaGetSymbolAddress((void**)&w1c,  g_w1c);
    cudaGetSymbolAddress((void**)&w2a,  g_w2a);
    cudaGetSymbolAddress((void**)&w2c,  g_w2c);
    cudaGetSymbolAddress((void**)&b1c,  g_b1c);

    cudaFuncSetAttribute(gemm_mma<false, false, true>,
                         cudaFuncAttributeMaxDynamicSharedMemorySize, GEMM_SMEM);
    cudaFuncSetAttribute(gemm_mma<true, true, false>,
                         cudaFuncAttributeMaxDynamicSharedMemorySize, GEMM_SMEM);
    cudaFuncSetAttribute(gemm_mma<true, false, false>,
                         cudaFuncAttributeMaxDynamicSharedMemorySize, GEMM_SMEM);
    cudaFuncSetAttribute(gru_mma,
                         cudaFuncAttributeMaxDynamicSharedMemorySize, GRU_SMEM);

    dim3 blk(256);

    // 1) all weight prep (round + W_hh fragment-major permute + bias concat)
    prep_all<<<1216, blk>>>(
        (const float4*)W_ih, (const float4*)Aw1, (const float4*)Cw1,
        (const float4*)Aw2, (const float4*)Cw2,
        (const float4*)Ab1, (const float4*)Cb1, W_hh,
        (float4*)wihr, (float4*)w1c, (float4*)w2a, (float4*)w2c,
        (float4*)b1c, wt2);
    // 2) std (independent)
    std_kernel<<<1, 32>>>(log_std, out_std);
    // 3) xg = features @ W_ih^T + b_ih (A-fragments rounded in-register)
    gemm_mma<false, false, true><<<dim3(G3/GBN, MTOT/GBM), blk, GEMM_SMEM>>>(
        features, wihr, b_ih, xg, G3, FF, FF);
    // 4) GRU scan -> lat (tf32-rounded), h_last      <-- profiled launch
    gru_mma<<<BB/RB2, dim3(512), GRU_SMEM>>>(xg, hidden, wt2, b_hh, starts, lat, out_h);
    // 5) fused actor+critic layer1 (reuses g_xg as [M,512])
    gemm_mma<true, true, false><<<dim3(512/GBN, MTOT/GBM), blk, GEMM_SMEM>>>(
        lat, w1c, b1c, xg, 512, HH, HH);
    // 6,7) layer2 actor / critic
    gemm_mma<true, false, false><<<dim3(HH/GBN, MTOT/GBM), blk, GEMM_SMEM>>>(
        xg,       w2a, Ab2, t2a, HH, HH, 512);
    gemm_mma<true, false, false><<<dim3(HH/GBN, MTOT/GBM), blk, GEMM_SMEM>>>(
        xg + 256, w2c, Cb2, t2c, HH, HH, 512);
    // 8) heads
    head_kernel<<<MTOT/8, blk>>>(t2a, t2c, Aw3, Ab3, Cw3, Cb3, out_main);
}

// round 11
// speedup vs baseline: 1.1318x; 1.0540x over previous
#include <cuda_runtime.h>
#include <math.h>
#include <stdint.h>

// Problem dims
#define BB 4096
#define TT 64
#define FF 256
#define HH 256
#define AA 12
#define MTOT (BB*TT)            // 262144 rows
#define G3  768

// Scratch (device globals; no cudaMalloc allowed)
__device__ float g_xg [(size_t)MTOT * G3];     // xg, later reused as t12 [M,512]
__device__ float g_lat[(size_t)MTOT * HH];
__device__ float g_pa [(size_t)2 * MTOT * 16]; // actor head partials [2][M][16]
__device__ float g_pc [(size_t)2 * MTOT];      // critic head partials [2][M]
__device__ float g_wt2[16 * 14336];            // W_hh fragment-major (padded slots)
__device__ float g_wihr[768 * 256];            // W_ih rounded
__device__ float g_w1c [512 * 256];            // [Aw1; Cw1] rounded
__device__ float g_w2a [256 * 256];
__device__ float g_w2c [256 * 256];
__device__ float g_b1c [512];                  // [Ab1 | Cb1]
__device__ float g_w3f [4096];                 // Aw3 B-fragments [32ksub][2nt][32ln][2]

__device__ __forceinline__ float round_tf32(float x) {
    uint32_t r;
    asm("cvt.rna.tf32.f32 %0, %1;" : "=r"(r) : "f"(x));
    return __uint_as_float(r);
}
__device__ __forceinline__ uint32_t round_tf32_u(uint32_t x) {
    uint32_t r;
    asm("cvt.rna.tf32.f32 %0, %1;" : "=r"(r) : "f"(__uint_as_float(x)));
    return r;
}
__device__ __forceinline__ uint32_t cvt_tf32_f(float x) {
    uint32_t r;
    asm("cvt.rna.tf32.f32 %0, %1;" : "=r"(r) : "f"(x));
    return r;
}

__device__ __forceinline__ uint32_t smem_u32(const void* p) {
    uint32_t a;
    asm("{ .reg .u64 t; cvta.to.shared.u64 t, %1; cvt.u32.u64 %0, t; }"
        : "=r"(a) : "l"(p));
    return a;
}

__device__ __forceinline__ void cp16_cg(void* dst, const void* src) {
    asm volatile("cp.async.cg.shared.global [%0], [%1], 16;"
                 :: "r"(smem_u32(dst)), "l"(src) : "memory");
}
__device__ __forceinline__ void l2_prefetch(const void* p) {
    asm volatile("prefetch.global.L2 [%0];" :: "l"(p));
}
#define CP_COMMIT()  asm volatile("cp.async.commit_group;" ::: "memory")
#define CP_WAIT1()   asm volatile("cp.async.wait_group 1;" ::: "memory")
#define CP_WAITALL() asm volatile("cp.async.wait_all;" ::: "memory")

#define LDMX4(r0,r1,r2,r3,addr) \
    asm volatile("ldmatrix.sync.aligned.m8n8.x4.shared.b16 {%0,%1,%2,%3}, [%4];" \
                 : "=r"(r0),"=r"(r1),"=r"(r2),"=r"(r3) : "r"(addr))
#define LDMX2(r0,r1,addr) \
    asm volatile("ldmatrix.sync.aligned.m8n8.x2.shared.b16 {%0,%1}, [%2];" \
                 : "=r"(r0),"=r"(r1) : "r"(addr))

__device__ __forceinline__ void mma_tf32(
    float& c0, float& c1, float& c2, float& c3,
    uint32_t a0, uint32_t a1, uint32_t a2, uint32_t a3,
    uint32_t b0, uint32_t b1)
{
    asm volatile(
        "mma.sync.aligned.m16n8k8.row.col.f32.tf32.tf32.f32 "
        "{%0,%1,%2,%3}, {%4,%5,%6,%7}, {%8,%9}, {%0,%1,%2,%3};"
        : "+f"(c0), "+f"(c1), "+f"(c2), "+f"(c3)
        : "r"(a0), "r"(a1), "r"(a2), "r"(a3), "r"(b0), "r"(b1));
}

// ===========================================================================
// Prep: ALL weight prep in one kernel.
// ===========================================================================
#define PREP_F4  114688
#define PREP_WHH (PREP_F4 + 196608)           // 311296
#define PREP_TOT (PREP_WHH + 4096)            // 315392 -> 1232 blocks
__global__ void prep_all(
    const float4* __restrict__ Wih, const float4* __restrict__ Aw1,
    const float4* __restrict__ Cw1, const float4* __restrict__ Aw2,
    const float4* __restrict__ Cw2, const float4* __restrict__ Ab1,
    const float4* __restrict__ Cb1, const float*  __restrict__ W_hh,
    const float*  __restrict__ Aw3,
    float4* __restrict__ wihr, float4* __restrict__ w1c,
    float4* __restrict__ w2a, float4* __restrict__ w2c,
    float4* __restrict__ b1c, float* __restrict__ Wt2,
    float* __restrict__ w3f)
{
    int i = blockIdx.x * 256 + threadIdx.x;
    if (i < PREP_F4) {
        const float4* src;
        float4* dst;
        if (i < 49152)      { src = Wih + i;            dst = wihr + i; }
        else if (i < 65536) { src = Aw1 + (i - 49152);  dst = w1c + (i - 49152); }
        else if (i < 81920) { src = Cw1 + (i - 65536);  dst = w1c + 16384 + (i - 65536); }
        else if (i < 98304) { src = Aw2 + (i - 81920);  dst = w2a + (i - 81920); }
        else                { src = Cw2 + (i - 98304);  dst = w2c + (i - 98304); }
        float4 v = *src;
        v.x = round_tf32(v.x); v.y = round_tf32(v.y);
        v.z = round_tf32(v.z); v.w = round_tf32(v.w);
        *dst = v;
        if (i < 64)       b1c[i] = Ab1[i];
        else if (i < 128) b1c[i] = Cb1[i - 64];
    } else if (i < PREP_WHH) {
        int j2 = i - PREP_F4;              // 0..196607
        int gcol = j2 >> 8, k = j2 & 255;
        int g = gcol >> 8, rem = gcol & 255;
        int wn = rem >> 5, nt = (rem >> 3) & 3, lanehi = rem & 7;
        int kt = k >> 4, s = (k >> 3) & 1, lanelo = k & 3, b = (k >> 2) & 1;
        int lane = lanehi * 4 + lanelo;
        int idx = (g * 4 + nt) * 2 + b;
        Wt2[(size_t)(kt * 2 + s) * 7168 + (wn * 32 + lane) * 28 + idx] =
            round_tf32(W_hh[(size_t)gcol * 256 + k]);
    } else if (i < PREP_TOT) {
        // Aw3 B-fragments for head mma (m16n8k8): [ksubg][ntile][lane][r]
        int j3 = i - PREP_WHH;             // 0..4095
        int ksubg = j3 >> 7;
        int rest  = j3 & 127;
        int ntile = rest >> 6;
        int lane  = (rest >> 1) & 31;
        int r     = rest & 1;
        int kg = ksubg * 8 + (lane & 3) + 4 * r;
        int a  = ntile * 8 + (lane >> 2);
        w3f[j3] = (a < AA) ? round_tf32(Aw3[a * 256 + kg]) : 0.f;
    }
}

// ===========================================================================
// tf32 mma.sync GEMM (generic): 128x128x32, 2 CTAs/SM, ldmatrix, cp.async.
// ===========================================================================
#define GBM 128
#define GBN 128
#define GBK 32
#define APITCH 36
#define STAGEF (GBM * APITCH)
#define GEMM_SMEM ((4 * STAGEF + GBN) * 4)    // 74240 B -> 2 CTAs/SM

// mainloop macro body shared by gemm_mma and gemm_l2 via function template
template<bool ROUND_A>
__device__ __forceinline__ void gemm_mainloop(
    float* sm, const float* Ag, const float* Wg,
    int K, int a_lm, int b_lm, float acc[4][4][4],
    int lrow, int lkq)
{
    const uint32_t sbase = smem_u32(sm);
    const int NK = K / GBK;
    auto stage_copy = [&](int kt) {
        float* st = sm + (kt & 1) * 2 * STAGEF;
        const float* ap = Ag + kt * GBK;
        const float* wp = Wg + kt * GBK;
        float* dA = st + lrow * APITCH + lkq;
        float* dB = st + STAGEF + lrow * APITCH + lkq;
#pragma unroll
        for (int u = 0; u < 4; u++) {
            cp16_cg(dA + 4 * u, ap + 4 * u);
            cp16_cg(dB + 4 * u, wp + 4 * u);
        }
    };
    stage_copy(0); CP_COMMIT();
    stage_copy(1); CP_COMMIT();
    for (int kt = 0; kt < NK; kt++) {
        if (kt < NK - 1) { CP_WAIT1(); } else { CP_WAITALL(); }
        __syncthreads();
        const uint32_t bufA = sbase + ((kt & 1) * 2 * STAGEF) * 4;
        const uint32_t bufB = bufA + STAGEF * 4;
#pragma unroll
        for (int k8 = 0; k8 < 4; k8++) {
            const int k0 = k8 * 8;
            uint32_t a[4][4];
#pragma unroll
            for (int mt = 0; mt < 4; mt++) {
                LDMX4(a[mt][0], a[mt][1], a[mt][2], a[mt][3],
                      bufA + (a_lm + mt * 16 * APITCH + k0) * 4);
                if (ROUND_A) {
#pragma unroll
                    for (int q = 0; q < 4; q++)
                        a[mt][q] = round_tf32_u(a[mt][q]);
                }
            }
            uint32_t b[4][2];
#pragma unroll
            for (int nt = 0; nt < 4; nt++)
                LDMX2(b[nt][0], b[nt][1],
                      bufB + (b_lm + nt * 8 * APITCH + k0) * 4);
#pragma unroll
            for (int mt = 0; mt < 4; mt++)
#pragma unroll
                for (int nt = 0; nt < 4; nt++)
                    mma_tf32(acc[mt][nt][0], acc[mt][nt][1],
                             acc[mt][nt][2], acc[mt][nt][3],
                             a[mt][0], a[mt][1], a[mt][2], a[mt][3],
                             b[nt][0], b[nt][1]);
        }
        __syncthreads();
        if (kt + 2 < NK) { stage_copy(kt + 2); CP_COMMIT(); }
    }
}

template<bool DO_TANH, bool ROUND_OUT, bool ROUND_A>
__global__ __launch_bounds__(256, 2) void gemm_mma(
    const float* __restrict__ A, const float* __restrict__ W,
    const float* __restrict__ bias, float* __restrict__ C,
    int N, int K, int lda)
{
    extern __shared__ float sm[];
    float* sBias = sm + 4 * STAGEF;
    const int tid  = threadIdx.x;
    const int lane = tid & 31;
    const int wid  = tid >> 5;
    const int wm   = wid >> 2;
    const int wn   = wid & 3;
    const int    bn = blockIdx.x * GBN;
    const size_t bm = (size_t)blockIdx.y * GBM;
    if (tid < GBN) sBias[tid] = bias[bn + tid];
    const int lrow = tid >> 1;
    const int lkq  = (tid & 1) * 16;
    const float* Ag = A + (bm + lrow) * lda + lkq;
    const float* Wg = W + ((size_t)(bn + lrow)) * K + lkq;
    const int a_lm = (wm * 64 + (lane & 15)) * APITCH + ((lane >> 4) << 2);
    const int b_lm = (wn * 32 + (lane & 7)) * APITCH + (((lane >> 3) & 1) << 2);

    float acc[4][4][4];
#pragma unroll
    for (int mt = 0; mt < 4; mt++)
#pragma unroll
        for (int nt = 0; nt < 4; nt++)
#pragma unroll
            for (int q = 0; q < 4; q++) acc[mt][nt][q] = 0.f;

    gemm_mainloop<ROUND_A>(sm, Ag, Wg, K, a_lm, b_lm, acc, lrow, lkq);

#pragma unroll
    for (int mt = 0; mt < 4; mt++) {
        const size_t row = bm + wm * 64 + mt * 16 + (lane >> 2);
        float* c0p = C + row * N + bn + wn * 32;
        float* c1p = c0p + (size_t)8 * N;
#pragma unroll
        for (int nt = 0; nt < 4; nt++) {
            const int cc = nt * 8 + (lane & 3) * 2;
            const float bx = sBias[wn * 32 + cc];
            const float by = sBias[wn * 32 + cc + 1];
            float v0 = acc[mt][nt][0] + bx, v1 = acc[mt][nt][1] + by;
            float v2 = acc[mt][nt][2] + bx, v3 = acc[mt][nt][3] + by;
            if (DO_TANH) {
                v0 = tanhf(v0); v1 = tanhf(v1);
                v2 = tanhf(v2); v3 = tanhf(v3);
            }
            if (ROUND_OUT) {
                v0 = round_tf32(v0); v1 = round_tf32(v1);
                v2 = round_tf32(v2); v3 = round_tf32(v3);
            }
            *(float2*)(c0p + cc) = make_float2(v0, v1);
            *(float2*)(c1p + cc) = make_float2(v2, v3);
        }
    }
}

// ===========================================================================
// Layer-2 GEMM fused with head. Writes head partials only (no t2 tensor).
// ACTOR: 64x32 -> 64x16 head via shuffle-converted A-frags + mma (Aw3 frags).
// CRITIC: 1-wide head via FFMA.
// Cross-CTA (2 column blocks) combined later by combine_kernel.
// ===========================================================================
template<bool ACTOR>
__global__ __launch_bounds__(256, 2) void gemm_l2(
    const float* __restrict__ A, const float* __restrict__ W,
    const float* __restrict__ bias, const float* __restrict__ w3f,
    const float* __restrict__ Cw3,
    float* __restrict__ partial, int K, int lda)
{
    extern __shared__ float sm[];
    float* sBias = sm + 4 * STAGEF;
    const int tid  = threadIdx.x;
    const int lane = tid & 31;
    const int wid  = tid >> 5;
    const int wm   = wid >> 2;
    const int wn   = wid & 3;
    const int    bn = blockIdx.x * GBN;       // 0 or 128
    const size_t bm = (size_t)blockIdx.y * GBM;
    if (tid < GBN) sBias[tid] = bias[bn + tid];
    const int lrow = tid >> 1;
    const int lkq  = (tid & 1) * 16;
    const float* Ag = A + (bm + lrow) * lda + lkq;
    const float* Wg = W + ((size_t)(bn + lrow)) * K + lkq;
    const int a_lm = (wm * 64 + (lane & 15)) * APITCH + ((lane >> 4) << 2);
    const int b_lm = (wn * 32 + (lane & 7)) * APITCH + (((lane >> 3) & 1) << 2);

    float acc[4][4][4];
#pragma unroll
    for (int mt = 0; mt < 4; mt++)
#pragma unroll
        for (int nt = 0; nt < 4; nt++)
#pragma unroll
            for (int q = 0; q < 4; q++) acc[mt][nt][q] = 0.f;

    gemm_mainloop<false>(sm, Ag, Wg, K, a_lm, b_lm, acc, lrow, lkq);

    // v = tanh(acc + bias) in place
#pragma unroll
    for (int mt = 0; mt < 4; mt++)
#pragma unroll
        for (int nt = 0; nt < 4; nt++) {
            const int cc = nt * 8 + (lane & 3) * 2;
            const float bx = sBias[wn * 32 + cc];
            const float by = sBias[wn * 32 + cc + 1];
            acc[mt][nt][0] = tanhf(acc[mt][nt][0] + bx);
            acc[mt][nt][1] = tanhf(acc[mt][nt][1] + by);
            acc[mt][nt][2] = tanhf(acc[mt][nt][2] + bx);
            acc[mt][nt][3] = tanhf(acc[mt][nt][3] + by);
        }

    const int j    = lane & 3;
    const int srcA = (lane & ~3) | (j >> 1);
    const int srcB = (lane & ~3) | (2 + (j >> 1));
    const bool odd = (lane & 1);

    if (ACTOR) {
        // head: [64 x 32] @ [32 x 16] via 32 mma; per-warp hacc, reduce over wn
        float* hred = sm;  // [128][17] reuse stage area (post-mainloop barrier)
        float hacc[4][2][4];
#pragma unroll
        for (int mt = 0; mt < 4; mt++)
#pragma unroll
            for (int n2 = 0; n2 < 2; n2++)
#pragma unroll
                for (int q = 0; q < 4; q++) hacc[mt][n2][q] = 0.f;

        const int ksgbase = (bn >> 3) + wn * 4;
#pragma unroll
        for (int ks = 0; ks < 4; ks++) {
            // load B fragments (L2-hot)
            float2 bf0 = *(const float2*)(w3f + (((ksgbase + ks) * 2 + 0) * 32 + lane) * 2);
            float2 bf1 = *(const float2*)(w3f + (((ksgbase + ks) * 2 + 1) * 32 + lane) * 2);
            uint32_t b00 = __float_as_uint(bf0.x), b01 = __float_as_uint(bf0.y);
            uint32_t b10 = __float_as_uint(bf1.x), b11 = __float_as_uint(bf1.y);
#pragma unroll
            for (int mt = 0; mt < 4; mt++) {
                float c0 = acc[mt][ks][0], c1 = acc[mt][ks][1];
                float c2 = acc[mt][ks][2], c3 = acc[mt][ks][3];
                float t0 = __shfl_sync(0xffffffffu, c0, srcA);
                float t1 = __shfl_sync(0xffffffffu, c1, srcA);
                float t2 = __shfl_sync(0xffffffffu, c2, srcA);
                float t3 = __shfl_sync(0xffffffffu, c3, srcA);
                float u0 = __shfl_sync(0xffffffffu, c0, srcB);
                float u1 = __shfl_sync(0xffffffffu, c1, srcB);
                float u2 = __shfl_sync(0xffffffffu, c2, srcB);
                float u3 = __shfl_sync(0xffffffffu, c3, srcB);
                uint32_t a0 = cvt_tf32_f(odd ? t1 : t0);
                uint32_t a1 = cvt_tf32_f(odd ? t3 : t2);
                uint32_t a2 = cvt_tf32_f(odd ? u1 : u0);
                uint32_t a3 = cvt_tf32_f(odd ? u3 : u2);
                mma_tf32(hacc[mt][0][0], hacc[mt][0][1], hacc[mt][0][2], hacc[mt][0][3],
                         a0, a1, a2, a3, b00, b01);
                mma_tf32(hacc[mt][1][0], hacc[mt][1][1], hacc[mt][1][2], hacc[mt][1][3],
                         a0, a1, a2, a3, b10, b11);
            }
        }
        // ordered cross-wn reduce into hred[128][17]
        for (int rr = 0; rr < 4; rr++) {
            if (wn == rr) {
#pragma unroll
                for (int mt = 0; mt < 4; mt++)
#pragma unroll
                    for (int n2 = 0; n2 < 2; n2++)
#pragma unroll
                        for (int q = 0; q < 4; q++) {
                            int row = wm * 64 + mt * 16 + (lane >> 2) + 8 * (q >> 1);
                            int col = n2 * 8 + 2 * (lane & 3) + (q & 1);
                            if (rr == 0) hred[row * 17 + col] = hacc[mt][n2][q];
                            else         hred[row * 17 + col] += hacc[mt][n2][q];
                        }
            }
            __syncthreads();
        }
        // write partials [2][M][16]
        const size_t pbase = (size_t)blockIdx.x * MTOT * 16 + bm * 16;
        for (int i = tid; i < 128 * 16; i += 256)
            partial[pbase + i] = hred[(i >> 4) * 17 + (i & 15)];
    } else {
        // critic: per-thread 64 FFMA with Cw3, shfl + ordered smem reduce
        float* hredc = sm;   // [128]
        float2 cw[4];
#pragma unroll
        for (int nt = 0; nt < 4; nt++)
            cw[nt] = *(const float2*)(Cw3 + bn + wn * 32 + nt * 8 + 2 * (lane & 3));
        float rsum[4][2];   // [mt][row half]
#pragma unroll
        for (int mt = 0; mt < 4; mt++) {
            float s0 = 0.f, s1 = 0.f;
#pragma unroll
            for (int nt = 0; nt < 4; nt++) {
                s0 = fmaf(acc[mt][nt][0], cw[nt].x, s0);
                s0 = fmaf(acc[mt][nt][1], cw[nt].y, s0);
                s1 = fmaf(acc[mt][nt][2], cw[nt].x, s1);
                s1 = fmaf(acc[mt][nt][3], cw[nt].y, s1);
            }
            // reduce over lane&3 (deterministic butterfly)
            s0 += __shfl_xor_sync(0xffffffffu, s0, 1);
            s0 += __shfl_xor_sync(0xffffffffu, s0, 2);
            s1 += __shfl_xor_sync(0xffffffffu, s1, 1);
            s1 += __shfl_xor_sync(0xffffffffu, s1, 2);
            rsum[mt][0] = s0; rsum[mt][1] = s1;
        }
        for (int rr = 0; rr < 4; rr++) {
            if (wn == rr && (lane & 3) == 0) {
#pragma unroll
                for (int mt = 0; mt < 4; mt++)
#pragma unroll
                    for (int qh = 0; qh < 2; qh++) {
                        int row = wm * 64 + mt * 16 + (lane >> 2) + 8 * qh;
                        if (rr == 0) hredc[row] = rsum[mt][qh];
                        else         hredc[row] += rsum[mt][qh];
                    }
            }
            __syncthreads();
        }
        const size_t pbase = (size_t)blockIdx.x * MTOT + bm;
        if (tid < 128) partial[pbase + tid] = hredc[tid];
    }
}

// combine partials -> out[:,0:13]
__global__ __launch_bounds__(256) void combine_kernel(
    const float* __restrict__ pa, const float* __restrict__ pc,
    const float* __restrict__ Ab3, const float* __restrict__ Cb3,
    float* __restrict__ out)
{
    size_t m = (size_t)blockIdx.x * 256 + threadIdx.x;
    const float* p0 = pa + m * 16;
    const float* p1 = pa + (size_t)MTOT * 16 + m * 16;
    float* o = out + m * 13;
#pragma unroll
    for (int a = 0; a < 12; a++)
        o[a] = p0[a] + p1[a] + Ab3[a];
    o[12] = pc[m] + pc[MTOT + m] + Cb3[0];
}

// ===========================================================================
// GRU scan (unchanged from R8/R10)
// ===========================================================================
#define RB2 32
#define HT_PITCH 260
#define WS_STAGE 14336
#define GRU_SMEM ((3*WS_STAGE + 32*HT_PITCH + 768) * 4 + 32*64*4)   // 216576 B

__global__ __launch_bounds__(512, 1) void gru_mma(
    const float* __restrict__ xg, const float* __restrict__ h0,
    const float* __restrict__ Wt2, const float* __restrict__ b_hh,
    const int* __restrict__ starts,
    float* __restrict__ lat, float* __restrict__ h_out)
{
    extern __shared__ float sm[];
    float* ws  = sm;
    float* ht  = ws + 3 * WS_STAGE;
    int*   sst = (int*)(ht + 32 * HT_PITCH);
    float* sbh = (float*)(sst + 32 * 64);

    const int tid  = threadIdx.x;
    const int lane = tid & 31;
    const int w    = tid >> 5;
    const int wm   = w >> 3;
    const int wn   = w & 7;
    const int b0   = blockIdx.x * RB2;

    for (int i = tid; i < 32 * 64; i += 512)
        sst[i] = starts[(size_t)(b0 + (i >> 6)) * TT + (i & 63)];
    for (int i = tid; i < 768; i += 512) sbh[i] = b_hh[i];

    float2 hreg[2][4];
#pragma unroll
    for (int rh = 0; rh < 2; rh++) {
        const int row = wm * 16 + rh * 8 + (lane >> 2);
        const float m0 = starts[(size_t)(b0 + row) * TT] ? 0.f : 1.f;
#pragma unroll
        for (int nt = 0; nt < 4; nt++) {
            const int c = wn * 32 + nt * 8 + (lane & 3) * 2;
            float2 v = *(const float2*)(h0 + (size_t)(b0 + row) * 256 + c);
            v.x *= m0; v.y *= m0;
            hreg[rh][nt] = v;
            ht[row * HT_PITCH + c]     = round_tf32(v.x);
            ht[row * HT_PITCH + c + 1] = round_tf32(v.y);
        }
    }

    auto stageW = [&](int tile, int buf) {
        const float4* src = (const float4*)(Wt2 + (size_t)tile * WS_STAGE) + tid;
        float4* dst = (float4*)(ws + buf * WS_STAGE) + tid;
#pragma unroll
        for (int u = 0; u < 7; u++)
            cp16_cg(dst + u * 512, src + u * 512);
    };

    stageW(0, 0); CP_COMMIT();
    stageW(1, 1); CP_COMMIT();

    const uint32_t ht_lm = smem_u32(ht)
        + ((wm * 16 + (lane & 15)) * HT_PITCH + ((lane >> 4) << 2)) * 4;
    const int bslot = (wn * 32 + lane) * 28;

    const int KS_TOTAL = TT * 16;
    int ks = 0;

    for (int t = 0; t < TT; t++) {
        float acc[12][4];
#pragma unroll
        for (int j = 0; j < 12; j++)
#pragma unroll
            for (int q = 0; q < 4; q++) acc[j][q] = 0.f;

        for (int kt = 0; kt < 16; kt++) {
            if (ks < KS_TOTAL - 1) { CP_WAIT1(); } else { CP_WAITALL(); }
            __syncthreads();

            if (ks + 2 < KS_TOTAL) {
                stageW((ks + 2) & 15, (ks + 2) % 3);
                CP_COMMIT();
            }

            if (tid < 48) {
                int li = kt * 48 + tid;
                int r = li / 24, cl = li % 24;
                l2_prefetch(xg + ((size_t)(b0 + r) * TT + t) * G3 + cl * 32);
            }

            const float* wstage = ws + (ks % 3) * WS_STAGE;
#pragma unroll
            for (int s = 0; s < 2; s++) {
                const int kg = kt * 16 + s * 8;
                uint32_t a0, a1, a2, a3;
                LDMX4(a0, a1, a2, a3, ht_lm + kg * 4);
                const float* wb = wstage + s * 7168 + bslot;
                float4 bf[6];
#pragma unroll
                for (int u = 0; u < 6; u++)
                    bf[u] = *(const float4*)(wb + u * 4);
                const uint32_t* bw = (const uint32_t*)bf;
#pragma unroll
                for (int j = 0; j < 12; j++)
                    mma_tf32(acc[j][0], acc[j][1], acc[j][2], acc[j][3],
                             a0, a1, a2, a3, bw[j * 2], bw[j * 2 + 1]);
            }
            ks++;
        }
        __syncthreads();

#pragma unroll
        for (int rh = 0; rh < 2; rh++) {
            const int row  = wm * 16 + rh * 8 + (lane >> 2);
            const int grow = b0 + row;
            const size_t gbt = (size_t)grow * TT + t;
            const float* xb = xg + gbt * 768;
            float* lb = lat + gbt * 256;
            float msk = 1.f;
            if (t < TT - 1) msk = sst[row * 64 + t + 1] ? 0.f : 1.f;
            const int q = rh * 2;
#pragma unroll
            for (int nt = 0; nt < 4; nt++) {
                const int c = wn * 32 + nt * 8 + (lane & 3) * 2;
                float2 xr = *(const float2*)(xb + c);
                float2 xz = *(const float2*)(xb + 256 + c);
                float2 xn = *(const float2*)(xb + 512 + c);
                float hr0 = acc[nt][q]         + sbh[c];
                float hr1 = acc[nt][q + 1]     + sbh[c + 1];
                float hz0 = acc[4 + nt][q]     + sbh[256 + c];
                float hz1 = acc[4 + nt][q + 1] + sbh[256 + c + 1];
                float hn0 = acc[8 + nt][q]     + sbh[512 + c];
                float hn1 = acc[8 + nt][q + 1] + sbh[512 + c + 1];
                float r0 = 1.f / (1.f + __expf(-(xr.x + hr0)));
                float r1 = 1.f / (1.f + __expf(-(xr.y + hr1)));
                float z0 = 1.f / (1.f + __expf(-(xz.x + hz0)));
                float z1 = 1.f / (1.f + __expf(-(xz.y + hz1)));
                float n0 = tanhf(xn.x + r0 * hn0);
                float n1 = tanhf(xn.y + r1 * hn1);
                float v0 = (1.f - z0) * n0 + z0 * hreg[rh][nt].x;
                float v1 = (1.f - z1) * n1 + z1 * hreg[rh][nt].y;
                *(float2*)(lb + c) = make_float2(round_tf32(v0), round_tf32(v1));
                if (t == TT - 1) {
                    *(float2*)(h_out + (size_t)grow * 256 + c) = make_float2(v0, v1);
                } else {
                    float m0 = v0 * msk, m1 = v1 * msk;
                    hreg[rh][nt] = make_float2(m0, m1);
                    ht[row * HT_PITCH + c]     = round_tf32(m0);
                    ht[row * HT_PITCH + c + 1] = round_tf32(m1);
                }
            }
        }
    }
}

__global__ void std_kernel(const float* __restrict__ log_std, float* __restrict__ out)
{
    int a = threadIdx.x;
    if (a < AA) {
        float v = log_std[a];
        v = fminf(fmaxf(v, -2.0f), -0.5f);
        out[a] = __expf(v);
    }
}

// ---------------------------------------------------------------------------
extern "C" void kernel_launch(void* const* d_in, const int* in_sizes, int n_in,
                              void* d_out, int out_size)
{
    const float* features = (const float*)d_in[0];
    const float* hidden   = (const float*)d_in[1];
    const float* W_ih     = (const float*)d_in[2];
    const float* W_hh     = (const float*)d_in[3];
    const float* b_ih     = (const float*)d_in[4];
    const float* b_hh     = (const float*)d_in[5];
    const float* Aw1      = (const float*)d_in[6];
    const float* Ab1      = (const float*)d_in[7];
    const float* Aw2      = (const float*)d_in[8];
    const float* Ab2      = (const float*)d_in[9];
    const float* Aw3      = (const float*)d_in[10];
    const float* Ab3      = (const float*)d_in[11];
    const float* Cw1      = (const float*)d_in[12];
    const float* Cb1      = (const float*)d_in[13];
    const float* Cw2      = (const float*)d_in[14];
    const float* Cb2      = (const float*)d_in[15];
    const float* Cw3      = (const float*)d_in[16];
    const float* Cb3      = (const float*)d_in[17];
    const float* log_std  = (const float*)d_in[18];
    const int*   starts   = (const int*)d_in[19];

    float* out      = (float*)d_out;
    float* out_main = out;
    float* out_std  = out + (size_t)MTOT * 13;
    float* out_h    = out + (size_t)MTOT * 13 + AA;

    float *xg, *lat, *pa, *pc, *wt2, *wihr, *w1c, *w2a, *w2c, *b1c, *w3f;
    cudaGetSymbolAddress((void**)&xg,   g_xg);
    cudaGetSymbolAddress((void**)&lat,  g_lat);
    cudaGetSymbolAddress((void**)&pa,   g_pa);
    cudaGetSymbolAddress((void**)&pc,   g_pc);
    cudaGetSymbolAddress((void**)&wt2,  g_wt2);
    cudaGetSymbolAddress((void**)&wihr, g_wihr);
    cudaGetSymbolAddress((void**)&w1c,  g_w1c);
    cudaGetSymbolAddress((void**)&w2a,  g_w2a);
    cudaGetSymbolAddress((void**)&w2c,  g_w2c);
    cudaGetSymbolAddress((void**)&b1c,  g_b1c);
    cudaGetSymbolAddress((void**)&w3f,  g_w3f);

    cudaFuncSetAttribute(gemm_mma<false, false, true>,
                         cudaFuncAttributeMaxDynamicSharedMemorySize, GEMM_SMEM);
    cudaFuncSetAttribute(gemm_mma<true, true, false>,
                         cudaFuncAttributeMaxDynamicSharedMemorySize, GEMM_SMEM);
    cudaFuncSetAttribute(gemm_l2<true>,
                         cudaFuncAttributeMaxDynamicSharedMemorySize, GEMM_SMEM);
    cudaFuncSetAttribute(gemm_l2<false>,
                         cudaFuncAttributeMaxDynamicSharedMemorySize, GEMM_SMEM);
    cudaFuncSetAttribute(gru_mma,
                         cudaFuncAttributeMaxDynamicSharedMemorySize, GRU_SMEM);

    dim3 blk(256);

    // 1) all weight prep (incl. Aw3 head fragments)
    prep_all<<<PREP_TOT/256, blk>>>(
        (const float4*)W_ih, (const float4*)Aw1, (const float4*)Cw1,
        (const float4*)Aw2, (const float4*)Cw2,
        (const float4*)Ab1, (const float4*)Cb1, W_hh, Aw3,
        (float4*)wihr, (float4*)w1c, (float4*)w2a, (float4*)w2c,
        (float4*)b1c, wt2, w3f);
    // 2) std (independent)
    std_kernel<<<1, 32>>>(log_std, out_std);
    // 3) xg = features @ W_ih^T + b_ih (A-fragments rounded in-register)
    gemm_mma<false, false, true><<<dim3(G3/GBN, MTOT/GBM), blk, GEMM_SMEM>>>(
        features, wihr, b_ih, xg, G3, FF, FF);
    // 4) GRU scan -> lat (tf32-rounded), h_last      <-- profiled launch
    gru_mma<<<BB/RB2, dim3(512), GRU_SMEM>>>(xg, hidden, wt2, b_hh, starts, lat, out_h);
    // 5) fused actor+critic layer1 (reuses g_xg as [M,512])
    gemm_mma<true, true, false><<<dim3(512/GBN, MTOT/GBM), blk, GEMM_SMEM>>>(
        lat, w1c, b1c, xg, 512, HH, HH);
    // 6,7) layer2 + fused heads -> partials
    gemm_l2<true><<<dim3(HH/GBN, MTOT/GBM), blk, GEMM_SMEM>>>(
        xg,       w2a, Ab2, w3f, Cw3, pa, HH, 512);
    gemm_l2<false><<<dim3(HH/GBN, MTOT/GBM), blk, GEMM_SMEM>>>(
        xg + 256, w2c, Cb2, w3f, Cw3, pc, HH, 512);
    // 8) combine partials + biases -> out[:,0:13]
    combine_kernel<<<MTOT/256, blk>>>(pa, pc, Ab3, Cb3, out_main);
}

// round 12
// speedup vs baseline: 1.1343x; 1.0023x over previous
#include <cuda_runtime.h>
#include <math.h>
#include <stdint.h>

// Problem dims
#define BB 4096
#define TT 64
#define FF 256
#define HH 256
#define AA 12
#define MTOT (BB*TT)            // 262144 rows
#define G3  768

// Scratch (device globals; no cudaMalloc allowed)
__device__ float g_xg [(size_t)MTOT * G3];     // xg, later reused as t12 [M,512]
__device__ float g_lat[(size_t)MTOT * HH];
__device__ float g_pa [(size_t)2 * MTOT * 16]; // actor head partials [2][M][16]
__device__ float g_pc [(size_t)2 * MTOT];      // critic head partials [2][M]
__device__ float g_wt2[16 * 14336];            // W_hh fragment-major (padded slots)
__device__ float g_wihr[768 * 256];            // W_ih rounded
__device__ float g_w1c [512 * 256];            // [Aw1; Cw1] rounded
__device__ float g_w2a [256 * 256];
__device__ float g_w2c [256 * 256];
__device__ float g_b1c [512];                  // [Ab1 | Cb1]
__device__ float g_w3f [4096];                 // Aw3 B-fragments [32ksub][2nt][32ln][2]

__device__ __forceinline__ float round_tf32(float x) {
    uint32_t r;
    asm("cvt.rna.tf32.f32 %0, %1;" : "=r"(r) : "f"(x));
    return __uint_as_float(r);
}
__device__ __forceinline__ uint32_t round_tf32_u(uint32_t x) {
    uint32_t r;
    asm("cvt.rna.tf32.f32 %0, %1;" : "=r"(r) : "f"(__uint_as_float(x)));
    return r;
}
__device__ __forceinline__ uint32_t cvt_tf32_f(float x) {
    uint32_t r;
    asm("cvt.rna.tf32.f32 %0, %1;" : "=r"(r) : "f"(x));
    return r;
}

__device__ __forceinline__ uint32_t smem_u32(const void* p) {
    uint32_t a;
    asm("{ .reg .u64 t; cvta.to.shared.u64 t, %1; cvt.u32.u64 %0, t; }"
        : "=r"(a) : "l"(p));
    return a;
}

__device__ __forceinline__ void cp16_cg(void* dst, const void* src) {
    asm volatile("cp.async.cg.shared.global [%0], [%1], 16;"
                 :: "r"(smem_u32(dst)), "l"(src) : "memory");
}
__device__ __forceinline__ void l2_prefetch(const void* p) {
    asm volatile("prefetch.global.L2 [%0];" :: "l"(p));
}
#define CP_COMMIT()  asm volatile("cp.async.commit_group;" ::: "memory")
#define CP_WAIT1()   asm volatile("cp.async.wait_group 1;" ::: "memory")
#define CP_WAITALL() asm volatile("cp.async.wait_all;" ::: "memory")

#define LDMX4(r0,r1,r2,r3,addr) \
    asm volatile("ldmatrix.sync.aligned.m8n8.x4.shared.b16 {%0,%1,%2,%3}, [%4];" \
                 : "=r"(r0),"=r"(r1),"=r"(r2),"=r"(r3) : "r"(addr))
#define LDMX2(r0,r1,addr) \
    asm volatile("ldmatrix.sync.aligned.m8n8.x2.shared.b16 {%0,%1}, [%2];" \
                 : "=r"(r0),"=r"(r1) : "r"(addr))

__device__ __forceinline__ void mma_tf32(
    float& c0, float& c1, float& c2, float& c3,
    uint32_t a0, uint32_t a1, uint32_t a2, uint32_t a3,
    uint32_t b0, uint32_t b1)
{
    asm volatile(
        "mma.sync.aligned.m16n8k8.row.col.f32.tf32.tf32.f32 "
        "{%0,%1,%2,%3}, {%4,%5,%6,%7}, {%8,%9}, {%0,%1,%2,%3};"
        : "+f"(c0), "+f"(c1), "+f"(c2), "+f"(c3)
        : "r"(a0), "r"(a1), "r"(a2), "r"(a3), "r"(b0), "r"(b1));
}

// ===========================================================================
// Prep: ALL weight prep in one kernel.
// ===========================================================================
#define PREP_F4  114688
#define PREP_WHH (PREP_F4 + 196608)           // 311296
#define PREP_TOT (PREP_WHH + 4096)            // 315392 -> 1232 blocks
__global__ void prep_all(
    const float4* __restrict__ Wih, const float4* __restrict__ Aw1,
    const float4* __restrict__ Cw1, const float4* __restrict__ Aw2,
    const float4* __restrict__ Cw2, const float4* __restrict__ Ab1,
    const float4* __restrict__ Cb1, const float*  __restrict__ W_hh,
    const float*  __restrict__ Aw3,
    float4* __restrict__ wihr, float4* __restrict__ w1c,
    float4* __restrict__ w2a, float4* __restrict__ w2c,
    float4* __restrict__ b1c, float* __restrict__ Wt2,
    float* __restrict__ w3f)
{
    int i = blockIdx.x * 256 + threadIdx.x;
    if (i < PREP_F4) {
        const float4* src;
        float4* dst;
        if (i < 49152)      { src = Wih + i;            dst = wihr + i; }
        else if (i < 65536) { src = Aw1 + (i - 49152);  dst = w1c + (i - 49152); }
        else if (i < 81920) { src = Cw1 + (i - 65536);  dst = w1c + 16384 + (i - 65536); }
        else if (i < 98304) { src = Aw2 + (i - 81920);  dst = w2a + (i - 81920); }
        else                { src = Cw2 + (i - 98304);  dst = w2c + (i - 98304); }
        float4 v = *src;
        v.x = round_tf32(v.x); v.y = round_tf32(v.y);
        v.z = round_tf32(v.z); v.w = round_tf32(v.w);
        *dst = v;
        if (i < 64)       b1c[i] = Ab1[i];
        else if (i < 128) b1c[i] = Cb1[i - 64];
    } else if (i < PREP_WHH) {
        int j2 = i - PREP_F4;              // 0..196607
        int gcol = j2 >> 8, k = j2 & 255;
        int g = gcol >> 8, rem = gcol & 255;
        int wn = rem >> 5, nt = (rem >> 3) & 3, lanehi = rem & 7;
        int kt = k >> 4, s = (k >> 3) & 1, lanelo = k & 3, b = (k >> 2) & 1;
        int lane = lanehi * 4 + lanelo;
        int idx = (g * 4 + nt) * 2 + b;
        Wt2[(size_t)(kt * 2 + s) * 7168 + (wn * 32 + lane) * 28 + idx] =
            round_tf32(W_hh[(size_t)gcol * 256 + k]);
    } else if (i < PREP_TOT) {
        // Aw3 B-fragments for head mma (m16n8k8): [ksubg][ntile][lane][r]
        int j3 = i - PREP_WHH;             // 0..4095
        int ksubg = j3 >> 7;
        int rest  = j3 & 127;
        int ntile = rest >> 6;
        int lane  = (rest >> 1) & 31;
        int r     = rest & 1;
        int kg = ksubg * 8 + (lane & 3) + 4 * r;
        int a  = ntile * 8 + (lane >> 2);
        w3f[j3] = (a < AA) ? round_tf32(Aw3[a * 256 + kg]) : 0.f;
    }
}

// ===========================================================================
// tf32 mma.sync GEMM (generic): 128x128x32, 2 CTAs/SM, ldmatrix, cp.async.
// ===========================================================================
#define GBM 128
#define GBN 128
#define GBK 32
#define APITCH 36
#define STAGEF (GBM * APITCH)
#define GEMM_SMEM ((4 * STAGEF + GBN) * 4)    // 74240 B -> 2 CTAs/SM

// mainloop macro body shared by gemm_mma and gemm_l2 via function template
template<bool ROUND_A>
__device__ __forceinline__ void gemm_mainloop(
    float* sm, const float* Ag, const float* Wg,
    int K, int a_lm, int b_lm, float acc[4][4][4],
    int lrow, int lkq)
{
    const uint32_t sbase = smem_u32(sm);
    const int NK = K / GBK;
    auto stage_copy = [&](int kt) {
        float* st = sm + (kt & 1) * 2 * STAGEF;
        const float* ap = Ag + kt * GBK;
        const float* wp = Wg + kt * GBK;
        float* dA = st + lrow * APITCH + lkq;
        float* dB = st + STAGEF + lrow * APITCH + lkq;
#pragma unroll
        for (int u = 0; u < 4; u++) {
            cp16_cg(dA + 4 * u, ap + 4 * u);
            cp16_cg(dB + 4 * u, wp + 4 * u);
        }
    };
    stage_copy(0); CP_COMMIT();
    stage_copy(1); CP_COMMIT();
    for (int kt = 0; kt < NK; kt++) {
        if (kt < NK - 1) { CP_WAIT1(); } else { CP_WAITALL(); }
        __syncthreads();
        const uint32_t bufA = sbase + ((kt & 1) * 2 * STAGEF) * 4;
        const uint32_t bufB = bufA + STAGEF * 4;
#pragma unroll
        for (int k8 = 0; k8 < 4; k8++) {
            const int k0 = k8 * 8;
            uint32_t a[4][4];
#pragma unroll
            for (int mt = 0; mt < 4; mt++) {
                LDMX4(a[mt][0], a[mt][1], a[mt][2], a[mt][3],
                      bufA + (a_lm + mt * 16 * APITCH + k0) * 4);
                if (ROUND_A) {
#pragma unroll
                    for (int q = 0; q < 4; q++)
                        a[mt][q] = round_tf32_u(a[mt][q]);
                }
            }
            uint32_t b[4][2];
#pragma unroll
            for (int nt = 0; nt < 4; nt++)
                LDMX2(b[nt][0], b[nt][1],
                      bufB + (b_lm + nt * 8 * APITCH + k0) * 4);
#pragma unroll
            for (int mt = 0; mt < 4; mt++)
#pragma unroll
                for (int nt = 0; nt < 4; nt++)
                    mma_tf32(acc[mt][nt][0], acc[mt][nt][1],
                             acc[mt][nt][2], acc[mt][nt][3],
                             a[mt][0], a[mt][1], a[mt][2], a[mt][3],
                             b[nt][0], b[nt][1]);
        }
        __syncthreads();
        if (kt + 2 < NK) { stage_copy(kt + 2); CP_COMMIT(); }
    }
}

template<bool DO_TANH, bool ROUND_OUT, bool ROUND_A>
__global__ __launch_bounds__(256, 2) void gemm_mma(
    const float* __restrict__ A, const float* __restrict__ W,
    const float* __restrict__ bias, float* __restrict__ C,
    int N, int K, int lda)
{
    extern __shared__ float sm[];
    float* sBias = sm + 4 * STAGEF;
    const int tid  = threadIdx.x;
    const int lane = tid & 31;
    const int wid  = tid >> 5;
    const int wm   = wid >> 2;
    const int wn   = wid & 3;
    const int    bn = blockIdx.x * GBN;
    const size_t bm = (size_t)blockIdx.y * GBM;
    if (tid < GBN) sBias[tid] = bias[bn + tid];
    const int lrow = tid >> 1;
    const int lkq  = (tid & 1) * 16;
    const float* Ag = A + (bm + lrow) * lda + lkq;
    const float* Wg = W + ((size_t)(bn + lrow)) * K + lkq;
    const int a_lm = (wm * 64 + (lane & 15)) * APITCH + ((lane >> 4) << 2);
    const int b_lm = (wn * 32 + (lane & 7)) * APITCH + (((lane >> 3) & 1) << 2);

    float acc[4][4][4];
#pragma unroll
    for (int mt = 0; mt < 4; mt++)
#pragma unroll
        for (int nt = 0; nt < 4; nt++)
#pragma unroll
            for (int q = 0; q < 4; q++) acc[mt][nt][q] = 0.f;

    gemm_mainloop<ROUND_A>(sm, Ag, Wg, K, a_lm, b_lm, acc, lrow, lkq);

#pragma unroll
    for (int mt = 0; mt < 4; mt++) {
        const size_t row = bm + wm * 64 + mt * 16 + (lane >> 2);
        float* c0p = C + row * N + bn + wn * 32;
        float* c1p = c0p + (size_t)8 * N;
#pragma unroll
        for (int nt = 0; nt < 4; nt++) {
            const int cc = nt * 8 + (lane & 3) * 2;
            const float bx = sBias[wn * 32 + cc];
            const float by = sBias[wn * 32 + cc + 1];
            float v0 = acc[mt][nt][0] + bx, v1 = acc[mt][nt][1] + by;
            float v2 = acc[mt][nt][2] + bx, v3 = acc[mt][nt][3] + by;
            if (DO_TANH) {
                v0 = tanhf(v0); v1 = tanhf(v1);
                v2 = tanhf(v2); v3 = tanhf(v3);
            }
            if (ROUND_OUT) {
                v0 = round_tf32(v0); v1 = round_tf32(v1);
                v2 = round_tf32(v2); v3 = round_tf32(v3);
            }
            *(float2*)(c0p + cc) = make_float2(v0, v1);
            *(float2*)(c1p + cc) = make_float2(v2, v3);
        }
    }
}

// ===========================================================================
// Layer-2 GEMM fused with head. Writes head partials only (no t2 tensor).
// ACTOR: 64x32 -> 64x16 head via shuffle-converted A-frags + mma (Aw3 frags).
// CRITIC: 1-wide head via FFMA.
// Cross-CTA (2 column blocks) combined later by combine_kernel.
// ===========================================================================
template<bool ACTOR>
__global__ __launch_bounds__(256, 2) void gemm_l2(
    const float* __restrict__ A, const float* __restrict__ W,
    const float* __restrict__ bias, const float* __restrict__ w3f,
    const float* __restrict__ Cw3,
    float* __restrict__ partial, int K, int lda)
{
    extern __shared__ float sm[];
    float* sBias = sm + 4 * STAGEF;
    const int tid  = threadIdx.x;
    const int lane = tid & 31;
    const int wid  = tid >> 5;
    const int wm   = wid >> 2;
    const int wn   = wid & 3;
    const int    bn = blockIdx.x * GBN;       // 0 or 128
    const size_t bm = (size_t)blockIdx.y * GBM;
    if (tid < GBN) sBias[tid] = bias[bn + tid];
    const int lrow = tid >> 1;
    const int lkq  = (tid & 1) * 16;
    const float* Ag = A + (bm + lrow) * lda + lkq;
    const float* Wg = W + ((size_t)(bn + lrow)) * K + lkq;
    const int a_lm = (wm * 64 + (lane & 15)) * APITCH + ((lane >> 4) << 2);
    const int b_lm = (wn * 32 + (lane & 7)) * APITCH + (((lane >> 3) & 1) << 2);

    float acc[4][4][4];
#pragma unroll
    for (int mt = 0; mt < 4; mt++)
#pragma unroll
        for (int nt = 0; nt < 4; nt++)
#pragma unroll
            for (int q = 0; q < 4; q++) acc[mt][nt][q] = 0.f;

    gemm_mainloop<false>(sm, Ag, Wg, K, a_lm, b_lm, acc, lrow, lkq);

    // v = tanh(acc + bias) in place
#pragma unroll
    for (int mt = 0; mt < 4; mt++)
#pragma unroll
        for (int nt = 0; nt < 4; nt++) {
            const int cc = nt * 8 + (lane & 3) * 2;
            const float bx = sBias[wn * 32 + cc];
            const float by = sBias[wn * 32 + cc + 1];
            acc[mt][nt][0] = tanhf(acc[mt][nt][0] + bx);
            acc[mt][nt][1] = tanhf(acc[mt][nt][1] + by);
            acc[mt][nt][2] = tanhf(acc[mt][nt][2] + bx);
            acc[mt][nt][3] = tanhf(acc[mt][nt][3] + by);
        }

    const int j    = lane & 3;
    const int srcA = (lane & ~3) | (j >> 1);
    const int srcB = (lane & ~3) | (2 + (j >> 1));
    const bool odd = (lane & 1);

    if (ACTOR) {
        // head: [64 x 32] @ [32 x 16] via 32 mma; per-warp hacc, reduce over wn
        float* hred = sm;  // [128][17] reuse stage area (post-mainloop barrier)
        float hacc[4][2][4];
#pragma unroll
        for (int mt = 0; mt < 4; mt++)
#pragma unroll
            for (int n2 = 0; n2 < 2; n2++)
#pragma unroll
                for (int q = 0; q < 4; q++) hacc[mt][n2][q] = 0.f;

        const int ksgbase = (bn >> 3) + wn * 4;
#pragma unroll
        for (int ks = 0; ks < 4; ks++) {
            // load B fragments (L2-hot)
            float2 bf0 = *(const float2*)(w3f + (((ksgbase + ks) * 2 + 0) * 32 + lane) * 2);
            float2 bf1 = *(const float2*)(w3f + (((ksgbase + ks) * 2 + 1) * 32 + lane) * 2);
            uint32_t b00 = __float_as_uint(bf0.x), b01 = __float_as_uint(bf0.y);
            uint32_t b10 = __float_as_uint(bf1.x), b11 = __float_as_uint(bf1.y);
#pragma unroll
            for (int mt = 0; mt < 4; mt++) {
                float c0 = acc[mt][ks][0], c1 = acc[mt][ks][1];
                float c2 = acc[mt][ks][2], c3 = acc[mt][ks][3];
                float t0 = __shfl_sync(0xffffffffu, c0, srcA);
                float t1 = __shfl_sync(0xffffffffu, c1, srcA);
                float t2 = __shfl_sync(0xffffffffu, c2, srcA);
                float t3 = __shfl_sync(0xffffffffu, c3, srcA);
                float u0 = __shfl_sync(0xffffffffu, c0, srcB);
                float u1 = __shfl_sync(0xffffffffu, c1, srcB);
                float u2 = __shfl_sync(0xffffffffu, c2, srcB);
                float u3 = __shfl_sync(0xffffffffu, c3, srcB);
                uint32_t a0 = cvt_tf32_f(odd ? t1 : t0);
                uint32_t a1 = cvt_tf32_f(odd ? t3 : t2);
                uint32_t a2 = cvt_tf32_f(odd ? u1 : u0);
                uint32_t a3 = cvt_tf32_f(odd ? u3 : u2);
                mma_tf32(hacc[mt][0][0], hacc[mt][0][1], hacc[mt][0][2], hacc[mt][0][3],
                         a0, a1, a2, a3, b00, b01);
                mma_tf32(hacc[mt][1][0], hacc[mt][1][1], hacc[mt][1][2], hacc[mt][1][3],
                         a0, a1, a2, a3, b10, b11);
            }
        }
        // ordered cross-wn reduce into hred[128][17]
        for (int rr = 0; rr < 4; rr++) {
            if (wn == rr) {
#pragma unroll
                for (int mt = 0; mt < 4; mt++)
#pragma unroll
                    for (int n2 = 0; n2 < 2; n2++)
#pragma unroll
                        for (int q = 0; q < 4; q++) {
                            int row = wm * 64 + mt * 16 + (lane >> 2) + 8 * (q >> 1);
                            int col = n2 * 8 + 2 * (lane & 3) + (q & 1);
                            if (rr == 0) hred[row * 17 + col] = hacc[mt][n2][q];
                            else         hred[row * 17 + col] += hacc[mt][n2][q];
                        }
            }
            __syncthreads();
        }
        // write partials [2][M][16]
        const size_t pbase = (size_t)blockIdx.x * MTOT * 16 + bm * 16;
        for (int i = tid; i < 128 * 16; i += 256)
            partial[pbase + i] = hred[(i >> 4) * 17 + (i & 15)];
    } else {
        // critic: per-thread 64 FFMA with Cw3, shfl + ordered smem reduce
        float* hredc = sm;   // [128]
        float2 cw[4];
#pragma unroll
        for (int nt = 0; nt < 4; nt++)
            cw[nt] = *(const float2*)(Cw3 + bn + wn * 32 + nt * 8 + 2 * (lane & 3));
        float rsum[4][2];   // [mt][row half]
#pragma unroll
        for (int mt = 0; mt < 4; mt++) {
            float s0 = 0.f, s1 = 0.f;
#pragma unroll
            for (int nt = 0; nt < 4; nt++) {
                s0 = fmaf(acc[mt][nt][0], cw[nt].x, s0);
                s0 = fmaf(acc[mt][nt][1], cw[nt].y, s0);
                s1 = fmaf(acc[mt][nt][2], cw[nt].x, s1);
                s1 = fmaf(acc[mt][nt][3], cw[nt].y, s1);
            }
            // reduce over lane&3 (deterministic butterfly)
            s0 += __shfl_xor_sync(0xffffffffu, s0, 1);
            s0 += __shfl_xor_sync(0xffffffffu, s0, 2);
            s1 += __shfl_xor_sync(0xffffffffu, s1, 1);
            s1 += __shfl_xor_sync(0xffffffffu, s1, 2);
            rsum[mt][0] = s0; rsum[mt][1] = s1;
        }
        for (int rr = 0; rr < 4; rr++) {
            if (wn == rr && (lane & 3) == 0) {
#pragma unroll
                for (int mt = 0; mt < 4; mt++)
#pragma unroll
                    for (int qh = 0; qh < 2; qh++) {
                        int row = wm * 64 + mt * 16 + (lane >> 2) + 8 * qh;
                        if (rr == 0) hredc[row] = rsum[mt][qh];
                        else         hredc[row] += rsum[mt][qh];
                    }
            }
            __syncthreads();
        }
        const size_t pbase = (size_t)blockIdx.x * MTOT + bm;
        if (tid < 128) partial[pbase + tid] = hredc[tid];
    }
}

// combine partials -> out[:,0:13]
__global__ __launch_bounds__(256) void combine_kernel(
    const float* __restrict__ pa, const float* __restrict__ pc,
    const float* __restrict__ Ab3, const float* __restrict__ Cb3,
    float* __restrict__ out)
{
    size_t m = (size_t)blockIdx.x * 256 + threadIdx.x;
    const float* p0 = pa + m * 16;
    const float* p1 = pa + (size_t)MTOT * 16 + m * 16;
    float* o = out + m * 13;
#pragma unroll
    for (int a = 0; a < 12; a++)
        o[a] = p0[a] + p1[a] + Ab3[a];
    o[12] = pc[m] + pc[MTOT + m] + Cb3[0];
}

// ===========================================================================
// GRU scan (unchanged from R8/R10)
// ===========================================================================
#define RB2 32
#define HT_PITCH 260
#define WS_STAGE 14336
#define GRU_SMEM ((3*WS_STAGE + 32*HT_PITCH + 768) * 4 + 32*64*4)   // 216576 B

__global__ __launch_bounds__(512, 1) void gru_mma(
    const float* __restrict__ xg, const float* __restrict__ h0,
    const float* __restrict__ Wt2, const float* __restrict__ b_hh,
    const int* __restrict__ starts,
    float* __restrict__ lat, float* __restrict__ h_out)
{
    extern __shared__ float sm[];
    float* ws  = sm;
    float* ht  = ws + 3 * WS_STAGE;
    int*   sst = (int*)(ht + 32 * HT_PITCH);
    float* sbh = (float*)(sst + 32 * 64);

    const int tid  = threadIdx.x;
    const int lane = tid & 31;
    const int w    = tid >> 5;
    const int wm   = w >> 3;
    const int wn   = w & 7;
    const int b0   = blockIdx.x * RB2;

    for (int i = tid; i < 32 * 64; i += 512)
        sst[i] = starts[(size_t)(b0 + (i >> 6)) * TT + (i & 63)];
    for (int i = tid; i < 768; i += 512) sbh[i] = b_hh[i];

    float2 hreg[2][4];
#pragma unroll
    for (int rh = 0; rh < 2; rh++) {
        const int row = wm * 16 + rh * 8 + (lane >> 2);
        const float m0 = starts[(size_t)(b0 + row) * TT] ? 0.f : 1.f;
#pragma unroll
        for (int nt = 0; nt < 4; nt++) {
            const int c = wn * 32 + nt * 8 + (lane & 3) * 2;
            float2 v = *(const float2*)(h0 + (size_t)(b0 + row) * 256 + c);
            v.x *= m0; v.y *= m0;
            hreg[rh][nt] = v;
            ht[row * HT_PITCH + c]     = round_tf32(v.x);
            ht[row * HT_PITCH + c + 1] = round_tf32(v.y);
        }
    }

    auto stageW = [&](int tile, int buf) {
        const float4* src = (const float4*)(Wt2 + (size_t)tile * WS_STAGE) + tid;
        float4* dst = (float4*)(ws + buf * WS_STAGE) + tid;
#pragma unroll
        for (int u = 0; u < 7; u++)
            cp16_cg(dst + u * 512, src + u * 512);
    };

    stageW(0, 0); CP_COMMIT();
    stageW(1, 1); CP_COMMIT();

    const uint32_t ht_lm = smem_u32(ht)
        + ((wm * 16 + (lane & 15)) * HT_PITCH + ((lane >> 4) << 2)) * 4;
    const int bslot = (wn * 32 + lane) * 28;

    const int KS_TOTAL = TT * 16;
    int ks = 0;

    for (int t = 0; t < TT; t++) {
        float acc[12][4];
#pragma unroll
        for (int j = 0; j < 12; j++)
#pragma unroll
            for (int q = 0; q < 4; q++) acc[j][q] = 0.f;

        for (int kt = 0; kt < 16; kt++) {
            if (ks < KS_TOTAL - 1) { CP_WAIT1(); } else { CP_WAITALL(); }
            __syncthreads();

            if (ks + 2 < KS_TOTAL) {
                stageW((ks + 2) & 15, (ks + 2) % 3);
                CP_COMMIT();
            }

            if (tid < 48) {
                int li = kt * 48 + tid;
                int r = li / 24, cl = li % 24;
                l2_prefetch(xg + ((size_t)(b0 + r) * TT + t) * G3 + cl * 32);
            }

            const float* wstage = ws + (ks % 3) * WS_STAGE;
#pragma unroll
            for (int s = 0; s < 2; s++) {
                const int kg = kt * 16 + s * 8;
                uint32_t a0, a1, a2, a3;
                LDMX4(a0, a1, a2, a3, ht_lm + kg * 4);
                const float* wb = wstage + s * 7168 + bslot;
                float4 bf[6];
#pragma unroll
                for (int u = 0; u < 6; u++)
                    bf[u] = *(const float4*)(wb + u * 4);
                const uint32_t* bw = (const uint32_t*)bf;
#pragma unroll
                for (int j = 0; j < 12; j++)
                    mma_tf32(acc[j][0], acc[j][1], acc[j][2], acc[j][3],
                             a0, a1, a2, a3, bw[j * 2], bw[j * 2 + 1]);
            }
            ks++;
        }
        __syncthreads();

#pragma unroll
        for (int rh = 0; rh < 2; rh++) {
            const int row  = wm * 16 + rh * 8 + (lane >> 2);
            const int grow = b0 + row;
            const size_t gbt = (size_t)grow * TT + t;
            const float* xb = xg + gbt * 768;
            float* lb = lat + gbt * 256;
            float msk = 1.f;
            if (t < TT - 1) msk = sst[row * 64 + t + 1] ? 0.f : 1.f;
            const int q = rh * 2;
#pragma unroll
            for (int nt = 0; nt < 4; nt++) {
                const int c = wn * 32 + nt * 8 + (lane & 3) * 2;
                float2 xr = *(const float2*)(xb + c);
                float2 xz = *(const float2*)(xb + 256 + c);
                float2 xn = *(const float2*)(xb + 512 + c);
                float hr0 = acc[nt][q]         + sbh[c];
                float hr1 = acc[nt][q + 1]     + sbh[c + 1];
                float hz0 = acc[4 + nt][q]     + sbh[256 + c];
                float hz1 = acc[4 + nt][q + 1] + sbh[256 + c + 1];
                float hn0 = acc[8 + nt][q]     + sbh[512 + c];
                float hn1 = acc[8 + nt][q + 1] + sbh[512 + c + 1];
                float r0 = 1.f / (1.f + __expf(-(xr.x + hr0)));
                float r1 = 1.f / (1.f + __expf(-(xr.y + hr1)));
                float z0 = 1.f / (1.f + __expf(-(xz.x + hz0)));
                float z1 = 1.f / (1.f + __expf(-(xz.y + hz1)));
                float n0 = tanhf(xn.x + r0 * hn0);
                float n1 = tanhf(xn.y + r1 * hn1);
                float v0 = (1.f - z0) * n0 + z0 * hreg[rh][nt].x;
                float v1 = (1.f - z1) * n1 + z1 * hreg[rh][nt].y;
                *(float2*)(lb + c) = make_float2(round_tf32(v0), round_tf32(v1));
                if (t == TT - 1) {
                    *(float2*)(h_out + (size_t)grow * 256 + c) = make_float2(v0, v1);
                } else {
                    float m0 = v0 * msk, m1 = v1 * msk;
                    hreg[rh][nt] = make_float2(m0, m1);
                    ht[row * HT_PITCH + c]     = round_tf32(m0);
                    ht[row * HT_PITCH + c + 1] = round_tf32(m1);
                }
            }
        }
    }
}

__global__ void std_kernel(const float* __restrict__ log_std, float* __restrict__ out)
{
    int a = threadIdx.x;
    if (a < AA) {
        float v = log_std[a];
        v = fminf(fmaxf(v, -2.0f), -0.5f);
        out[a] = __expf(v);
    }
}

// ---------------------------------------------------------------------------
extern "C" void kernel_launch(void* const* d_in, const int* in_sizes, int n_in,
                              void* d_out, int out_size)
{
    const float* features = (const float*)d_in[0];
    const float* hidden   = (const float*)d_in[1];
    const float* W_ih     = (const float*)d_in[2];
    const float* W_hh     = (const float*)d_in[3];
    const float* b_ih     = (const float*)d_in[4];
    const float* b_hh     = (const float*)d_in[5];
    const float* Aw1      = (const float*)d_in[6];
    const float* Ab1      = (const float*)d_in[7];
    const float* Aw2      = (const float*)d_in[8];
    const float* Ab2      = (const float*)d_in[9];
    const float* Aw3      = (const float*)d_in[10];
    const float* Ab3      = (const float*)d_in[11];
    const float* Cw1      = (const float*)d_in[12];
    const float* Cb1      = (const float*)d_in[13];
    const float* Cw2      = (const float*)d_in[14];
    const float* Cb2      = (const float*)d_in[15];
    const float* Cw3      = (const float*)d_in[16];
    const float* Cb3      = (const float*)d_in[17];
    const float* log_std  = (const float*)d_in[18];
    const int*   starts   = (const int*)d_in[19];

    float* out      = (float*)d_out;
    float* out_main = out;
    float* out_std  = out + (size_t)MTOT * 13;
    float* out_h    = out + (size_t)MTOT * 13 + AA;

    float *xg, *lat, *pa, *pc, *wt2, *wihr, *w1c, *w2a, *w2c, *b1c, *w3f;
    cudaGetSymbolAddress((void**)&xg,   g_xg);
    cudaGetSymbolAddress((void**)&lat,  g_lat);
    cudaGetSymbolAddress((void**)&pa,   g_pa);
    cudaGetSymbolAddress((void**)&pc,   g_pc);
    cudaGetSymbolAddress((void**)&wt2,  g_wt2);
    cudaGetSymbolAddress((void**)&wihr, g_wihr);
    cudaGetSymbolAddress((void**)&w1c,  g_w1c);
    cudaGetSymbolAddress((void**)&w2a,  g_w2a);
    cudaGetSymbolAddress((void**)&w2c,  g_w2c);
    cudaGetSymbolAddress((void**)&b1c,  g_b1c);
    cudaGetSymbolAddress((void**)&w3f,  g_w3f);

    cudaFuncSetAttribute(gemm_mma<false, false, true>,
                         cudaFuncAttributeMaxDynamicSharedMemorySize, GEMM_SMEM);
    cudaFuncSetAttribute(gemm_mma<true, true, false>,
                         cudaFuncAttributeMaxDynamicSharedMemorySize, GEMM_SMEM);
    cudaFuncSetAttribute(gemm_l2<true>,
                         cudaFuncAttributeMaxDynamicSharedMemorySize, GEMM_SMEM);
    cudaFuncSetAttribute(gemm_l2<false>,
                         cudaFuncAttributeMaxDynamicSharedMemorySize, GEMM_SMEM);
    cudaFuncSetAttribute(gru_mma,
                         cudaFuncAttributeMaxDynamicSharedMemorySize, GRU_SMEM);

    dim3 blk(256);

    // 1) all weight prep (incl. Aw3 head fragments)
    prep_all<<<PREP_TOT/256, blk>>>(
        (const float4*)W_ih, (const float4*)Aw1, (const float4*)Cw1,
        (const float4*)Aw2, (const float4*)Cw2,
        (const float4*)Ab1, (const float4*)Cb1, W_hh, Aw3,
        (float4*)wihr, (float4*)w1c, (float4*)w2a, (float4*)w2c,
        (float4*)b1c, wt2, w3f);
    // 2) std (independent)
    std_kernel<<<1, 32>>>(log_std, out_std);
    // 3) xg = features @ W_ih^T + b_ih (A-fragments rounded in-register)
    gemm_mma<false, false, true><<<dim3(G3/GBN, MTOT/GBM), blk, GEMM_SMEM>>>(
        features, wihr, b_ih, xg, G3, FF, FF);
    // 4) GRU scan -> lat (tf32-rounded), h_last      <-- profiled launch
    gru_mma<<<BB/RB2, dim3(512), GRU_SMEM>>>(xg, hidden, wt2, b_hh, starts, lat, out_h);
    // 5) fused actor+critic layer1 (reuses g_xg as [M,512])
    gemm_mma<true, true, false><<<dim3(512/GBN, MTOT/GBM), blk, GEMM_SMEM>>>(
        lat, w1c, b1c, xg, 512, HH, HH);
    // 6,7) layer2 + fused heads -> partials
    gemm_l2<true><<<dim3(HH/GBN, MTOT/GBM), blk, GEMM_SMEM>>>(
        xg,       w2a, Ab2, w3f, Cw3, pa, HH, 512);
    gemm_l2<false><<<dim3(HH/GBN, MTOT/GBM), blk, GEMM_SMEM>>>(
        xg + 256, w2c, Cb2, w3f, Cw3, pc, HH, 512);
    // 8) combine partials + biases -> out[:,0:13]
    combine_kernel<<<MTOT/256, blk>>>(pa, pc, Ab3, Cb3, out_main);
}

// round 13
// speedup vs baseline: 1.1349x; 1.0005x over previous
#include <cuda_runtime.h>
#include <math.h>
#include <stdint.h>

// Problem dims
#define BB 4096
#define TT 64
#define FF 256
#define HH 256
#define AA 12
#define MTOT (BB*TT)            // 262144 rows
#define G3  768

// Scratch (device globals; no cudaMalloc allowed)
__device__ float g_xg [(size_t)MTOT * G3];     // xg, later reused as t12 [M,512]
__device__ float g_lat[(size_t)MTOT * HH];
__device__ float g_pa [(size_t)2 * MTOT * 16]; // actor head partials [2][M][16]
__device__ float g_pc [(size_t)2 * MTOT];      // critic head partials [2][M]
__device__ float g_wt2[16 * 14336];            // W_hh fragment-major (padded slots)
__device__ float g_wihr[768 * 256];            // W_ih rounded
__device__ float g_w1c [512 * 256];            // [Aw1; Cw1] rounded
__device__ float g_w2a [256 * 256];
__device__ float g_w2c [256 * 256];
__device__ float g_b1c [512];                  // [Ab1 | Cb1]
__device__ float g_w3f [4096];                 // Aw3 B-fragments [32ksub][2nt][32ln][2]

__device__ __forceinline__ float round_tf32(float x) {
    uint32_t r;
    asm("cvt.rna.tf32.f32 %0, %1;" : "=r"(r) : "f"(x));
    return __uint_as_float(r);
}
__device__ __forceinline__ uint32_t round_tf32_u(uint32_t x) {
    uint32_t r;
    asm("cvt.rna.tf32.f32 %0, %1;" : "=r"(r) : "f"(__uint_as_float(x)));
    return r;
}
__device__ __forceinline__ uint32_t cvt_tf32_f(float x) {
    uint32_t r;
    asm("cvt.rna.tf32.f32 %0, %1;" : "=r"(r) : "f"(x));
    return r;
}

__device__ __forceinline__ uint32_t smem_u32(const void* p) {
    uint32_t a;
    asm("{ .reg .u64 t; cvta.to.shared.u64 t, %1; cvt.u32.u64 %0, t; }"
        : "=r"(a) : "l"(p));
    return a;
}

__device__ __forceinline__ void cp16_cg(void* dst, const void* src) {
    asm volatile("cp.async.cg.shared.global [%0], [%1], 16;"
                 :: "r"(smem_u32(dst)), "l"(src) : "memory");
}
__device__ __forceinline__ void l2_prefetch(const void* p) {
    asm volatile("prefetch.global.L2 [%0];" :: "l"(p));
}
#define CP_COMMIT()  asm volatile("cp.async.commit_group;" ::: "memory")
#define CP_WAIT1()   asm volatile("cp.async.wait_group 1;" ::: "memory")
#define CP_WAITALL() asm volatile("cp.async.wait_all;" ::: "memory")

#define LDMX4(r0,r1,r2,r3,addr) \
    asm volatile("ldmatrix.sync.aligned.m8n8.x4.shared.b16 {%0,%1,%2,%3}, [%4];" \
                 : "=r"(r0),"=r"(r1),"=r"(r2),"=r"(r3) : "r"(addr))
#define LDMX2(r0,r1,addr) \
    asm volatile("ldmatrix.sync.aligned.m8n8.x2.shared.b16 {%0,%1}, [%2];" \
                 : "=r"(r0),"=r"(r1) : "r"(addr))

__device__ __forceinline__ void mma_tf32(
    float& c0, float& c1, float& c2, float& c3,
    uint32_t a0, uint32_t a1, uint32_t a2, uint32_t a3,
    uint32_t b0, uint32_t b1)
{
    asm volatile(
        "mma.sync.aligned.m16n8k8.row.col.f32.tf32.tf32.f32 "
        "{%0,%1,%2,%3}, {%4,%5,%6,%7}, {%8,%9}, {%0,%1,%2,%3};"
        : "+f"(c0), "+f"(c1), "+f"(c2), "+f"(c3)
        : "r"(a0), "r"(a1), "r"(a2), "r"(a3), "r"(b0), "r"(b1));
}

// ===========================================================================
// Prep: ALL weight prep in one kernel.
// ===========================================================================
#define PREP_F4  114688
#define PREP_WHH (PREP_F4 + 196608)           // 311296
#define PREP_TOT (PREP_WHH + 4096)            // 315392 -> 1232 blocks
__global__ void prep_all(
    const float4* __restrict__ Wih, const float4* __restrict__ Aw1,
    const float4* __restrict__ Cw1, const float4* __restrict__ Aw2,
    const float4* __restrict__ Cw2, const float4* __restrict__ Ab1,
    const float4* __restrict__ Cb1, const float*  __restrict__ W_hh,
    const float*  __restrict__ Aw3,
    float4* __restrict__ wihr, float4* __restrict__ w1c,
    float4* __restrict__ w2a, float4* __restrict__ w2c,
    float4* __restrict__ b1c, float* __restrict__ Wt2,
    float* __restrict__ w3f)
{
    int i = blockIdx.x * 256 + threadIdx.x;
    if (i < PREP_F4) {
        const float4* src;
        float4* dst;
        if (i < 49152)      { src = Wih + i;            dst = wihr + i; }
        else if (i < 65536) { src = Aw1 + (i - 49152);  dst = w1c + (i - 49152); }
        else if (i < 81920) { src = Cw1 + (i - 65536);  dst = w1c + 16384 + (i - 65536); }
        else if (i < 98304) { src = Aw2 + (i - 81920);  dst = w2a + (i - 81920); }
        else                { src = Cw2 + (i - 98304);  dst = w2c + (i - 98304); }
        float4 v = *src;
        v.x = round_tf32(v.x); v.y = round_tf32(v.y);
        v.z = round_tf32(v.z); v.w = round_tf32(v.w);
        *dst = v;
        if (i < 64)       b1c[i] = Ab1[i];
        else if (i < 128) b1c[i] = Cb1[i - 64];
    } else if (i < PREP_WHH) {
        int j2 = i - PREP_F4;              // 0..196607
        int gcol = j2 >> 8, k = j2 & 255;
        int g = gcol >> 8, rem = gcol & 255;
        int wn = rem >> 5, nt = (rem >> 3) & 3, lanehi = rem & 7;
        int kt = k >> 4, s = (k >> 3) & 1, lanelo = k & 3, b = (k >> 2) & 1;
        int lane = lanehi * 4 + lanelo;
        int idx = (g * 4 + nt) * 2 + b;
        Wt2[(size_t)(kt * 2 + s) * 7168 + (wn * 32 + lane) * 28 + idx] =
            round_tf32(W_hh[(size_t)gcol * 256 + k]);
    } else if (i < PREP_TOT) {
        // Aw3 B-fragments for head mma (m16n8k8): [ksubg][ntile][lane][r]
        int j3 = i - PREP_WHH;             // 0..4095
        int ksubg = j3 >> 7;
        int rest  = j3 & 127;
        int ntile = rest >> 6;
        int lane  = (rest >> 1) & 31;
        int r     = rest & 1;
        int kg = ksubg * 8 + (lane & 3) + 4 * r;
        int a  = ntile * 8 + (lane >> 2);
        w3f[j3] = (a < AA) ? round_tf32(Aw3[a * 256 + kg]) : 0.f;
    }
}

// ===========================================================================
// tf32 mma.sync GEMM (generic): 128x128x32, 2 CTAs/SM, ldmatrix, cp.async.
// ===========================================================================
#define GBM 128
#define GBN 128
#define GBK 32
#define APITCH 36
#define STAGEF (GBM * APITCH)
#define GEMM_SMEM ((4 * STAGEF + GBN) * 4)    // 74240 B -> 2 CTAs/SM

// mainloop macro body shared by gemm_mma and gemm_l2 via function template
template<bool ROUND_A>
__device__ __forceinline__ void gemm_mainloop(
    float* sm, const float* Ag, const float* Wg,
    int K, int a_lm, int b_lm, float acc[4][4][4],
    int lrow, int lkq)
{
    const uint32_t sbase = smem_u32(sm);
    const int NK = K / GBK;
    auto stage_copy = [&](int kt) {
        float* st = sm + (kt & 1) * 2 * STAGEF;
        const float* ap = Ag + kt * GBK;
        const float* wp = Wg + kt * GBK;
        float* dA = st + lrow * APITCH + lkq;
        float* dB = st + STAGEF + lrow * APITCH + lkq;
#pragma unroll
        for (int u = 0; u < 4; u++) {
            cp16_cg(dA + 4 * u, ap + 4 * u);
            cp16_cg(dB + 4 * u, wp + 4 * u);
        }
    };
    stage_copy(0); CP_COMMIT();
    stage_copy(1); CP_COMMIT();
    for (int kt = 0; kt < NK; kt++) {
        if (kt < NK - 1) { CP_WAIT1(); } else { CP_WAITALL(); }
        __syncthreads();
        const uint32_t bufA = sbase + ((kt & 1) * 2 * STAGEF) * 4;
        const uint32_t bufB = bufA + STAGEF * 4;
#pragma unroll
        for (int k8 = 0; k8 < 4; k8++) {
            const int k0 = k8 * 8;
            uint32_t a[4][4];
#pragma unroll
            for (int mt = 0; mt < 4; mt++) {
                LDMX4(a[mt][0], a[mt][1], a[mt][2], a[mt][3],
                      bufA + (a_lm + mt * 16 * APITCH + k0) * 4);
                if (ROUND_A) {
#pragma unroll
                    for (int q = 0; q < 4; q++)
                        a[mt][q] = round_tf32_u(a[mt][q]);
                }
            }
            uint32_t b[4][2];
#pragma unroll
            for (int nt = 0; nt < 4; nt++)
                LDMX2(b[nt][0], b[nt][1],
                      bufB + (b_lm + nt * 8 * APITCH + k0) * 4);
#pragma unroll
            for (int mt = 0; mt < 4; mt++)
#pragma unroll
                for (int nt = 0; nt < 4; nt++)
                    mma_tf32(acc[mt][nt][0], acc[mt][nt][1],
                             acc[mt][nt][2], acc[mt][nt][3],
                             a[mt][0], a[mt][1], a[mt][2], a[mt][3],
                             b[nt][0], b[nt][1]);
        }
        __syncthreads();
        if (kt + 2 < NK) { stage_copy(kt + 2); CP_COMMIT(); }
    }
}

template<bool DO_TANH, bool ROUND_OUT, bool ROUND_A>
__global__ __launch_bounds__(256, 2) void gemm_mma(
    const float* __restrict__ A, const float* __restrict__ W,
    const float* __restrict__ bias, float* __restrict__ C,
    int N, int K, int lda)
{
    extern __shared__ float sm[];
    float* sBias = sm + 4 * STAGEF;
    const int tid  = threadIdx.x;
    const int lane = tid & 31;
    const int wid  = tid >> 5;
    const int wm   = wid >> 2;
    const int wn   = wid & 3;
    const int    bn = blockIdx.x * GBN;
    const size_t bm = (size_t)blockIdx.y * GBM;
    if (tid < GBN) sBias[tid] = bias[bn + tid];
    const int lrow = tid >> 1;
    const int lkq  = (tid & 1) * 16;
    const float* Ag = A + (bm + lrow) * lda + lkq;
    const float* Wg = W + ((size_t)(bn + lrow)) * K + lkq;
    const int a_lm = (wm * 64 + (lane & 15)) * APITCH + ((lane >> 4) << 2);
    const int b_lm = (wn * 32 + (lane & 7)) * APITCH + (((lane >> 3) & 1) << 2);

    float acc[4][4][4];
#pragma unroll
    for (int mt = 0; mt < 4; mt++)
#pragma unroll
        for (int nt = 0; nt < 4; nt++)
#pragma unroll
            for (int q = 0; q < 4; q++) acc[mt][nt][q] = 0.f;

    gemm_mainloop<ROUND_A>(sm, Ag, Wg, K, a_lm, b_lm, acc, lrow, lkq);

#pragma unroll
    for (int mt = 0; mt < 4; mt++) {
        const size_t row = bm + wm * 64 + mt * 16 + (lane >> 2);
        float* c0p = C + row * N + bn + wn * 32;
        float* c1p = c0p + (size_t)8 * N;
#pragma unroll
        for (int nt = 0; nt < 4; nt++) {
            const int cc = nt * 8 + (lane & 3) * 2;
            const float bx = sBias[wn * 32 + cc];
            const float by = sBias[wn * 32 + cc + 1];
            float v0 = acc[mt][nt][0] + bx, v1 = acc[mt][nt][1] + by;
            float v2 = acc[mt][nt][2] + bx, v3 = acc[mt][nt][3] + by;
            if (DO_TANH) {
                v0 = tanhf(v0); v1 = tanhf(v1);
                v2 = tanhf(v2); v3 = tanhf(v3);
            }
            if (ROUND_OUT) {
                v0 = round_tf32(v0); v1 = round_tf32(v1);
                v2 = round_tf32(v2); v3 = round_tf32(v3);
            }
            *(float2*)(c0p + cc) = make_float2(v0, v1);
            *(float2*)(c1p + cc) = make_float2(v2, v3);
        }
    }
}

// ===========================================================================
// Layer-2 GEMM fused with head. Writes head partials only (no t2 tensor).
// ACTOR: 64x32 -> 64x16 head via shuffle-converted A-frags + mma (Aw3 frags).
// CRITIC: 1-wide head via FFMA.
// Cross-CTA (2 column blocks) combined later by combine_kernel.
// ===========================================================================
template<bool ACTOR>
__global__ __launch_bounds__(256, 2) void gemm_l2(
    const float* __restrict__ A, const float* __restrict__ W,
    const float* __restrict__ bias, const float* __restrict__ w3f,
    const float* __restrict__ Cw3,
    float* __restrict__ partial, int K, int lda)
{
    extern __shared__ float sm[];
    float* sBias = sm + 4 * STAGEF;
    const int tid  = threadIdx.x;
    const int lane = tid & 31;
    const int wid  = tid >> 5;
    const int wm   = wid >> 2;
    const int wn   = wid & 3;
    const int    bn = blockIdx.x * GBN;       // 0 or 128
    const size_t bm = (size_t)blockIdx.y * GBM;
    if (tid < GBN) sBias[tid] = bias[bn + tid];
    const int lrow = tid >> 1;
    const int lkq  = (tid & 1) * 16;
    const float* Ag = A + (bm + lrow) * lda + lkq;
    const float* Wg = W + ((size_t)(bn + lrow)) * K + lkq;
    const int a_lm = (wm * 64 + (lane & 15)) * APITCH + ((lane >> 4) << 2);
    const int b_lm = (wn * 32 + (lane & 7)) * APITCH + (((lane >> 3) & 1) << 2);

    float acc[4][4][4];
#pragma unroll
    for (int mt = 0; mt < 4; mt++)
#pragma unroll
        for (int nt = 0; nt < 4; nt++)
#pragma unroll
            for (int q = 0; q < 4; q++) acc[mt][nt][q] = 0.f;

    gemm_mainloop<false>(sm, Ag, Wg, K, a_lm, b_lm, acc, lrow, lkq);

    // v = tanh(acc + bias) in place
#pragma unroll
    for (int mt = 0; mt < 4; mt++)
#pragma unroll
        for (int nt = 0; nt < 4; nt++) {
            const int cc = nt * 8 + (lane & 3) * 2;
            const float bx = sBias[wn * 32 + cc];
            const float by = sBias[wn * 32 + cc + 1];
            acc[mt][nt][0] = tanhf(acc[mt][nt][0] + bx);
            acc[mt][nt][1] = tanhf(acc[mt][nt][1] + by);
            acc[mt][nt][2] = tanhf(acc[mt][nt][2] + bx);
            acc[mt][nt][3] = tanhf(acc[mt][nt][3] + by);
        }

    const int j    = lane & 3;
    const int srcA = (lane & ~3) | (j >> 1);
    const int srcB = (lane & ~3) | (2 + (j >> 1));
    const bool odd = (lane & 1);

    if (ACTOR) {
        // head: [64 x 32] @ [32 x 16] via 32 mma; per-warp hacc, reduce over wn
        float* hred = sm;  // [128][17] reuse stage area (post-mainloop barrier)
        float hacc[4][2][4];
#pragma unroll
        for (int mt = 0; mt < 4; mt++)
#pragma unroll
            for (int n2 = 0; n2 < 2; n2++)
#pragma unroll
                for (int q = 0; q < 4; q++) hacc[mt][n2][q] = 0.f;

        const int ksgbase = (bn >> 3) + wn * 4;
#pragma unroll
        for (int ks = 0; ks < 4; ks++) {
            // load B fragments (L2-hot)
            float2 bf0 = *(const float2*)(w3f + (((ksgbase + ks) * 2 + 0) * 32 + lane) * 2);
            float2 bf1 = *(const float2*)(w3f + (((ksgbase + ks) * 2 + 1) * 32 + lane) * 2);
            uint32_t b00 = __float_as_uint(bf0.x), b01 = __float_as_uint(bf0.y);
            uint32_t b10 = __float_as_uint(bf1.x), b11 = __float_as_uint(bf1.y);
#pragma unroll
            for (int mt = 0; mt < 4; mt++) {
                float c0 = acc[mt][ks][0], c1 = acc[mt][ks][1];
                float c2 = acc[mt][ks][2], c3 = acc[mt][ks][3];
                float t0 = __shfl_sync(0xffffffffu, c0, srcA);
                float t1 = __shfl_sync(0xffffffffu, c1, srcA);
                float t2 = __shfl_sync(0xffffffffu, c2, srcA);
                float t3 = __shfl_sync(0xffffffffu, c3, srcA);
                float u0 = __shfl_sync(0xffffffffu, c0, srcB);
                float u1 = __shfl_sync(0xffffffffu, c1, srcB);
                float u2 = __shfl_sync(0xffffffffu, c2, srcB);
                float u3 = __shfl_sync(0xffffffffu, c3, srcB);
                uint32_t a0 = cvt_tf32_f(odd ? t1 : t0);
                uint32_t a1 = cvt_tf32_f(odd ? t3 : t2);
                uint32_t a2 = cvt_tf32_f(odd ? u1 : u0);
                uint32_t a3 = cvt_tf32_f(odd ? u3 : u2);
                mma_tf32(hacc[mt][0][0], hacc[mt][0][1], hacc[mt][0][2], hacc[mt][0][3],
                         a0, a1, a2, a3, b00, b01);
                mma_tf32(hacc[mt][1][0], hacc[mt][1][1], hacc[mt][1][2], hacc[mt][1][3],
                         a0, a1, a2, a3, b10, b11);
            }
        }
        // ordered cross-wn reduce into hred[128][17]
        for (int rr = 0; rr < 4; rr++) {
            if (wn == rr) {
#pragma unroll
                for (int mt = 0; mt < 4; mt++)
#pragma unroll
                    for (int n2 = 0; n2 < 2; n2++)
#pragma unroll
                        for (int q = 0; q < 4; q++) {
                            int row = wm * 64 + mt * 16 + (lane >> 2) + 8 * (q >> 1);
                            int col = n2 * 8 + 2 * (lane & 3) + (q & 1);
                            if (rr == 0) hred[row * 17 + col] = hacc[mt][n2][q];
                            else         hred[row * 17 + col] += hacc[mt][n2][q];
                        }
            }
            __syncthreads();
        }
        // write partials [2][M][16]
        const size_t pbase = (size_t)blockIdx.x * MTOT * 16 + bm * 16;
        for (int i = tid; i < 128 * 16; i += 256)
            partial[pbase + i] = hred[(i >> 4) * 17 + (i & 15)];
    } else {
        // critic: per-thread 64 FFMA with Cw3, shfl + ordered smem reduce
        float* hredc = sm;   // [128]
        float2 cw[4];
#pragma unroll
        for (int nt = 0; nt < 4; nt++)
            cw[nt] = *(const float2*)(Cw3 + bn + wn * 32 + nt * 8 + 2 * (lane & 3));
        float rsum[4][2];   // [mt][row half]
#pragma unroll
        for (int mt = 0; mt < 4; mt++) {
            float s0 = 0.f, s1 = 0.f;
#pragma unroll
            for (int nt = 0; nt < 4; nt++) {
                s0 = fmaf(acc[mt][nt][0], cw[nt].x, s0);
                s0 = fmaf(acc[mt][nt][1], cw[nt].y, s0);
                s1 = fmaf(acc[mt][nt][2], cw[nt].x, s1);
                s1 = fmaf(acc[mt][nt][3], cw[nt].y, s1);
            }
            // reduce over lane&3 (deterministic butterfly)
            s0 += __shfl_xor_sync(0xffffffffu, s0, 1);
            s0 += __shfl_xor_sync(0xffffffffu, s0, 2);
            s1 += __shfl_xor_sync(0xffffffffu, s1, 1);
            s1 += __shfl_xor_sync(0xffffffffu, s1, 2);
            rsum[mt][0] = s0; rsum[mt][1] = s1;
        }
        for (int rr = 0; rr < 4; rr++) {
            if (wn == rr && (lane & 3) == 0) {
#pragma unroll
                for (int mt = 0; mt < 4; mt++)
#pragma unroll
                    for (int qh = 0; qh < 2; qh++) {
                        int row = wm * 64 + mt * 16 + (lane >> 2) + 8 * qh;
                        if (rr == 0) hredc[row] = rsum[mt][qh];
                        else         hredc[row] += rsum[mt][qh];
                    }
            }
            __syncthreads();
        }
        const size_t pbase = (size_t)blockIdx.x * MTOT + bm;
        if (tid < 128) partial[pbase + tid] = hredc[tid];
    }
}

// combine partials -> out[:,0:13]
__global__ __launch_bounds__(256) void combine_kernel(
    const float* __restrict__ pa, const float* __restrict__ pc,
    const float* __restrict__ Ab3, const float* __restrict__ Cb3,
    float* __restrict__ out)
{
    size_t m = (size_t)blockIdx.x * 256 + threadIdx.x;
    const float* p0 = pa + m * 16;
    const float* p1 = pa + (size_t)MTOT * 16 + m * 16;
    float* o = out + m * 13;
#pragma unroll
    for (int a = 0; a < 12; a++)
        o[a] = p0[a] + p1[a] + Ab3[a];
    o[12] = pc[m] + pc[MTOT + m] + Cb3[0];
}

// ===========================================================================
// GRU scan (unchanged from R8/R10)
// ===========================================================================
#define RB2 32
#define HT_PITCH 260
#define WS_STAGE 14336
#define GRU_SMEM ((3*WS_STAGE + 32*HT_PITCH + 768) * 4 + 32*64*4)   // 216576 B

__global__ __launch_bounds__(512, 1) void gru_mma(
    const float* __restrict__ xg, const float* __restrict__ h0,
    const float* __restrict__ Wt2, const float* __restrict__ b_hh,
    const int* __restrict__ starts,
    float* __restrict__ lat, float* __restrict__ h_out)
{
    extern __shared__ float sm[];
    float* ws  = sm;
    float* ht  = ws + 3 * WS_STAGE;
    int*   sst = (int*)(ht + 32 * HT_PITCH);
    float* sbh = (float*)(sst + 32 * 64);

    const int tid  = threadIdx.x;
    const int lane = tid & 31;
    const int w    = tid >> 5;
    const int wm   = w >> 3;
    const int wn   = w & 7;
    const int b0   = blockIdx.x * RB2;

    for (int i = tid; i < 32 * 64; i += 512)
        sst[i] = starts[(size_t)(b0 + (i >> 6)) * TT + (i & 63)];
    for (int i = tid; i < 768; i += 512) sbh[i] = b_hh[i];

    float2 hreg[2][4];
#pragma unroll
    for (int rh = 0; rh < 2; rh++) {
        const int row = wm * 16 + rh * 8 + (lane >> 2);
        const float m0 = starts[(size_t)(b0 + row) * TT] ? 0.f : 1.f;
#pragma unroll
        for (int nt = 0; nt < 4; nt++) {
            const int c = wn * 32 + nt * 8 + (lane & 3) * 2;
            float2 v = *(const float2*)(h0 + (size_t)(b0 + row) * 256 + c);
            v.x *= m0; v.y *= m0;
            hreg[rh][nt] = v;
            ht[row * HT_PITCH + c]     = round_tf32(v.x);
            ht[row * HT_PITCH + c + 1] = round_tf32(v.y);
        }
    }

    auto stageW = [&](int tile, int buf) {
        const float4* src = (const float4*)(Wt2 + (size_t)tile * WS_STAGE) + tid;
        float4* dst = (float4*)(ws + buf * WS_STAGE) + tid;
#pragma unroll
        for (int u = 0; u < 7; u++)
            cp16_cg(dst + u * 512, src + u * 512);
    };

    stageW(0, 0); CP_COMMIT();
    stageW(1, 1); CP_COMMIT();

    const uint32_t ht_lm = smem_u32(ht)
        + ((wm * 16 + (lane & 15)) * HT_PITCH + ((lane >> 4) << 2)) * 4;
    const int bslot = (wn * 32 + lane) * 28;

    const int KS_TOTAL = TT * 16;
    int ks = 0;

    for (int t = 0; t < TT; t++) {
        float acc[12][4];
#pragma unroll
        for (int j = 0; j < 12; j++)
#pragma unroll
            for (int q = 0; q < 4; q++) acc[j][q] = 0.f;

        for (int kt = 0; kt < 16; kt++) {
            if (ks < KS_TOTAL - 1) { CP_WAIT1(); } else { CP_WAITALL(); }
            __syncthreads();

            if (ks + 2 < KS_TOTAL) {
                stageW((ks + 2) & 15, (ks + 2) % 3);
                CP_COMMIT();
            }

            if (tid < 48) {
                int li = kt * 48 + tid;
                int r = li / 24, cl = li % 24;
                l2_prefetch(xg + ((size_t)(b0 + r) * TT + t) * G3 + cl * 32);
            }

            const float* wstage = ws + (ks % 3) * WS_STAGE;
#pragma unroll
            for (int s = 0; s < 2; s++) {
                const int kg = kt * 16 + s * 8;
                uint32_t a0, a1, a2, a3;
                LDMX4(a0, a1, a2, a3, ht_lm + kg * 4);
                const float* wb = wstage + s * 7168 + bslot;
                float4 bf[6];
#pragma unroll
                for (int u = 0; u < 6; u++)
                    bf[u] = *(const float4*)(wb + u * 4);
                const uint32_t* bw = (const uint32_t*)bf;
#pragma unroll
                for (int j = 0; j < 12; j++)
                    mma_tf32(acc[j][0], acc[j][1], acc[j][2], acc[j][3],
                             a0, a1, a2, a3, bw[j * 2], bw[j * 2 + 1]);
            }
            ks++;
        }
        __syncthreads();

#pragma unroll
        for (int rh = 0; rh < 2; rh++) {
            const int row  = wm * 16 + rh * 8 + (lane >> 2);
            const int grow = b0 + row;
            const size_t gbt = (size_t)grow * TT + t;
            const float* xb = xg + gbt * 768;
            float* lb = lat + gbt * 256;
            float msk = 1.f;
            if (t < TT - 1) msk = sst[row * 64 + t + 1] ? 0.f : 1.f;
            const int q = rh * 2;
#pragma unroll
            for (int nt = 0; nt < 4; nt++) {
                const int c = wn * 32 + nt * 8 + (lane & 3) * 2;
                float2 xr = *(const float2*)(xb + c);
                float2 xz = *(const float2*)(xb + 256 + c);
                float2 xn = *(const float2*)(xb + 512 + c);
                float hr0 = acc[nt][q]         + sbh[c];
                float hr1 = acc[nt][q + 1]     + sbh[c + 1];
                float hz0 = acc[4 + nt][q]     + sbh[256 + c];
                float hz1 = acc[4 + nt][q + 1] + sbh[256 + c + 1];
                float hn0 = acc[8 + nt][q]     + sbh[512 + c];
                float hn1 = acc[8 + nt][q + 1] + sbh[512 + c + 1];
                float r0 = 1.f / (1.f + __expf(-(xr.x + hr0)));
                float r1 = 1.f / (1.f + __expf(-(xr.y + hr1)));
                float z0 = 1.f / (1.f + __expf(-(xz.x + hz0)));
                float z1 = 1.f / (1.f + __expf(-(xz.y + hz1)));
                float n0 = tanhf(xn.x + r0 * hn0);
                float n1 = tanhf(xn.y + r1 * hn1);
                float v0 = (1.f - z0) * n0 + z0 * hreg[rh][nt].x;
                float v1 = (1.f - z1) * n1 + z1 * hreg[rh][nt].y;
                *(float2*)(lb + c) = make_float2(round_tf32(v0), round_tf32(v1));
                if (t == TT - 1) {
                    *(float2*)(h_out + (size_t)grow * 256 + c) = make_float2(v0, v1);
                } else {
                    float m0 = v0 * msk, m1 = v1 * msk;
                    hreg[rh][nt] = make_float2(m0, m1);
                    ht[row * HT_PITCH + c]     = round_tf32(m0);
                    ht[row * HT_PITCH + c + 1] = round_tf32(m1);
                }
            }
        }
    }
}

__global__ void std_kernel(const float* __restrict__ log_std, float* __restrict__ out)
{
    int a = threadIdx.x;
    if (a < AA) {
        float v = log_std[a];
        v = fminf(fmaxf(v, -2.0f), -0.5f);
        out[a] = __expf(v);
    }
}

// ---------------------------------------------------------------------------
extern "C" void kernel_launch(void* const* d_in, const int* in_sizes, int n_in,
                              void* d_out, int out_size)
{
    const float* features = (const float*)d_in[0];
    const float* hidden   = (const float*)d_in[1];
    const float* W_ih     = (const float*)d_in[2];
    const float* W_hh     = (const float*)d_in[3];
    const float* b_ih     = (const float*)d_in[4];
    const float* b_hh     = (const float*)d_in[5];
    const float* Aw1      = (const float*)d_in[6];
    const float* Ab1      = (const float*)d_in[7];
    const float* Aw2      = (const float*)d_in[8];
    const float* Ab2      = (const float*)d_in[9];
    const float* Aw3      = (const float*)d_in[10];
    const float* Ab3      = (const float*)d_in[11];
    const float* Cw1      = (const float*)d_in[12];
    const float* Cb1      = (const float*)d_in[13];
    const float* Cw2      = (const float*)d_in[14];
    const float* Cb2      = (const float*)d_in[15];
    const float* Cw3      = (const float*)d_in[16];
    const float* Cb3      = (const float*)d_in[17];
    const float* log_std  = (const float*)d_in[18];
    const int*   starts   = (const int*)d_in[19];

    float* out      = (float*)d_out;
    float* out_main = out;
    float* out_std  = out + (size_t)MTOT * 13;
    float* out_h    = out + (size_t)MTOT * 13 + AA;

    float *xg, *lat, *pa, *pc, *wt2, *wihr, *w1c, *w2a, *w2c, *b1c, *w3f;
    cudaGetSymbolAddress((void**)&xg,   g_xg);
    cudaGetSymbolAddress((void**)&lat,  g_lat);
    cudaGetSymbolAddress((void**)&pa,   g_pa);
    cudaGetSymbolAddress((void**)&pc,   g_pc);
    cudaGetSymbolAddress((void**)&wt2,  g_wt2);
    cudaGetSymbolAddress((void**)&wihr, g_wihr);
    cudaGetSymbolAddress((void**)&w1c,  g_w1c);
    cudaGetSymbolAddress((void**)&w2a,  g_w2a);
    cudaGetSymbolAddress((void**)&w2c,  g_w2c);
    cudaGetSymbolAddress((void**)&b1c,  g_b1c);
    cudaGetSymbolAddress((void**)&w3f,  g_w3f);

    cudaFuncSetAttribute(gemm_mma<false, false, true>,
                         cudaFuncAttributeMaxDynamicSharedMemorySize, GEMM_SMEM);
    cudaFuncSetAttribute(gemm_mma<true, true, false>,
                         cudaFuncAttributeMaxDynamicSharedMemorySize, GEMM_SMEM);
    cudaFuncSetAttribute(gemm_l2<true>,
                         cudaFuncAttributeMaxDynamicSharedMemorySize, GEMM_SMEM);
    cudaFuncSetAttribute(gemm_l2<false>,
                         cudaFuncAttributeMaxDynamicSharedMemorySize, GEMM_SMEM);
    cudaFuncSetAttribute(gru_mma,
                         cudaFuncAttributeMaxDynamicSharedMemorySize, GRU_SMEM);

    dim3 blk(256);

    // 1) all weight prep (incl. Aw3 head fragments)
    prep_all<<<PREP_TOT/256, blk>>>(
        (const float4*)W_ih, (const float4*)Aw1, (const float4*)Cw1,
        (const float4*)Aw2, (const float4*)Cw2,
        (const float4*)Ab1, (const float4*)Cb1, W_hh, Aw3,
        (float4*)wihr, (float4*)w1c, (float4*)w2a, (float4*)w2c,
        (float4*)b1c, wt2, w3f);
    // 2) std (independent)
    std_kernel<<<1, 32>>>(log_std, out_std);
    // 3) xg = features @ W_ih^T + b_ih (A-fragments rounded in-register)
    gemm_mma<false, false, true><<<dim3(G3/GBN, MTOT/GBM), blk, GEMM_SMEM>>>(
        features, wihr, b_ih, xg, G3, FF, FF);
    // 4) GRU scan -> lat (tf32-rounded), h_last      <-- profiled launch
    gru_mma<<<BB/RB2, dim3(512), GRU_SMEM>>>(xg, hidden, wt2, b_hh, starts, lat, out_h);
    // 5) fused actor+critic layer1 (reuses g_xg as [M,512])
    gemm_mma<true, true, false><<<dim3(512/GBN, MTOT/GBM), blk, GEMM_SMEM>>>(
        lat, w1c, b1c, xg, 512, HH, HH);
    // 6,7) layer2 + fused heads -> partials
    gemm_l2<true><<<dim3(HH/GBN, MTOT/GBM), blk, GEMM_SMEM>>>(
        xg,       w2a, Ab2, w3f, Cw3, pa, HH, 512);
    gemm_l2<false><<<dim3(HH/GBN, MTOT/GBM), blk, GEMM_SMEM>>>(
        xg + 256, w2c, Cb2, w3f, Cw3, pc, HH, 512);
    // 8) combine partials + biases -> out[:,0:13]
    combine_kernel<<<MTOT/256, blk>>>(pa, pc, Ab3, Cb3, out_main);
}

// round 14
// speedup vs baseline: 1.1444x; 1.0084x over previous
#include <cuda_runtime.h>
#include <math.h>
#include <stdint.h>

// Problem dims
#define BB 4096
#define TT 64
#define FF 256
#define HH 256
#define AA 12
#define MTOT (BB*TT)            // 262144 rows
#define G3  768

// Scratch (device globals; no cudaMalloc allowed)
__device__ float g_xg [(size_t)MTOT * G3];     // xg, later reused as t12 [M,512]
__device__ float g_lat[(size_t)MTOT * HH];
__device__ float g_pa [(size_t)2 * MTOT * 16]; // actor head partials [2][M][16]
__device__ float g_pc [(size_t)2 * MTOT];      // critic head partials [2][M]
__device__ float g_wt2[16 * 14336];            // W_hh fragment-major (padded slots)
__device__ float g_wihr[768 * 256];            // W_ih rounded
__device__ float g_w1c [512 * 256];            // [Aw1; Cw1] rounded
__device__ float g_w2a [256 * 256];
__device__ float g_w2c [256 * 256];
__device__ float g_b1c [512];                  // [Ab1 | Cb1]
__device__ float g_w3f [4096];                 // Aw3 B-fragments

__device__ __forceinline__ float round_tf32(float x) {
    uint32_t r;
    asm("cvt.rna.tf32.f32 %0, %1;" : "=r"(r) : "f"(x));
    return __uint_as_float(r);
}
__device__ __forceinline__ uint32_t round_tf32_u(uint32_t x) {
    uint32_t r;
    asm("cvt.rna.tf32.f32 %0, %1;" : "=r"(r) : "f"(__uint_as_float(x)));
    return r;
}
__device__ __forceinline__ uint32_t cvt_tf32_f(float x) {
    uint32_t r;
    asm("cvt.rna.tf32.f32 %0, %1;" : "=r"(r) : "f"(x));
    return r;
}

__device__ __forceinline__ uint32_t smem_u32(const void* p) {
    uint32_t a;
    asm("{ .reg .u64 t; cvta.to.shared.u64 t, %1; cvt.u32.u64 %0, t; }"
        : "=r"(a) : "l"(p));
    return a;
}

__device__ __forceinline__ void cp16_cg(void* dst, const void* src) {
    asm volatile("cp.async.cg.shared.global [%0], [%1], 16;"
                 :: "r"(smem_u32(dst)), "l"(src) : "memory");
}
__device__ __forceinline__ void l2_prefetch(const void* p) {
    asm volatile("prefetch.global.L2 [%0];" :: "l"(p));
}
#define CP_COMMIT()  asm volatile("cp.async.commit_group;" ::: "memory")
#define CP_WAIT1()   asm volatile("cp.async.wait_group 1;" ::: "memory")
#define CP_WAITALL() asm volatile("cp.async.wait_all;" ::: "memory")

#define LDMX4(r0,r1,r2,r3,addr) \
    asm volatile("ldmatrix.sync.aligned.m8n8.x4.shared.b16 {%0,%1,%2,%3}, [%4];" \
                 : "=r"(r0),"=r"(r1),"=r"(r2),"=r"(r3) : "r"(addr))
#define LDMX2(r0,r1,addr) \
    asm volatile("ldmatrix.sync.aligned.m8n8.x2.shared.b16 {%0,%1}, [%2];" \
                 : "=r"(r0),"=r"(r1) : "r"(addr))

__device__ __forceinline__ void mma_tf32(
    float& c0, float& c1, float& c2, float& c3,
    uint32_t a0, uint32_t a1, uint32_t a2, uint32_t a3,
    uint32_t b0, uint32_t b1)
{
    asm volatile(
        "mma.sync.aligned.m16n8k8.row.col.f32.tf32.tf32.f32 "
        "{%0,%1,%2,%3}, {%4,%5,%6,%7}, {%8,%9}, {%0,%1,%2,%3};"
        : "+f"(c0), "+f"(c1), "+f"(c2), "+f"(c3)
        : "r"(a0), "r"(a1), "r"(a2), "r"(a3), "r"(b0), "r"(b1));
}

// ===========================================================================
// Prep: ALL weight prep in one kernel.
// ===========================================================================
#define PREP_F4  114688
#define PREP_WHH (PREP_F4 + 196608)           // 311296
#define PREP_TOT (PREP_WHH + 4096)            // 315392 -> 1232 blocks
__global__ void prep_all(
    const float4* __restrict__ Wih, const float4* __restrict__ Aw1,
    const float4* __restrict__ Cw1, const float4* __restrict__ Aw2,
    const float4* __restrict__ Cw2, const float4* __restrict__ Ab1,
    const float4* __restrict__ Cb1, const float*  __restrict__ W_hh,
    const float*  __restrict__ Aw3,
    float4* __restrict__ wihr, float4* __restrict__ w1c,
    float4* __restrict__ w2a, float4* __restrict__ w2c,
    float4* __restrict__ b1c, float* __restrict__ Wt2,
    float* __restrict__ w3f)
{
    int i = blockIdx.x * 256 + threadIdx.x;
    if (i < PREP_F4) {
        const float4* src;
        float4* dst;
        if (i < 49152)      { src = Wih + i;            dst = wihr + i; }
        else if (i < 65536) { src = Aw1 + (i - 49152);  dst = w1c + (i - 49152); }
        else if (i < 81920) { src = Cw1 + (i - 65536);  dst = w1c + 16384 + (i - 65536); }
        else if (i < 98304) { src = Aw2 + (i - 81920);  dst = w2a + (i - 81920); }
        else                { src = Cw2 + (i - 98304);  dst = w2c + (i - 98304); }
        float4 v = *src;
        v.x = round_tf32(v.x); v.y = round_tf32(v.y);
        v.z = round_tf32(v.z); v.w = round_tf32(v.w);
        *dst = v;
        if (i < 64)       b1c[i] = Ab1[i];
        else if (i < 128) b1c[i] = Cb1[i - 64];
    } else if (i < PREP_WHH) {
        int j2 = i - PREP_F4;              // 0..196607
        int gcol = j2 >> 8, k = j2 & 255;
        int g = gcol >> 8, rem = gcol & 255;
        int wn = rem >> 5, nt = (rem >> 3) & 3, lanehi = rem & 7;
        int kt = k >> 4, s = (k >> 3) & 1, lanelo = k & 3, b = (k >> 2) & 1;
        int lane = lanehi * 4 + lanelo;
        int idx = (g * 4 + nt) * 2 + b;
        Wt2[(size_t)(kt * 2 + s) * 7168 + (wn * 32 + lane) * 28 + idx] =
            round_tf32(W_hh[(size_t)gcol * 256 + k]);
    } else if (i < PREP_TOT) {
        int j3 = i - PREP_WHH;             // 0..4095
        int ksubg = j3 >> 7;
        int rest  = j3 & 127;
        int ntile = rest >> 6;
        int lane  = (rest >> 1) & 31;
        int r     = rest & 1;
        int kg = ksubg * 8 + (lane & 3) + 4 * r;
        int a  = ntile * 8 + (lane >> 2);
        w3f[j3] = (a < AA) ? round_tf32(Aw3[a * 256 + kg]) : 0.f;
    }
}

// ===========================================================================
// tf32 mma.sync GEMM: 128x128x32, 2 CTAs/SM, ldmatrix, cp.async,
// per-CTA k-tile phase rotation (L2 de-hotspotting).
// ===========================================================================
#define GBM 128
#define GBN 128
#define GBK 32
#define APITCH 36
#define STAGEF (GBM * APITCH)
#define GEMM_SMEM ((4 * STAGEF + GBN) * 4)    // 74240 B -> 2 CTAs/SM

template<bool ROUND_A>
__device__ __forceinline__ void gemm_mainloop(
    float* sm, const float* Ag, const float* Wg,
    int K, int a_lm, int b_lm, float acc[4][4][4],
    int lrow, int lkq, int phase)
{
    const uint32_t sbase = smem_u32(sm);
    const int NK = K / GBK;
    auto stage_copy = [&](int kt) {
        int tl = kt + phase;
        if (tl >= NK) tl -= NK;
        float* st = sm + (kt & 1) * 2 * STAGEF;
        const float* ap = Ag + tl * GBK;
        const float* wp = Wg + tl * GBK;
        float* dA = st + lrow * APITCH + lkq;
        float* dB = st + STAGEF + lrow * APITCH + lkq;
#pragma unroll
        for (int u = 0; u < 4; u++) {
            cp16_cg(dA + 4 * u, ap + 4 * u);
            cp16_cg(dB + 4 * u, wp + 4 * u);
        }
    };
    stage_copy(0); CP_COMMIT();
    stage_copy(1); CP_COMMIT();
    for (int kt = 0; kt < NK; kt++) {
        if (kt < NK - 1) { CP_WAIT1(); } else { CP_WAITALL(); }
        __syncthreads();
        const uint32_t bufA = sbase + ((kt & 1) * 2 * STAGEF) * 4;
        const uint32_t bufB = bufA + STAGEF * 4;
#pragma unroll
        for (int k8 = 0; k8 < 4; k8++) {
            const int k0 = k8 * 8;
            uint32_t a[4][4];
#pragma unroll
            for (int mt = 0; mt < 4; mt++) {
                LDMX4(a[mt][0], a[mt][1], a[mt][2], a[mt][3],
                      bufA + (a_lm + mt * 16 * APITCH + k0) * 4);
                if (ROUND_A) {
#pragma unroll
                    for (int q = 0; q < 4; q++)
                        a[mt][q] = round_tf32_u(a[mt][q]);
                }
            }
            uint32_t b[4][2];
#pragma unroll
            for (int nt = 0; nt < 4; nt++)
                LDMX2(b[nt][0], b[nt][1],
                      bufB + (b_lm + nt * 8 * APITCH + k0) * 4);
#pragma unroll
            for (int mt = 0; mt < 4; mt++)
#pragma unroll
                for (int nt = 0; nt < 4; nt++)
                    mma_tf32(acc[mt][nt][0], acc[mt][nt][1],
                             acc[mt][nt][2], acc[mt][nt][3],
                             a[mt][0], a[mt][1], a[mt][2], a[mt][3],
                             b[nt][0], b[nt][1]);
        }
        __syncthreads();
        if (kt + 2 < NK) { stage_copy(kt + 2); CP_COMMIT(); }
    }
}

template<bool DO_TANH, bool ROUND_OUT, bool ROUND_A>
__global__ __launch_bounds__(256, 2) void gemm_mma(
    const float* __restrict__ A, const float* __restrict__ W,
    const float* __restrict__ bias, float* __restrict__ C,
    int N, int K, int lda)
{
    extern __shared__ float sm[];
    float* sBias = sm + 4 * STAGEF;
    const int tid  = threadIdx.x;
    const int lane = tid & 31;
    const int wid  = tid >> 5;
    const int wm   = wid >> 2;
    const int wn   = wid & 3;
    const int    bn = blockIdx.x * GBN;
    const size_t bm = (size_t)blockIdx.y * GBM;
    if (tid < GBN) sBias[tid] = bias[bn + tid];
    const int lrow = tid >> 1;
    const int lkq  = (tid & 1) * 16;
    const float* Ag = A + (bm + lrow) * lda + lkq;
    const float* Wg = W + ((size_t)(bn + lrow)) * K + lkq;
    const int a_lm = (wm * 64 + (lane & 15)) * APITCH + ((lane >> 4) << 2);
    const int b_lm = (wn * 32 + (lane & 7)) * APITCH + (((lane >> 3) & 1) << 2);
    const int phase = blockIdx.y & ((K / GBK) - 1);

    float acc[4][4][4];
#pragma unroll
    for (int mt = 0; mt < 4; mt++)
#pragma unroll
        for (int nt = 0; nt < 4; nt++)
#pragma unroll
            for (int q = 0; q < 4; q++) acc[mt][nt][q] = 0.f;

    gemm_mainloop<ROUND_A>(sm, Ag, Wg, K, a_lm, b_lm, acc, lrow, lkq, phase);

#pragma unroll
    for (int mt = 0; mt < 4; mt++) {
        const size_t row = bm + wm * 64 + mt * 16 + (lane >> 2);
        float* c0p = C + row * N + bn + wn * 32;
        float* c1p = c0p + (size_t)8 * N;
#pragma unroll
        for (int nt = 0; nt < 4; nt++) {
            const int cc = nt * 8 + (lane & 3) * 2;
            const float bx = sBias[wn * 32 + cc];
            const float by = sBias[wn * 32 + cc + 1];
            float v0 = acc[mt][nt][0] + bx, v1 = acc[mt][nt][1] + by;
            float v2 = acc[mt][nt][2] + bx, v3 = acc[mt][nt][3] + by;
            if (DO_TANH) {
                v0 = tanhf(v0); v1 = tanhf(v1);
                v2 = tanhf(v2); v3 = tanhf(v3);
            }
            if (ROUND_OUT) {
                v0 = round_tf32(v0); v1 = round_tf32(v1);
                v2 = round_tf32(v2); v3 = round_tf32(v3);
            }
            *(float2*)(c0p + cc) = make_float2(v0, v1);
            *(float2*)(c1p + cc) = make_float2(v2, v3);
        }
    }
}

// ===========================================================================
// Layer-2 GEMM fused with head (unchanged logic; rotated mainloop).
// ===========================================================================
template<bool ACTOR>
__global__ __launch_bounds__(256, 2) void gemm_l2(
    const float* __restrict__ A, const float* __restrict__ W,
    const float* __restrict__ bias, const float* __restrict__ w3f,
    const float* __restrict__ Cw3,
    float* __restrict__ partial, int K, int lda)
{
    extern __shared__ float sm[];
    float* sBias = sm + 4 * STAGEF;
    const int tid  = threadIdx.x;
    const int lane = tid & 31;
    const int wid  = tid >> 5;
    const int wm   = wid >> 2;
    const int wn   = wid & 3;
    const int    bn = blockIdx.x * GBN;
    const size_t bm = (size_t)blockIdx.y * GBM;
    if (tid < GBN) sBias[tid] = bias[bn + tid];
    const int lrow = tid >> 1;
    const int lkq  = (tid & 1) * 16;
    const float* Ag = A + (bm + lrow) * lda + lkq;
    const float* Wg = W + ((size_t)(bn + lrow)) * K + lkq;
    const int a_lm = (wm * 64 + (lane & 15)) * APITCH + ((lane >> 4) << 2);
    const int b_lm = (wn * 32 + (lane & 7)) * APITCH + (((lane >> 3) & 1) << 2);
    const int phase = blockIdx.y & ((K / GBK) - 1);

    float acc[4][4][4];
#pragma unroll
    for (int mt = 0; mt < 4; mt++)
#pragma unroll
        for (int nt = 0; nt < 4; nt++)
#pragma unroll
            for (int q = 0; q < 4; q++) acc[mt][nt][q] = 0.f;

    gemm_mainloop<false>(sm, Ag, Wg, K, a_lm, b_lm, acc, lrow, lkq, phase);

#pragma unroll
    for (int mt = 0; mt < 4; mt++)
#pragma unroll
        for (int nt = 0; nt < 4; nt++) {
            const int cc = nt * 8 + (lane & 3) * 2;
            const float bx = sBias[wn * 32 + cc];
            const float by = sBias[wn * 32 + cc + 1];
            acc[mt][nt][0] = tanhf(acc[mt][nt][0] + bx);
            acc[mt][nt][1] = tanhf(acc[mt][nt][1] + by);
            acc[mt][nt][2] = tanhf(acc[mt][nt][2] + bx);
            acc[mt][nt][3] = tanhf(acc[mt][nt][3] + by);
        }

    const int j    = lane & 3;
    const int srcA = (lane & ~3) | (j >> 1);
    const int srcB = (lane & ~3) | (2 + (j >> 1));
    const bool odd = (lane & 1);

    if (ACTOR) {
        float* hred = sm;
        float hacc[4][2][4];
#pragma unroll
        for (int mt = 0; mt < 4; mt++)
#pragma unroll
            for (int n2 = 0; n2 < 2; n2++)
#pragma unroll
                for (int q = 0; q < 4; q++) hacc[mt][n2][q] = 0.f;

        const int ksgbase = (bn >> 3) + wn * 4;
#pragma unroll
        for (int ks = 0; ks < 4; ks++) {
            float2 bf0 = *(const float2*)(w3f + (((ksgbase + ks) * 2 + 0) * 32 + lane) * 2);
            float2 bf1 = *(const float2*)(w3f + (((ksgbase + ks) * 2 + 1) * 32 + lane) * 2);
            uint32_t b00 = __float_as_uint(bf0.x), b01 = __float_as_uint(bf0.y);
            uint32_t b10 = __float_as_uint(bf1.x), b11 = __float_as_uint(bf1.y);
#pragma unroll
            for (int mt = 0; mt < 4; mt++) {
                float c0 = acc[mt][ks][0], c1 = acc[mt][ks][1];
                float c2 = acc[mt][ks][2], c3 = acc[mt][ks][3];
                float t0 = __shfl_sync(0xffffffffu, c0, srcA);
                float t1 = __shfl_sync(0xffffffffu, c1, srcA);
                float t2 = __shfl_sync(0xffffffffu, c2, srcA);
                float t3 = __shfl_sync(0xffffffffu, c3, srcA);
                float u0 = __shfl_sync(0xffffffffu, c0, srcB);
                float u1 = __shfl_sync(0xffffffffu, c1, srcB);
                float u2 = __shfl_sync(0xffffffffu, c2, srcB);
                float u3 = __shfl_sync(0xffffffffu, c3, srcB);
                uint32_t a0 = cvt_tf32_f(odd ? t1 : t0);
                uint32_t a1 = cvt_tf32_f(odd ? t3 : t2);
                uint32_t a2 = cvt_tf32_f(odd ? u1 : u0);
                uint32_t a3 = cvt_tf32_f(odd ? u3 : u2);
                mma_tf32(hacc[mt][0][0], hacc[mt][0][1], hacc[mt][0][2], hacc[mt][0][3],
                         a0, a1, a2, a3, b00, b01);
                mma_tf32(hacc[mt][1][0], hacc[mt][1][1], hacc[mt][1][2], hacc[mt][1][3],
                         a0, a1, a2, a3, b10, b11);
            }
        }
        for (int rr = 0; rr < 4; rr++) {
            if (wn == rr) {
#pragma unroll
                for (int mt = 0; mt < 4; mt++)
#pragma unroll
                    for (int n2 = 0; n2 < 2; n2++)
#pragma unroll
                        for (int q = 0; q < 4; q++) {
                            int row = wm * 64 + mt * 16 + (lane >> 2) + 8 * (q >> 1);
                            int col = n2 * 8 + 2 * (lane & 3) + (q & 1);
                            if (rr == 0) hred[row * 17 + col] = hacc[mt][n2][q];
                            else         hred[row * 17 + col] += hacc[mt][n2][q];
                        }
            }
            __syncthreads();
        }
        const size_t pbase = (size_t)blockIdx.x * MTOT * 16 + bm * 16;
        for (int i = tid; i < 128 * 16; i += 256)
            partial[pbase + i] = hred[(i >> 4) * 17 + (i & 15)];
    } else {
        float* hredc = sm;
        float2 cw[4];
#pragma unroll
        for (int nt = 0; nt < 4; nt++)
            cw[nt] = *(const float2*)(Cw3 + bn + wn * 32 + nt * 8 + 2 * (lane & 3));
        float rsum[4][2];
#pragma unroll
        for (int mt = 0; mt < 4; mt++) {
            float s0 = 0.f, s1 = 0.f;
#pragma unroll
            for (int nt = 0; nt < 4; nt++) {
                s0 = fmaf(acc[mt][nt][0], cw[nt].x, s0);
                s0 = fmaf(acc[mt][nt][1], cw[nt].y, s0);
                s1 = fmaf(acc[mt][nt][2], cw[nt].x, s1);
                s1 = fmaf(acc[mt][nt][3], cw[nt].y, s1);
            }
            s0 += __shfl_xor_sync(0xffffffffu, s0, 1);
            s0 += __shfl_xor_sync(0xffffffffu, s0, 2);
            s1 += __shfl_xor_sync(0xffffffffu, s1, 1);
            s1 += __shfl_xor_sync(0xffffffffu, s1, 2);
            rsum[mt][0] = s0; rsum[mt][1] = s1;
        }
        for (int rr = 0; rr < 4; rr++) {
            if (wn == rr && (lane & 3) == 0) {
#pragma unroll
                for (int mt = 0; mt < 4; mt++)
#pragma unroll
                    for (int qh = 0; qh < 2; qh++) {
                        int row = wm * 64 + mt * 16 + (lane >> 2) + 8 * qh;
                        if (rr == 0) hredc[row] = rsum[mt][qh];
                        else         hredc[row] += rsum[mt][qh];
                    }
            }
            __syncthreads();
        }
        const size_t pbase = (size_t)blockIdx.x * MTOT + bm;
        if (tid < 128) partial[pbase + tid] = hredc[tid];
    }
}

// combine partials -> out[:,0:13]
__global__ __launch_bounds__(256) void combine_kernel(
    const float* __restrict__ pa, const float* __restrict__ pc,
    const float* __restrict__ Ab3, const float* __restrict__ Cb3,
    float* __restrict__ out)
{
    size_t m = (size_t)blockIdx.x * 256 + threadIdx.x;
    const float* p0 = pa + m * 16;
    const float* p1 = pa + (size_t)MTOT * 16 + m * 16;
    float* o = out + m * 13;
#pragma unroll
    for (int a = 0; a < 12; a++)
        o[a] = p0[a] + p1[a] + Ab3[a];
    o[12] = pc[m] + pc[MTOT + m] + Cb3[0];
}

// ===========================================================================
// GRU scan: k-tile phase rotation per block (L2 de-hotspotting); otherwise R13.
// ===========================================================================
#define RB2 32
#define HT_PITCH 260
#define WS_STAGE 14336
#define GRU_SMEM ((3*WS_STAGE + 32*HT_PITCH + 768) * 4 + 32*64*4)   // 216576 B

__global__ __launch_bounds__(512, 1) void gru_mma(
    const float* __restrict__ xg, const float* __restrict__ h0,
    const float* __restrict__ Wt2, const float* __restrict__ b_hh,
    const int* __restrict__ starts,
    float* __restrict__ lat, float* __restrict__ h_out)
{
    extern __shared__ float sm[];
    float* ws  = sm;
    float* ht  = ws + 3 * WS_STAGE;
    int*   sst = (int*)(ht + 32 * HT_PITCH);
    float* sbh = (float*)(sst + 32 * 64);

    const int tid  = threadIdx.x;
    const int lane = tid & 31;
    const int w    = tid >> 5;
    const int wm   = w >> 3;
    const int wn   = w & 7;
    const int b0   = blockIdx.x * RB2;
    const int phase = blockIdx.x & 15;

    for (int i = tid; i < 32 * 64; i += 512)
        sst[i] = starts[(size_t)(b0 + (i >> 6)) * TT + (i & 63)];
    for (int i = tid; i < 768; i += 512) sbh[i] = b_hh[i];

    float2 hreg[2][4];
#pragma unroll
    for (int rh = 0; rh < 2; rh++) {
        const int row = wm * 16 + rh * 8 + (lane >> 2);
        const float m0 = starts[(size_t)(b0 + row) * TT] ? 0.f : 1.f;
#pragma unroll
        for (int nt = 0; nt < 4; nt++) {
            const int c = wn * 32 + nt * 8 + (lane & 3) * 2;
            float2 v = *(const float2*)(h0 + (size_t)(b0 + row) * 256 + c);
            v.x *= m0; v.y *= m0;
            hreg[rh][nt] = v;
            ht[row * HT_PITCH + c]     = round_tf32(v.x);
            ht[row * HT_PITCH + c + 1] = round_tf32(v.y);
        }
    }

    auto stageW = [&](int tile, int buf) {
        const float4* src = (const float4*)(Wt2 + (size_t)tile * WS_STAGE) + tid;
        float4* dst = (float4*)(ws + buf * WS_STAGE) + tid;
#pragma unroll
        for (int u = 0; u < 7; u++)
            cp16_cg(dst + u * 512, src + u * 512);
    };

    stageW(phase, 0); CP_COMMIT();
    stageW((phase + 1) & 15, 1); CP_COMMIT();

    const uint32_t ht_lm = smem_u32(ht)
        + ((wm * 16 + (lane & 15)) * HT_PITCH + ((lane >> 4) << 2)) * 4;
    const int bslot = (wn * 32 + lane) * 28;

    const int KS_TOTAL = TT * 16;
    int ks = 0;

    for (int t = 0; t < TT; t++) {
        float acc[12][4];
#pragma unroll
        for (int j = 0; j < 12; j++)
#pragma unroll
            for (int q = 0; q < 4; q++) acc[j][q] = 0.f;

        for (int kt = 0; kt < 16; kt++) {
            if (ks < KS_TOTAL - 1) { CP_WAIT1(); } else { CP_WAITALL(); }
            __syncthreads();

            if (ks + 2 < KS_TOTAL) {
                stageW((phase + ks + 2) & 15, (ks + 2) % 3);
                CP_COMMIT();
            }

            if (tid < 48) {
                int li = kt * 48 + tid;
                int r = li / 24, cl = li % 24;
                l2_prefetch(xg + ((size_t)(b0 + r) * TT + t) * G3 + cl * 32);
            }

            const int tc = (phase + ks) & 15;   // rotated k-tile being computed
            const float* wstage = ws + (ks % 3) * WS_STAGE;
#pragma unroll
            for (int s = 0; s < 2; s++) {
                const int kg = tc * 16 + s * 8;
                uint32_t a0, a1, a2, a3;
                LDMX4(a0, a1, a2, a3, ht_lm + kg * 4);
                const float* wb = wstage + s * 7168 + bslot;
                float4 bf[6];
#pragma unroll
                for (int u = 0; u < 6; u++)
                    bf[u] = *(const float4*)(wb + u * 4);
                const uint32_t* bw = (const uint32_t*)bf;
#pragma unroll
                for (int j = 0; j < 12; j++)
                    mma_tf32(acc[j][0], acc[j][1], acc[j][2], acc[j][3],
                             a0, a1, a2, a3, bw[j * 2], bw[j * 2 + 1]);
            }
            ks++;
        }
        __syncthreads();

#pragma unroll
        for (int rh = 0; rh < 2; rh++) {
            const int row  = wm * 16 + rh * 8 + (lane >> 2);
            const int grow = b0 + row;
            const size_t gbt = (size_t)grow * TT + t;
            const float* xb = xg + gbt * 768;
            float* lb = lat + gbt * 256;
            float msk = 1.f;
            if (t < TT - 1) msk = sst[row * 64 + t + 1] ? 0.f : 1.f;
            const int q = rh * 2;
#pragma unroll
            for (int nt = 0; nt < 4; nt++) {
                const int c = wn * 32 + nt * 8 + (lane & 3) * 2;
                float2 xr = *(const float2*)(xb + c);
                float2 xz = *(const float2*)(xb + 256 + c);
                float2 xn = *(const float2*)(xb + 512 + c);
                float hr0 = acc[nt][q]         + sbh[c];
                float hr1 = acc[nt][q + 1]     + sbh[c + 1];
                float hz0 = acc[4 + nt][q]     + sbh[256 + c];
                float hz1 = acc[4 + nt][q + 1] + sbh[256 + c + 1];
                float hn0 = acc[8 + nt][q]     + sbh[512 + c];
                float hn1 = acc[8 + nt][q + 1] + sbh[512 + c + 1];
                float r0 = 1.f / (1.f + __expf(-(xr.x + hr0)));
                float r1 = 1.f / (1.f + __expf(-(xr.y + hr1)));
                float z0 = 1.f / (1.f + __expf(-(xz.x + hz0)));
                float z1 = 1.f / (1.f + __expf(-(xz.y + hz1)));
                float n0 = tanhf(xn.x + r0 * hn0);
                float n1 = tanhf(xn.y + r1 * hn1);
                float v0 = (1.f - z0) * n0 + z0 * hreg[rh][nt].x;
                float v1 = (1.f - z1) * n1 + z1 * hreg[rh][nt].y;
                *(float2*)(lb + c) = make_float2(round_tf32(v0), round_tf32(v1));
                if (t == TT - 1) {
                    *(float2*)(h_out + (size_t)grow * 256 + c) = make_float2(v0, v1);
                } else {
                    float m0 = v0 * msk, m1 = v1 * msk;
                    hreg[rh][nt] = make_float2(m0, m1);
                    ht[row * HT_PITCH + c]     = round_tf32(m0);
                    ht[row * HT_PITCH + c + 1] = round_tf32(m1);
                }
            }
        }
    }
}

__global__ void std_kernel(const float* __restrict__ log_std, float* __restrict__ out)
{
    int a = threadIdx.x;
    if (a < AA) {
        float v = log_std[a];
        v = fminf(fmaxf(v, -2.0f), -0.5f);
        out[a] = __expf(v);
    }
}

// ---------------------------------------------------------------------------
extern "C" void kernel_launch(void* const* d_in, const int* in_sizes, int n_in,
                              void* d_out, int out_size)
{
    const float* features = (const float*)d_in[0];
    const float* hidden   = (const float*)d_in[1];
    const float* W_ih     = (const float*)d_in[2];
    const float* W_hh     = (const float*)d_in[3];
    const float* b_ih     = (const float*)d_in[4];
    const float* b_hh     = (const float*)d_in[5];
    const float* Aw1      = (const float*)d_in[6];
    const float* Ab1      = (const float*)d_in[7];
    const float* Aw2      = (const float*)d_in[8];
    const float* Ab2      = (const float*)d_in[9];
    const float* Aw3      = (const float*)d_in[10];
    const float* Ab3      = (const float*)d_in[11];
    const float* Cw1      = (const float*)d_in[12];
    const float* Cb1      = (const float*)d_in[13];
    const float* Cw2      = (const float*)d_in[14];
    const float* Cb2      = (const float*)d_in[15];
    const float* Cw3      = (const float*)d_in[16];
    const float* Cb3      = (const float*)d_in[17];
    const float* log_std  = (const float*)d_in[18];
    const int*   starts   = (const int*)d_in[19];

    float* out      = (float*)d_out;
    float* out_main = out;
    float* out_std  = out + (size_t)MTOT * 13;
    float* out_h    = out + (size_t)MTOT * 13 + AA;

    float *xg, *lat, *pa, *pc, *wt2, *wihr, *w1c, *w2a, *w2c, *b1c, *w3f;
    cudaGetSymbolAddress((void**)&xg,   g_xg);
    cudaGetSymbolAddress((void**)&lat,  g_lat);
    cudaGetSymbolAddress((void**)&pa,   g_pa);
    cudaGetSymbolAddress((void**)&pc,   g_pc);
    cudaGetSymbolAddress((void**)&wt2,  g_wt2);
    cudaGetSymbolAddress((void**)&wihr, g_wihr);
    cudaGetSymbolAddress((void**)&w1c,  g_w1c);
    cudaGetSymbolAddress((void**)&w2a,  g_w2a);
    cudaGetSymbolAddress((void**)&w2c,  g_w2c);
    cudaGetSymbolAddress((void**)&b1c,  g_b1c);
    cudaGetSymbolAddress((void**)&w3f,  g_w3f);

    cudaFuncSetAttribute(gemm_mma<false, false, true>,
                         cudaFuncAttributeMaxDynamicSharedMemorySize, GEMM_SMEM);
    cudaFuncSetAttribute(gemm_mma<true, true, false>,
                         cudaFuncAttributeMaxDynamicSharedMemorySize, GEMM_SMEM);
    cudaFuncSetAttribute(gemm_l2<true>,
                         cudaFuncAttributeMaxDynamicSharedMemorySize, GEMM_SMEM);
    cudaFuncSetAttribute(gemm_l2<false>,
                         cudaFuncAttributeMaxDynamicSharedMemorySize, GEMM_SMEM);
    cudaFuncSetAttribute(gru_mma,
                         cudaFuncAttributeMaxDynamicSharedMemorySize, GRU_SMEM);

    dim3 blk(256);

    // 1) all weight prep (incl. Aw3 head fragments)
    prep_all<<<PREP_TOT/256, blk>>>(
        (const float4*)W_ih, (const float4*)Aw1, (const float4*)Cw1,
        (const float4*)Aw2, (const float4*)Cw2,
        (const float4*)Ab1, (const float4*)Cb1, W_hh, Aw3,
        (float4*)wihr, (float4*)w1c, (float4*)w2a, (float4*)w2c,
        (float4*)b1c, wt2, w3f);
    // 2) std (independent)
    std_kernel<<<1, 32>>>(log_std, out_std);
    // 3) xg = features @ W_ih^T + b_ih (A-fragments rounded in-register)
    gemm_mma<false, false, true><<<dim3(G3/GBN, MTOT/GBM), blk, GEMM_SMEM>>>(
        features, wihr, b_ih, xg, G3, FF, FF);
    // 4) GRU scan -> lat (tf32-rounded), h_last      <-- profiled launch
    gru_mma<<<BB/RB2, dim3(512), GRU_SMEM>>>(xg, hidden, wt2, b_hh, starts, lat, out_h);
    // 5) fused actor+critic layer1 (reuses g_xg as [M,512])
    gemm_mma<true, true, false><<<dim3(512/GBN, MTOT/GBM), blk, GEMM_SMEM>>>(
        lat, w1c, b1c, xg, 512, HH, HH);
    // 6,7) layer2 + fused heads -> partials
    gemm_l2<true><<<dim3(HH/GBN, MTOT/GBM), blk, GEMM_SMEM>>>(
        xg,       w2a, Ab2, w3f, Cw3, pa, HH, 512);
    gemm_l2<false><<<dim3(HH/GBN, MTOT/GBM), blk, GEMM_SMEM>>>(
        xg + 256, w2c, Cb2, w3f, Cw3, pc, HH, 512);
    // 8) combine partials + biases -> out[:,0:13]
    combine_kernel<<<MTOT/256, blk>>>(pa, pc, Ab3, Cb3, out_main);
}

// round 15
// speedup vs baseline: 1.8786x; 1.6416x over previous
#include <cuda_runtime.h>
#include <cuda_fp16.h>
#include <math.h>
#include <stdint.h>

// Problem dims
#define BB 4096
#define TT 64
#define FF 256
#define HH 256
#define AA 12
#define MTOT (BB*TT)            // 262144 rows
#define G3  768

// Scratch (device globals; no cudaMalloc allowed)
__device__ __half g_xgh [(size_t)MTOT * G3];   // xg half; reused as t12 [M,512]
__device__ __half g_lath[(size_t)MTOT * HH];   // latent half
__device__ __half g_t1h [(size_t)MTOT * HH];   // features half
__device__ float  g_pa  [(size_t)2 * MTOT * 16];
__device__ float  g_pc  [(size_t)2 * MTOT];
__device__ uint32_t g_wt2h[16 * 7168];         // W_hh frag-major half2 slots
__device__ __half g_wihr[768 * 256];
__device__ __half g_w1c [512 * 256];
__device__ __half g_w2a [256 * 256];
__device__ __half g_w2c [256 * 256];
__device__ float  g_b1c [512];
__device__ float  g_w3f [4096];                // Aw3 tf32 B-fragments (head)

__device__ __forceinline__ float round_tf32(float x) {
    uint32_t r;
    asm("cvt.rna.tf32.f32 %0, %1;" : "=r"(r) : "f"(x));
    return __uint_as_float(r);
}
__device__ __forceinline__ uint32_t cvt_tf32_f(float x) {
    uint32_t r;
    asm("cvt.rna.tf32.f32 %0, %1;" : "=r"(r) : "f"(x));
    return r;
}

__device__ __forceinline__ uint32_t smem_u32(const void* p) {
    uint32_t a;
    asm("{ .reg .u64 t; cvta.to.shared.u64 t, %1; cvt.u32.u64 %0, t; }"
        : "=r"(a) : "l"(p));
    return a;
}

__device__ __forceinline__ void cp16_cg(void* dst, const void* src) {
    asm volatile("cp.async.cg.shared.global [%0], [%1], 16;"
                 :: "r"(smem_u32(dst)), "l"(src) : "memory");
}
__device__ __forceinline__ void l2_prefetch(const void* p) {
    asm volatile("prefetch.global.L2 [%0];" :: "l"(p));
}
#define CP_COMMIT()  asm volatile("cp.async.commit_group;" ::: "memory")
#define CP_WAIT1()   asm volatile("cp.async.wait_group 1;" ::: "memory")
#define CP_WAITALL() asm volatile("cp.async.wait_all;" ::: "memory")

#define LDMX4(r0,r1,r2,r3,addr) \
    asm volatile("ldmatrix.sync.aligned.m8n8.x4.shared.b16 {%0,%1,%2,%3}, [%4];" \
                 : "=r"(r0),"=r"(r1),"=r"(r2),"=r"(r3) : "r"(addr))
#define LDMX2(r0,r1,addr) \
    asm volatile("ldmatrix.sync.aligned.m8n8.x2.shared.b16 {%0,%1}, [%2];" \
                 : "=r"(r0),"=r"(r1) : "r"(addr))

// fp16 mma with fp32 accumulate
__device__ __forceinline__ void mma_f16(
    float& c0, float& c1, float& c2, float& c3,
    uint32_t a0, uint32_t a1, uint32_t a2, uint32_t a3,
    uint32_t b0, uint32_t b1)
{
    asm volatile(
        "mma.sync.aligned.m16n8k16.row.col.f32.f16.f16.f32 "
        "{%0,%1,%2,%3}, {%4,%5,%6,%7}, {%8,%9}, {%0,%1,%2,%3};"
        : "+f"(c0), "+f"(c1), "+f"(c2), "+f"(c3)
        : "r"(a0), "r"(a1), "r"(a2), "r"(a3), "r"(b0), "r"(b1));
}
// tf32 mma (head only)
__device__ __forceinline__ void mma_tf32(
    float& c0, float& c1, float& c2, float& c3,
    uint32_t a0, uint32_t a1, uint32_t a2, uint32_t a3,
    uint32_t b0, uint32_t b1)
{
    asm volatile(
        "mma.sync.aligned.m16n8k8.row.col.f32.tf32.tf32.f32 "
        "{%0,%1,%2,%3}, {%4,%5,%6,%7}, {%8,%9}, {%0,%1,%2,%3};"
        : "+f"(c0), "+f"(c1), "+f"(c2), "+f"(c3)
        : "r"(a0), "r"(a1), "r"(a2), "r"(a3), "r"(b0), "r"(b1));
}

__device__ __forceinline__ uint32_t pack_h2(float a, float b) {
    __half2 h = __floats2half2_rn(a, b);
    return *(uint32_t*)&h;
}

// ===========================================================================
// Prep: all weights -> half (+ W_hh fragment-major half2 slots + Aw3 frags)
// ===========================================================================
#define PREP_F4  114688
#define PREP_WHH (PREP_F4 + 98304)            // 212992
#define PREP_TOT (PREP_WHH + 4096)            // 217088 -> 848 blocks
__global__ void prep_all(
    const float4* __restrict__ Wih, const float4* __restrict__ Aw1,
    const float4* __restrict__ Cw1, const float4* __restrict__ Aw2,
    const float4* __restrict__ Cw2, const float* __restrict__ Ab1,
    const float* __restrict__ Cb1, const float*  __restrict__ W_hh,
    const float*  __restrict__ Aw3,
    uint2* __restrict__ wihr, uint2* __restrict__ w1c,
    uint2* __restrict__ w2a, uint2* __restrict__ w2c,
    float* __restrict__ b1c, uint32_t* __restrict__ Wt2h,
    float* __restrict__ w3f)
{
    int i = blockIdx.x * 256 + threadIdx.x;
    if (i < PREP_F4) {
        const float4* src;
        uint2* dst;
        if (i < 49152)      { src = Wih + i;            dst = wihr + i; }
        else if (i < 65536) { src = Aw1 + (i - 49152);  dst = w1c + (i - 49152); }
        else if (i < 81920) { src = Cw1 + (i - 65536);  dst = w1c + 16384 + (i - 65536); }
        else if (i < 98304) { src = Aw2 + (i - 81920);  dst = w2a + (i - 81920); }
        else                { src = Cw2 + (i - 98304);  dst = w2c + (i - 98304); }
        float4 v = *src;
        *dst = make_uint2(pack_h2(v.x, v.y), pack_h2(v.z, v.w));
        if (i < 256)       b1c[i] = Ab1[i];
        else if (i < 512)  b1c[i] = Cb1[i - 256];
    } else if (i < PREP_WHH) {
        int j2 = i - PREP_F4;              // 0..98303
        int kt  = j2 / 6144;
        int rem = j2 % 6144;
        int s   = rem / 24;                // slot = wn*32+lane
        int idx = rem % 24;
        int wn = s >> 5, lane = s & 31;
        int j12 = idx >> 1, b = idx & 1;
        int g = j12 >> 2, nt = j12 & 3;
        int col = g * 256 + wn * 32 + nt * 8 + (lane >> 2);
        int k0  = kt * 16 + 2 * (lane & 3) + 8 * b;
        Wt2h[kt * 7168 + s * 28 + idx] =
            pack_h2(W_hh[(size_t)col * 256 + k0], W_hh[(size_t)col * 256 + k0 + 1]);
    } else if (i < PREP_TOT) {
        int j3 = i - PREP_WHH;             // 0..4095
        int ksubg = j3 >> 7;
        int rest  = j3 & 127;
        int ntile = rest >> 6;
        int lane  = (rest >> 1) & 31;
        int r     = rest & 1;
        int kg = ksubg * 8 + (lane & 3) + 4 * r;
        int a  = ntile * 8 + (lane >> 2);
        w3f[j3] = (a < AA) ? round_tf32(Aw3[a * 256 + kg]) : 0.f;
    }
}

// features fp32 -> half
__global__ void feat_half(const float4* __restrict__ src, uint2* __restrict__ dst)
{
    size_t i = (size_t)blockIdx.x * 256 + threadIdx.x;
    float4 v = src[i];
    dst[i] = make_uint2(pack_h2(v.x, v.y), pack_h2(v.z, v.w));
}

// ===========================================================================
// fp16 mma GEMM: tile 128x128, BK=32 (2 x k16 steps), 2-stage cp.async,
// 2 CTAs/SM, ldmatrix fragments, per-CTA k-tile rotation.
// C output is half.
// ===========================================================================
#define GBM 128
#define GBN 128
#define GBK 32
#define PH 40                                  // halves pitch (80B rows)
#define ASTG (GBM * PH)                        // 5120 halves per A/B stage
#define GEMM_SMEM (4 * ASTG * 2 + GBN * 4)     // 40960 + 512 = 41472 B

__device__ __forceinline__ void gemm16_mainloop(
    __half* smh, const __half* Ag, const __half* Wg,
    int K, int a_lm, int b_lm, float acc[4][4][4],
    int lrow, int lkq, int phase)
{
    const uint32_t sbase = smem_u32(smh);
    const int NK = K / GBK;
    auto stage_copy = [&](int kt) {
        int tl = kt + phase;
        if (tl >= NK) tl -= NK;
        __half* st = smh + (kt & 1) * 2 * ASTG;
        const __half* ap = Ag + tl * GBK;
        const __half* wp = Wg + tl * GBK;
        __half* dA = st + lrow * PH + lkq;
        __half* dB = st + ASTG + lrow * PH + lkq;
        cp16_cg(dA,     ap);
        cp16_cg(dA + 8, ap + 8);
        cp16_cg(dB,     wp);
        cp16_cg(dB + 8, wp + 8);
    };
    stage_copy(0); CP_COMMIT();
    stage_copy(1); CP_COMMIT();
    for (int kt = 0; kt < NK; kt++) {
        if (kt < NK - 1) { CP_WAIT1(); } else { CP_WAITALL(); }
        __syncthreads();
        const uint32_t bufA = sbase + ((kt & 1) * 2 * ASTG) * 2;
        const uint32_t bufB = bufA + ASTG * 2;
#pragma unroll
        for (int ks = 0; ks < 2; ks++) {
            const int k0 = ks * 16;
            uint32_t a[4][4];
#pragma unroll
            for (int mt = 0; mt < 4; mt++)
                LDMX4(a[mt][0], a[mt][1], a[mt][2], a[mt][3],
                      bufA + (a_lm + mt * 16 * PH + k0) * 2);
            uint32_t b[4][2];
#pragma unroll
            for (int nt = 0; nt < 4; nt++)
                LDMX2(b[nt][0], b[nt][1],
                      bufB + (b_lm + nt * 8 * PH + k0) * 2);
#pragma unroll
            for (int mt = 0; mt < 4; mt++)
#pragma unroll
                for (int nt = 0; nt < 4; nt++)
                    mma_f16(acc[mt][nt][0], acc[mt][nt][1],
                            acc[mt][nt][2], acc[mt][nt][3],
                            a[mt][0], a[mt][1], a[mt][2], a[mt][3],
                            b[nt][0], b[nt][1]);
        }
        __syncthreads();
        if (kt + 2 < NK) { stage_copy(kt + 2); CP_COMMIT(); }
    }
}

template<bool DO_TANH>
__global__ __launch_bounds__(256, 2) void gemm_h(
    const __half* __restrict__ A, const __half* __restrict__ W,
    const float* __restrict__ bias, __half* __restrict__ C,
    int N, int K, int lda)
{
    extern __shared__ __half smh[];
    float* sBias = (float*)(smh + 4 * ASTG);
    const int tid  = threadIdx.x;
    const int lane = tid & 31;
    const int wid  = tid >> 5;
    const int wm   = wid >> 2;
    const int wn   = wid & 3;
    const int    bn = blockIdx.x * GBN;
    const size_t bm = (size_t)blockIdx.y * GBM;
    if (tid < GBN) sBias[tid] = bias[bn + tid];
    const int lrow = tid >> 1;
    const int lkq  = (tid & 1) * 16;
    const __half* Ag = A + (bm + lrow) * lda + lkq;
    const __half* Wg = W + ((size_t)(bn + lrow)) * K + lkq;
    const int a_lm = (wm * 64 + (lane & 15)) * PH + ((lane >> 4) << 3);
    const int b_lm = (wn * 32 + (lane & 7)) * PH + (((lane >> 3) & 1) << 3);
    const int phase = blockIdx.y & ((K / GBK) - 1);

    float acc[4][4][4];
#pragma unroll
    for (int mt = 0; mt < 4; mt++)
#pragma unroll
        for (int nt = 0; nt < 4; nt++)
#pragma unroll
            for (int q = 0; q < 4; q++) acc[mt][nt][q] = 0.f;

    gemm16_mainloop(smh, Ag, Wg, K, a_lm, b_lm, acc, lrow, lkq, phase);

#pragma unroll
    for (int mt = 0; mt < 4; mt++) {
        const size_t row = bm + wm * 64 + mt * 16 + (lane >> 2);
        __half* c0p = C + row * N + bn + wn * 32;
        __half* c1p = c0p + (size_t)8 * N;
#pragma unroll
        for (int nt = 0; nt < 4; nt++) {
            const int cc = nt * 8 + (lane & 3) * 2;
            const float bx = sBias[wn * 32 + cc];
            const float by = sBias[wn * 32 + cc + 1];
            float v0 = acc[mt][nt][0] + bx, v1 = acc[mt][nt][1] + by;
            float v2 = acc[mt][nt][2] + bx, v3 = acc[mt][nt][3] + by;
            if (DO_TANH) {
                v0 = tanhf(v0); v1 = tanhf(v1);
                v2 = tanhf(v2); v3 = tanhf(v3);
            }
            *(uint32_t*)(c0p + cc) = pack_h2(v0, v1);
            *(uint32_t*)(c1p + cc) = pack_h2(v2, v3);
        }
    }
}

// ===========================================================================
// Layer-2 GEMM (fp16 mainloop) fused with heads -> partials.
// ===========================================================================
template<bool ACTOR>
__global__ __launch_bounds__(256, 2) void gemm_l2(
    const __half* __restrict__ A, const __half* __restrict__ W,
    const float* __restrict__ bias, const float* __restrict__ w3f,
    const float* __restrict__ Cw3,
    float* __restrict__ partial, int K, int lda)
{
    extern __shared__ __half smh[];
    float* sBias = (float*)(smh + 4 * ASTG);
    float* sred  = (float*)smh;             // reuse stage area post-mainloop
    const int tid  = threadIdx.x;
    const int lane = tid & 31;
    const int wid  = tid >> 5;
    const int wm   = wid >> 2;
    const int wn   = wid & 3;
    const int    bn = blockIdx.x * GBN;
    const size_t bm = (size_t)blockIdx.y * GBM;
    if (tid < GBN) sBias[tid] = bias[bn + tid];
    const int lrow = tid >> 1;
    const int lkq  = (tid & 1) * 16;
    const __half* Ag = A + (bm + lrow) * lda + lkq;
    const __half* Wg = W + ((size_t)(bn + lrow)) * K + lkq;
    const int a_lm = (wm * 64 + (lane & 15)) * PH + ((lane >> 4) << 3);
    const int b_lm = (wn * 32 + (lane & 7)) * PH + (((lane >> 3) & 1) << 3);
    const int phase = blockIdx.y & ((K / GBK) - 1);

    float acc[4][4][4];
#pragma unroll
    for (int mt = 0; mt < 4; mt++)
#pragma unroll
        for (int nt = 0; nt < 4; nt++)
#pragma unroll
            for (int q = 0; q < 4; q++) acc[mt][nt][q] = 0.f;

    gemm16_mainloop(smh, Ag, Wg, K, a_lm, b_lm, acc, lrow, lkq, phase);

#pragma unroll
    for (int mt = 0; mt < 4; mt++)
#pragma unroll
        for (int nt = 0; nt < 4; nt++) {
            const int cc = nt * 8 + (lane & 3) * 2;
            const float bx = sBias[wn * 32 + cc];
            const float by = sBias[wn * 32 + cc + 1];
            acc[mt][nt][0] = tanhf(acc[mt][nt][0] + bx);
            acc[mt][nt][1] = tanhf(acc[mt][nt][1] + by);
            acc[mt][nt][2] = tanhf(acc[mt][nt][2] + bx);
            acc[mt][nt][3] = tanhf(acc[mt][nt][3] + by);
        }

    const int j    = lane & 3;
    const int srcA = (lane & ~3) | (j >> 1);
    const int srcB = (lane & ~3) | (2 + (j >> 1));
    const bool odd = (lane & 1);

    if (ACTOR) {
        float hacc[4][2][4];
#pragma unroll
        for (int mt = 0; mt < 4; mt++)
#pragma unroll
            for (int n2 = 0; n2 < 2; n2++)
#pragma unroll
                for (int q = 0; q < 4; q++) hacc[mt][n2][q] = 0.f;

        const int ksgbase = (bn >> 3) + wn * 4;
#pragma unroll
        for (int ks = 0; ks < 4; ks++) {
            float2 bf0 = *(const float2*)(w3f + (((ksgbase + ks) * 2 + 0) * 32 + lane) * 2);
            float2 bf1 = *(const float2*)(w3f + (((ksgbase + ks) * 2 + 1) * 32 + lane) * 2);
            uint32_t b00 = __float_as_uint(bf0.x), b01 = __float_as_uint(bf0.y);
            uint32_t b10 = __float_as_uint(bf1.x), b11 = __float_as_uint(bf1.y);
#pragma unroll
            for (int mt = 0; mt < 4; mt++) {
                float c0 = acc[mt][ks][0], c1 = acc[mt][ks][1];
                float c2 = acc[mt][ks][2], c3 = acc[mt][ks][3];
                float t0 = __shfl_sync(0xffffffffu, c0, srcA);
                float t1 = __shfl_sync(0xffffffffu, c1, srcA);
                float t2 = __shfl_sync(0xffffffffu, c2, srcA);
                float t3 = __shfl_sync(0xffffffffu, c3, srcA);
                float u0 = __shfl_sync(0xffffffffu, c0, srcB);
                float u1 = __shfl_sync(0xffffffffu, c1, srcB);
                float u2 = __shfl_sync(0xffffffffu, c2, srcB);
                float u3 = __shfl_sync(0xffffffffu, c3, srcB);
                uint32_t a0 = cvt_tf32_f(odd ? t1 : t0);
                uint32_t a1 = cvt_tf32_f(odd ? t3 : t2);
                uint32_t a2 = cvt_tf32_f(odd ? u1 : u0);
                uint32_t a3 = cvt_tf32_f(odd ? u3 : u2);
                mma_tf32(hacc[mt][0][0], hacc[mt][0][1], hacc[mt][0][2], hacc[mt][0][3],
                         a0, a1, a2, a3, b00, b01);
                mma_tf32(hacc[mt][1][0], hacc[mt][1][1], hacc[mt][1][2], hacc[mt][1][3],
                         a0, a1, a2, a3, b10, b11);
            }
        }
        for (int rr = 0; rr < 4; rr++) {
            if (wn == rr) {
#pragma unroll
                for (int mt = 0; mt < 4; mt++)
#pragma unroll
                    for (int n2 = 0; n2 < 2; n2++)
#pragma unroll
                        for (int q = 0; q < 4; q++) {
                            int row = wm * 64 + mt * 16 + (lane >> 2) + 8 * (q >> 1);
                            int col = n2 * 8 + 2 * (lane & 3) + (q & 1);
                            if (rr == 0) sred[row * 17 + col] = hacc[mt][n2][q];
                            else         sred[row * 17 + col] += hacc[mt][n2][q];
                        }
            }
            __syncthreads();
        }
        const size_t pbase = (size_t)blockIdx.x * MTOT * 16 + bm * 16;
        for (int i = tid; i < 128 * 16; i += 256)
            partial[pbase + i] = sred[(i >> 4) * 17 + (i & 15)];
    } else {
        float2 cw[4];
#pragma unroll
        for (int nt = 0; nt < 4; nt++)
            cw[nt] = *(const float2*)(Cw3 + bn + wn * 32 + nt * 8 + 2 * (lane & 3));
        float rsum[4][2];
#pragma unroll
        for (int mt = 0; mt < 4; mt++) {
            float s0 = 0.f, s1 = 0.f;
#pragma unroll
            for (int nt = 0; nt < 4; nt++) {
                s0 = fmaf(acc[mt][nt][0], cw[nt].x, s0);
                s0 = fmaf(acc[mt][nt][1], cw[nt].y, s0);
                s1 = fmaf(acc[mt][nt][2], cw[nt].x, s1);
                s1 = fmaf(acc[mt][nt][3], cw[nt].y, s1);
            }
            s0 += __shfl_xor_sync(0xffffffffu, s0, 1);
            s0 += __shfl_xor_sync(0xffffffffu, s0, 2);
            s1 += __shfl_xor_sync(0xffffffffu, s1, 1);
            s1 += __shfl_xor_sync(0xffffffffu, s1, 2);
            rsum[mt][0] = s0; rsum[mt][1] = s1;
        }
        for (int rr = 0; rr < 4; rr++) {
            if (wn == rr && (lane & 3) == 0) {
#pragma unroll
                for (int mt = 0; mt < 4; mt++)
#pragma unroll
                    for (int qh = 0; qh < 2; qh++) {
                        int row = wm * 64 + mt * 16 + (lane >> 2) + 8 * qh;
                        if (rr == 0) sred[row] = rsum[mt][qh];
                        else         sred[row] += rsum[mt][qh];
                    }
            }
            __syncthreads();
        }
        const size_t pbase = (size_t)blockIdx.x * MTOT + bm;
        if (tid < 128) partial[pbase + tid] = sred[tid];
    }
}

// combine partials -> out[:,0:13]
__global__ __launch_bounds__(256) void combine_kernel(
    const float* __restrict__ pa, const float* __restrict__ pc,
    const float* __restrict__ Ab3, const float* __restrict__ Cb3,
    float* __restrict__ out)
{
    size_t m = (size_t)blockIdx.x * 256 + threadIdx.x;
    const float* p0 = pa + m * 16;
    const float* p1 = pa + (size_t)MTOT * 16 + m * 16;
    float* o = out + m * 13;
#pragma unroll
    for (int a = 0; a < 12; a++)
        o[a] = p0[a] + p1[a] + Ab3[a];
    o[12] = pc[m] + pc[MTOT + m] + Cb3[0];
}

// ===========================================================================
// GRU scan fp16: 512 threads, frag-major half2 W (28KB/kt stages),
// half ht for ldmatrix, fp32 h in registers, k-tile rotation.
// ===========================================================================
#define RB2 32
#define HT_PH 264                  // halves pitch
#define WS_U32 7168                // u32 per k-tile stage
// smem: ws[3][7168] u32 | hth[32][264] half | sst[32][64] int | sbh[768] f
#define GRU_SMEM (3*WS_U32*4 + 32*HT_PH*2 + 32*64*4 + 768*4)   // 114176 B

__global__ __launch_bounds__(512, 1) void gru_mma(
    const __half* __restrict__ xgh, const float* __restrict__ h0,
    const uint32_t* __restrict__ Wt2h, const float* __restrict__ b_hh,
    const int* __restrict__ starts,
    __half* __restrict__ lath, float* __restrict__ h_out)
{
    extern __shared__ char smraw[];
    uint32_t* ws  = (uint32_t*)smraw;                  // [3][7168]
    __half*   hth = (__half*)(ws + 3 * WS_U32);        // [32][264]
    int*      sst = (int*)(hth + 32 * HT_PH);          // [32][64]
    float*    sbh = (float*)(sst + 32 * 64);           // [768]

    const int tid  = threadIdx.x;
    const int lane = tid & 31;
    const int w    = tid >> 5;
    const int wm   = w >> 3;
    const int wn   = w & 7;
    const int b0   = blockIdx.x * RB2;
    const int phase = blockIdx.x & 15;

    for (int i = tid; i < 32 * 64; i += 512)
        sst[i] = starts[(size_t)(b0 + (i >> 6)) * TT + (i & 63)];
    for (int i = tid; i < 768; i += 512) sbh[i] = b_hh[i];

    float2 hreg[2][4];
#pragma unroll
    for (int rh = 0; rh < 2; rh++) {
        const int row = wm * 16 + rh * 8 + (lane >> 2);
        const float m0 = starts[(size_t)(b0 + row) * TT] ? 0.f : 1.f;
#pragma unroll
        for (int nt = 0; nt < 4; nt++) {
            const int c = wn * 32 + nt * 8 + (lane & 3) * 2;
            float2 v = *(const float2*)(h0 + (size_t)(b0 + row) * 256 + c);
            v.x *= m0; v.y *= m0;
            hreg[rh][nt] = v;
            *(uint32_t*)(hth + row * HT_PH + c) = pack_h2(v.x, v.y);
        }
    }

    // stage: 7168 u32 = 1792 x 16B chunks; 512 threads x 3.5
    auto stageW = [&](int tile, int buf) {
        const float4* src = (const float4*)(Wt2h + (size_t)tile * WS_U32);
        float4* dst = (float4*)(ws + buf * WS_U32);
        cp16_cg(dst + tid,        src + tid);
        cp16_cg(dst + 512 + tid,  src + 512 + tid);
        cp16_cg(dst + 1024 + tid, src + 1024 + tid);
        if (tid < 256) cp16_cg(dst + 1536 + tid, src + 1536 + tid);
    };

    stageW(phase, 0); CP_COMMIT();
    stageW((phase + 1) & 15, 1); CP_COMMIT();

    const uint32_t ht_lm = smem_u32(hth)
        + ((wm * 16 + (lane & 15)) * HT_PH + ((lane >> 4) << 3)) * 2;
    const int bslot = (wn * 32 + lane) * 28;

    const int KS_TOTAL = TT * 16;
    int ks = 0;

    for (int t = 0; t < TT; t++) {
        float acc[12][4];
#pragma unroll
        for (int j = 0; j < 12; j++)
#pragma unroll
            for (int q = 0; q < 4; q++) acc[j][q] = 0.f;

        for (int kt = 0; kt < 16; kt++) {
            if (ks < KS_TOTAL - 1) { CP_WAIT1(); } else { CP_WAITALL(); }
            __syncthreads();

            if (ks + 2 < KS_TOTAL) {
                stageW((phase + ks + 2) & 15, (ks + 2) % 3);
                CP_COMMIT();
            }

            // prefetch xg[t] slice: 32 rows x 12 lines = 384 lines, 24/kt
            if (tid < 24) {
                int li = kt * 24 + tid;
                int r = li / 12, cl = li % 12;
                l2_prefetch((const char*)(xgh + ((size_t)(b0 + r) * TT + t) * G3)
                            + cl * 128);
            }

            const int tc = (phase + ks) & 15;
            const uint32_t* wb = ws + (ks % 3) * WS_U32 + bslot;
            uint32_t a0, a1, a2, a3;
            LDMX4(a0, a1, a2, a3, ht_lm + tc * 32);
            float4 bf[6];
#pragma unroll
            for (int u = 0; u < 6; u++)
                bf[u] = *(const float4*)(wb + u * 4);
            const uint32_t* bw = (const uint32_t*)bf;
#pragma unroll
            for (int j = 0; j < 12; j++)
                mma_f16(acc[j][0], acc[j][1], acc[j][2], acc[j][3],
                        a0, a1, a2, a3, bw[j * 2], bw[j * 2 + 1]);
            ks++;
        }
        __syncthreads();

#pragma unroll
        for (int rh = 0; rh < 2; rh++) {
            const int row  = wm * 16 + rh * 8 + (lane >> 2);
            const int grow = b0 + row;
            const size_t gbt = (size_t)grow * TT + t;
            const __half* xb = xgh + gbt * G3;
            __half* lb = lath + gbt * 256;
            float msk = 1.f;
            if (t < TT - 1) msk = sst[row * 64 + t + 1] ? 0.f : 1.f;
            const int q = rh * 2;
#pragma unroll
            for (int nt = 0; nt < 4; nt++) {
                const int c = wn * 32 + nt * 8 + (lane & 3) * 2;
                float2 xr = __half22float2(*(const __half2*)(xb + c));
                float2 xz = __half22float2(*(const __half2*)(xb + 256 + c));
                float2 xn = __half22float2(*(const __half2*)(xb + 512 + c));
                float hr0 = acc[nt][q]         + sbh[c];
                float hr1 = acc[nt][q + 1]     + sbh[c + 1];
                float hz0 = acc[4 + nt][q]     + sbh[256 + c];
                float hz1 = acc[4 + nt][q + 1] + sbh[256 + c + 1];
                float hn0 = acc[8 + nt][q]     + sbh[512 + c];
                float hn1 = acc[8 + nt][q + 1] + sbh[512 + c + 1];
                float r0 = 1.f / (1.f + __expf(-(xr.x + hr0)));
                float r1 = 1.f / (1.f + __expf(-(xr.y + hr1)));
                float z0 = 1.f / (1.f + __expf(-(xz.x + hz0)));
                float z1 = 1.f / (1.f + __expf(-(xz.y + hz1)));
                float n0 = tanhf(xn.x + r0 * hn0);
                float n1 = tanhf(xn.y + r1 * hn1);
                float v0 = (1.f - z0) * n0 + z0 * hreg[rh][nt].x;
                float v1 = (1.f - z1) * n1 + z1 * hreg[rh][nt].y;
                *(uint32_t*)(lb + c) = pack_h2(v0, v1);
                if (t == TT - 1) {
                    *(float2*)(h_out + (size_t)grow * 256 + c) = make_float2(v0, v1);
                } else {
                    float m0 = v0 * msk, m1 = v1 * msk;
                    hreg[rh][nt] = make_float2(m0, m1);
                    *(uint32_t*)(hth + row * HT_PH + c) = pack_h2(m0, m1);
                }
            }
        }
    }
}

__global__ void std_kernel(const float* __restrict__ log_std, float* __restrict__ out)
{
    int a = threadIdx.x;
    if (a < AA) {
        float v = log_std[a];
        v = fminf(fmaxf(v, -2.0f), -0.5f);
        out[a] = __expf(v);
    }
}

// ---------------------------------------------------------------------------
extern "C" void kernel_launch(void* const* d_in, const int* in_sizes, int n_in,
                              void* d_out, int out_size)
{
    const float* features = (const float*)d_in[0];
    const float* hidden   = (const float*)d_in[1];
    const float* W_ih     = (const float*)d_in[2];
    const float* W_hh     = (const float*)d_in[3];
    const float* b_ih     = (const float*)d_in[4];
    const float* b_hh     = (const float*)d_in[5];
    const float* Aw1      = (const float*)d_in[6];
    const float* Ab1      = (const float*)d_in[7];
    const float* Aw2      = (const float*)d_in[8];
    const float* Ab2      = (const float*)d_in[9];
    const float* Aw3      = (const float*)d_in[10];
    const float* Ab3      = (const float*)d_in[11];
    const float* Cw1      = (const float*)d_in[12];
    const float* Cb1      = (const float*)d_in[13];
    const float* Cw2      = (const float*)d_in[14];
    const float* Cb2      = (const float*)d_in[15];
    const float* Cw3      = (const float*)d_in[16];
    const float* Cb3      = (const float*)d_in[17];
    const float* log_std  = (const float*)d_in[18];
    const int*   starts   = (const int*)d_in[19];

    float* out      = (float*)d_out;
    float* out_main = out;
    float* out_std  = out + (size_t)MTOT * 13;
    float* out_h    = out + (size_t)MTOT * 13 + AA;

    __half *xgh, *lath, *t1h, *wihr, *w1c, *w2a, *w2c;
    float *pa, *pc, *b1c, *w3f;
    uint32_t *wt2h;
    cudaGetSymbolAddress((void**)&xgh,  g_xgh);
    cudaGetSymbolAddress((void**)&lath, g_lath);
    cudaGetSymbolAddress((void**)&t1h,  g_t1h);
    cudaGetSymbolAddress((void**)&pa,   g_pa);
    cudaGetSymbolAddress((void**)&pc,   g_pc);
    cudaGetSymbolAddress((void**)&wt2h, g_wt2h);
    cudaGetSymbolAddress((void**)&wihr, g_wihr);
    cudaGetSymbolAddress((void**)&w1c,  g_w1c);
    cudaGetSymbolAddress((void**)&w2a,  g_w2a);
    cudaGetSymbolAddress((void**)&w2c,  g_w2c);
    cudaGetSymbolAddress((void**)&b1c,  g_b1c);
    cudaGetSymbolAddress((void**)&w3f,  g_w3f);

    cudaFuncSetAttribute(gemm_h<false>,
                         cudaFuncAttributeMaxDynamicSharedMemorySize, GEMM_SMEM);
    cudaFuncSetAttribute(gemm_h<true>,
                         cudaFuncAttributeMaxDynamicSharedMemorySize, GEMM_SMEM);
    cudaFuncSetAttribute(gemm_l2<true>,
                         cudaFuncAttributeMaxDynamicSharedMemorySize, GEMM_SMEM);
    cudaFuncSetAttribute(gemm_l2<false>,
                         cudaFuncAttributeMaxDynamicSharedMemorySize, GEMM_SMEM);
    cudaFuncSetAttribute(gru_mma,
                         cudaFuncAttributeMaxDynamicSharedMemorySize, GRU_SMEM);

    dim3 blk(256);

    // 1) weight prep (half + frag-major + head frags + bias concat)
    prep_all<<<PREP_TOT/256, blk>>>(
        (const float4*)W_ih, (const float4*)Aw1, (const float4*)Cw1,
        (const float4*)Aw2, (const float4*)Cw2, Ab1, Cb1, W_hh, Aw3,
        (uint2*)wihr, (uint2*)w1c, (uint2*)w2a, (uint2*)w2c,
        b1c, wt2h, w3f);
    // 2) features -> half
    feat_half<<<((size_t)MTOT*256)/1024, blk>>>(
        (const float4*)features, (uint2*)t1h);
    // 3) std (independent)
    std_kernel<<<1, 32>>>(log_std, out_std);
    // 4) xg = features @ W_ih^T + b_ih (half out)   <-- profiled launch
    gemm_h<false><<<dim3(G3/GBN, MTOT/GBM), blk, GEMM_SMEM>>>(
        t1h, wihr, b_ih, xgh, G3, FF, FF);
    // 5) GRU scan -> lat (half), h_last (fp32)
    gru_mma<<<BB/RB2, dim3(512), GRU_SMEM>>>(
        xgh, hidden, wt2h, b_hh, starts, lath, out_h);
    // 6) fused actor+critic layer1 (reuses g_xgh as [M,512] half)
    gemm_h<true><<<dim3(512/GBN, MTOT/GBM), blk, GEMM_SMEM>>>(
        lath, w1c, b1c, xgh, 512, HH, HH);
    // 7,8) layer2 + fused heads -> partials
    gemm_l2<true><<<dim3(HH/GBN, MTOT/GBM), blk, GEMM_SMEM>>>(
        xgh,       w2a, Ab2, w3f, Cw3, pa, HH, 512);
    gemm_l2<false><<<dim3(HH/GBN, MTOT/GBM), blk, GEMM_SMEM>>>(
        xgh + 256, w2c, Cb2, w3f, Cw3, pc, HH, 512);
    // 9) combine partials + biases -> out[:,0:13]
    combine_kernel<<<MTOT/256, blk>>>(pa, pc, Ab3, Cb3, out_main);
}